// round 9
// baseline (speedup 1.0000x reference)
#include <cuda_runtime.h>
#include <cuda_bf16.h>
#include <cstdint>
#include <cstddef>

// ---------------------------------------------------------------------------
// BiLSTM-NER, Round 8: fused 2-layer persistent LSTM with SPLIT barriers:
//  * bar0 (h0 state) arrives MID-interval right after the h0 store; the next
//    interval's wait overlaps the whole L1 phase of neighbor CTAs.
//  * bar1 (h1 state) is waited only immediately before the h1 tile load.
//  * xw pre-activations stored bf16 (halves the 402MB g_xw traffic).
// FF GEMMs / conv / em / CRF unchanged.
// ---------------------------------------------------------------------------

#define Tt 256
#define Bb 256
#define Hh 384
#define G4 1536   // 4*H
#define INP 100
#define Kc 10
#define NCTA_LSTM 96

typedef __nv_bfloat16 bf16;

// ============================ PTX helpers ==================================
__device__ __forceinline__ uint32_t smem_to_u32(const void* p) {
    uint32_t a;
    asm("{ .reg .u64 t; cvta.to.shared.u64 t, %1; cvt.u32.u64 %0, t; }"
        : "=r"(a) : "l"(p));
    return a;
}
__device__ __forceinline__ void ldsm4(uint32_t* r, uint32_t saddr) {
    asm volatile("ldmatrix.sync.aligned.m8n8.x4.shared.b16 {%0,%1,%2,%3}, [%4];"
        : "=r"(r[0]), "=r"(r[1]), "=r"(r[2]), "=r"(r[3]) : "r"(saddr));
}
__device__ __forceinline__ void mma_bf16(float* c, const uint32_t* a, const uint32_t* b) {
    asm volatile(
        "mma.sync.aligned.m16n8k16.row.col.f32.bf16.bf16.f32 "
        "{%0,%1,%2,%3}, {%4,%5,%6,%7}, {%8,%9}, {%0,%1,%2,%3};"
        : "+f"(c[0]), "+f"(c[1]), "+f"(c[2]), "+f"(c[3])
        : "r"(a[0]), "r"(a[1]), "r"(a[2]), "r"(a[3]), "r"(b[0]), "r"(b[1]));
}
#define CP_ASYNC16(sa, ga) \
    asm volatile("cp.async.cg.shared.global [%0], [%1], 16;" \
                 :: "r"(sa), "l"(ga) : "memory")
#define CP_COMMIT() asm volatile("cp.async.commit_group;" ::: "memory")
#define CP_WAIT0()  asm volatile("cp.async.wait_group 0;" ::: "memory")

__device__ __forceinline__ float tanh_ap(float x) {
    float y; asm("tanh.approx.f32 %0, %1;" : "=f"(y) : "f"(x)); return y;
}
__device__ __forceinline__ float sig_ap(float x) {
    return fmaf(tanh_ap(0.5f * x), 0.5f, 0.5f);
}

// ------------------------- scratch (device globals) ------------------------
__device__ bf16  g_xwb[(size_t)Tt * Bb * G4];      // layer-0 gate pre-acts (bf16)
__device__ bf16  g_xb[(size_t)Tt * Bb * 128];      // x padded to K=128, bf16
__device__ bf16  g_h1b[(size_t)Tt * Bb * Hh];      // layer1 outputs (bf16)
__device__ bf16  g_m1b[(size_t)Tt * Bb * 512];     // MLP hidden 1 (bf16)
__device__ bf16  g_m2b[(size_t)Tt * Bb * 1024];    // MLP hidden 2 (bf16)
__device__ float g_em[(size_t)Tt * Bb * Kc];       // emissions (fp32)
__device__ bf16  g_wih0b[1536 * 128];              // Wih0 padded K=128
__device__ bf16  g_w1b[512 * 384];
__device__ bf16  g_w2b[1024 * 512];
__device__ bf16  g_h0buf[2 * Bb * Hh];             // recurrent h0 state (bf16)
__device__ bf16  g_h1buf[2 * Bb * Hh];             // recurrent h1 state (bf16)
__device__ float g_partial[Bb];

// 8 barrier slots: [bar(0/1) * 4 + batch-group], each on its own 256B line
__device__ unsigned int          g_bcnt[8 * 64];
__device__ volatile unsigned int g_bgen[8 * 64];

// ------------------------------ init state --------------------------------
__global__ void init_state_kernel() {
    int i = blockIdx.x * blockDim.x + threadIdx.x;
    if (i < 2 * Bb * Hh) {
        g_h0buf[i] = __float2bfloat16(0.f);
        g_h1buf[i] = __float2bfloat16(0.f);
    }
    if (i < 8 * 64) { g_bcnt[i] = 0u; g_bgen[i] = 0u; }
}

// ---------------------- merged bf16 conversions ----------------------------
#define S0 (65536 * 128)
#define S1 (1536 * 128)
#define S3 (512 * 384)
#define S4 (1024 * 512)
__global__ __launch_bounds__(256) void conv_all(
    const float* __restrict__ x, const float* __restrict__ Wih0,
    const float* __restrict__ W1, const float* __restrict__ W2)
{
    const int total = S0 + S1 + S3 + S4;
    for (int i = blockIdx.x * blockDim.x + threadIdx.x; i < total;
         i += gridDim.x * blockDim.x) {
        if (i < S0) {
            int r = i >> 7, c = i & 127;
            g_xb[i] = (c < INP) ? __float2bfloat16(x[(size_t)r * INP + c])
                                : __float2bfloat16(0.f);
        } else if (i < S0 + S1) {
            int j = i - S0;
            int r = j >> 7, c = j & 127;
            g_wih0b[j] = (c < INP) ? __float2bfloat16(Wih0[(size_t)r * INP + c])
                                   : __float2bfloat16(0.f);
        } else if (i < S0 + S1 + S3) {
            int j = i - S0 - S1;
            g_w1b[j] = __float2bfloat16(W1[j]);
        } else {
            int j = i - S0 - S1 - S3;
            g_w2b[j] = __float2bfloat16(W2[j]);
        }
    }
}

// ---------------- split group barriers (24 CTAs per group) -----------------
// arrive: last of 24 arrivals publishes generation `target`.
// wait: spin until generation >= target. Generations are monotonic in t.
__device__ __forceinline__ void bar_arrive(int slot, unsigned int target) {
    __threadfence();
    __syncthreads();
    if (threadIdx.x == 0) {
        if (atomicAdd(&g_bcnt[slot * 64], 1u) == 23u) {
            g_bcnt[slot * 64] = 0u;
            __threadfence();
            g_bgen[slot * 64] = target;
        }
    }
}
__device__ __forceinline__ void bar_wait(int slot, unsigned int target) {
    if (threadIdx.x == 0) {
        while (g_bgen[slot * 64] < target) { }
    }
    __syncthreads();
}

// ======================== HMMA feed-forward GEMM ===========================
__global__ __launch_bounds__(256) void mma_gemm(
    const bf16* __restrict__ A, const bf16* __restrict__ B,
    const float* __restrict__ bias1, const float* __restrict__ bias2,
    float* __restrict__ Cf, bf16* __restrict__ Cb,
    int M, int N, int K)
{
    __shared__ __align__(16) bf16 smA[2][128 * 40];
    __shared__ __align__(16) bf16 smB[2][128 * 40];

    const int tid = threadIdx.x;
    const int lane = tid & 31;
    const int wid = tid >> 5;
    const int wm = wid & 3;
    const int wn = wid >> 2;
    const int m0 = blockIdx.y * 128;
    const int n0 = blockIdx.x * 128;

    const uint32_t saddrA[2] = { smem_to_u32(smA[0]), smem_to_u32(smA[1]) };
    const uint32_t saddrB[2] = { smem_to_u32(smB[0]), smem_to_u32(smB[1]) };

    float acc[2][8][4];
#pragma unroll
    for (int i = 0; i < 2; i++)
#pragma unroll
        for (int j = 0; j < 8; j++)
#pragma unroll
            for (int q = 0; q < 4; q++) acc[i][j][q] = 0.f;

    const uint32_t a_off =
        (uint32_t)(((wm * 32 + (lane & 15)) * 40 + (lane >> 4) * 8) * 2);
    uint32_t b_off[4];
#pragma unroll
    for (int jp = 0; jp < 4; jp++)
        b_off[jp] = (uint32_t)(((wn * 64 + jp * 16 + (lane & 7) + ((lane >> 4) << 3)) * 40
                                + ((lane >> 3) & 1) * 8) * 2);

    const int lrow = tid >> 2;
    const int lc   = tid & 3;

    const int nkt = K >> 5;
#pragma unroll
    for (int it = 0; it < 2; it++) {
        int row = lrow + it * 64;
        uint32_t d = (uint32_t)((row * 40 + lc * 8) * 2);
        CP_ASYNC16(saddrA[0] + d, A + (size_t)(m0 + row) * K + lc * 8);
        CP_ASYNC16(saddrB[0] + d, B + (size_t)(n0 + row) * K + lc * 8);
    }
    CP_COMMIT();

    for (int kt = 0; kt < nkt; kt++) {
        CP_WAIT0();
        __syncthreads();
        if (kt + 1 < nkt) {
            int s = (kt + 1) & 1;
            int k0 = (kt + 1) * 32;
#pragma unroll
            for (int it = 0; it < 2; it++) {
                int row = lrow + it * 64;
                uint32_t d = (uint32_t)((row * 40 + lc * 8) * 2);
                CP_ASYNC16(saddrA[s] + d, A + (size_t)(m0 + row) * K + k0 + lc * 8);
                CP_ASYNC16(saddrB[s] + d, B + (size_t)(n0 + row) * K + k0 + lc * 8);
            }
        }
        CP_COMMIT();

        const uint32_t sa = saddrA[kt & 1];
        const uint32_t sb = saddrB[kt & 1];
#pragma unroll
        for (int kk = 0; kk < 2; kk++) {
            uint32_t a[2][4], b[4][4];
            ldsm4(a[0], sa + a_off + kk * 32);
            ldsm4(a[1], sa + a_off + 1280 + kk * 32);
#pragma unroll
            for (int jp = 0; jp < 4; jp++)
                ldsm4(b[jp], sb + b_off[jp] + kk * 32);
#pragma unroll
            for (int mt = 0; mt < 2; mt++)
#pragma unroll
                for (int j = 0; j < 8; j++)
                    mma_bf16(acc[mt][j], a[mt], &b[j >> 1][(j & 1) * 2]);
        }
        __syncthreads();
    }

#pragma unroll
    for (int mt = 0; mt < 2; mt++)
#pragma unroll
        for (int j = 0; j < 8; j++)
#pragma unroll
            for (int p = 0; p < 2; p++) {
                int row = m0 + wm * 32 + mt * 16 + (lane >> 2) + p * 8;
                int col = n0 + wn * 64 + j * 8 + (lane & 3) * 2;
                float bb0 = bias1[col], bb1 = bias1[col + 1];
                if (bias2) { bb0 += bias2[col]; bb1 += bias2[col + 1]; }
                float v0 = acc[mt][j][p * 2] + bb0;
                float v1 = acc[mt][j][p * 2 + 1] + bb1;
                if (Cf) {
                    *(float2*)(Cf + (size_t)row * N + col) = make_float2(v0, v1);
                } else {
                    *(__nv_bfloat162*)(Cb + (size_t)row * N + col) =
                        __floats2bfloat162_rn(v0, v1);
                }
            }
}

// ================== fused 2-layer persistent LSTM ==========================
// 96 CTAs (4 batch x 24 colgroups), 256 threads = 8 warps (4m x 2n-half).
// Interval t: phase A = L0 step t (arrive bar0 right after h0(t) store);
//             phase B = L1 step t-1 (wait bar1 just before the h1 load,
//             arrive bar1 at end). Phase B overlaps neighbors' bar0 waits.
__device__ __forceinline__ void mma_pass24(
    float (*acc)[4], uint32_t a_base, uint32_t w_base,
    uint32_t a_off, uint32_t b_off0, uint32_t b_off1)
{
#pragma unroll 6
    for (int kt = 0; kt < 24; kt++) {
        uint32_t koff = (uint32_t)(kt * 32);
        uint32_t a[4], b0[4], b1[4];
        ldsm4(a, a_base + a_off + koff);
        ldsm4(b0, w_base + b_off0 + koff);
        ldsm4(b1, w_base + b_off1 + koff);
        mma_bf16(acc[0], a, &b0[0]);
        mma_bf16(acc[1], a, &b0[2]);
        mma_bf16(acc[2], a, &b1[0]);
        mma_bf16(acc[3], a, &b1[2]);
    }
}

__global__ __launch_bounds__(256) void lstm_fused(
    const float* __restrict__ Whh0, const float* __restrict__ Wih1,
    const float* __restrict__ Whh1, const float* __restrict__ bih1,
    const float* __restrict__ bhh1)
{
    extern __shared__ bf16 dsm[];
    bf16* W0sm  = dsm;                    // Whh0 slice  (64n x 392)
    bf16* Wi1sm = dsm + 64 * 392;         // Wih1 slice
    bf16* W1sm  = dsm + 2 * 64 * 392;     // Whh1 slice
    bf16* Asm   = dsm + 3 * 64 * 392;     // shared A tile (64 x 392)
    const uint32_t w0base  = smem_to_u32(W0sm);
    const uint32_t wi1base = smem_to_u32(Wi1sm);
    const uint32_t w1base  = smem_to_u32(W1sm);
    const uint32_t abase   = smem_to_u32(Asm);

    const int tid = threadIdx.x;
    const int lane = tid & 31;
    const int wid = tid >> 5;
    const int wm = wid & 3;              // 16-row m tile
    const int wn = wid >> 2;             // h-col half (0/1)
    const int bx = blockIdx.x & 3;
    const int by = blockIdx.x >> 2;
    const int b0 = bx * 64;
    const int c0 = by * 16;

    // ---- load 3 resident W slices: [n][k], n = g*16+hc
    for (int idx = tid; idx < 64 * 384; idx += 256) {
        int n = idx / 384, k = idx - n * 384;
        int g = n >> 4, hc = n & 15;
        size_t grow = (size_t)(g * Hh + c0 + hc) * Hh + k;
        int d = n * 392 + k;
        W0sm[d]  = __float2bfloat16(Whh0[grow]);
        Wi1sm[d] = __float2bfloat16(Wih1[grow]);
        W1sm[d]  = __float2bfloat16(Whh1[grow]);
    }

    const uint32_t a_off =
        (uint32_t)(((wm * 16 + (lane & 15)) * 392 + (lane >> 4) * 8) * 2);
    const uint32_t b_k = ((lane >> 3) & 1) * 8;
    const uint32_t b_off0 =
        (uint32_t)((((0 + (lane >> 4)) * 16 + wn * 8 + (lane & 7)) * 392 + b_k) * 2);
    const uint32_t b_off1 =
        (uint32_t)((((2 + (lane >> 4)) * 16 + wn * 8 + (lane & 7)) * 392 + b_k) * 2);

    const int prow = lane >> 2;          // 0..7
    const int pcol = (lane & 3) * 2;     // 0,2,4,6
    const int colg = c0 + wn * 8 + pcol;

    float bi1[4][2];
#pragma unroll
    for (int g = 0; g < 4; g++)
#pragma unroll
        for (int q = 0; q < 2; q++)
            bi1[g][q] = bih1[g * Hh + colg + q] + bhh1[g * Hh + colg + q];

    float cst0[4], cst1[4];
#pragma unroll
    for (int i = 0; i < 4; i++) { cst0[i] = 0.f; cst1[i] = 0.f; }

    for (int t = 0; t <= Tt; t++) {
        const int ph = t & 1;
        const bool doL0 = (t < Tt);
        const bool doL1 = (t >= 1);

        // ---- xw(t) fragments (bf16): issue BEFORE the barrier wait so the
        //      DRAM latency hides under bar0 propagation.
        float2 xv[4][2];
        if (doL0) {
            const bf16* xw = g_xwb + (size_t)t * Bb * G4;
#pragma unroll
            for (int g = 0; g < 4; g++)
#pragma unroll
                for (int p = 0; p < 2; p++) {
                    int brow = b0 + wm * 16 + prow + p * 8;
                    xv[g][p] = __bfloat1622float2(
                        *(const __nv_bfloat162*)(xw + (size_t)brow * G4 + g * Hh + colg));
                }
        }

        if (t) bar_wait(bx, (unsigned int)t);   // h0(t-1) published

        // ---- load A = h0(t-1) tile (used by L0 recurrence and L1 input)
        {
            const bf16* hprev0 = g_h0buf + (size_t)ph * Bb * Hh;
#pragma unroll
            for (int it = 0; it < 12; it++) {
                int idx = tid + it * 256;
                int row = idx / 48, c = idx - row * 48;
                CP_ASYNC16(abase + (uint32_t)((row * 392 + c * 8) * 2),
                           hprev0 + (size_t)(b0 + row) * Hh + c * 8);
            }
            CP_COMMIT(); CP_WAIT0();
            __syncthreads();
        }

        // ================= phase A : layer-0 step t =================
        if (doL0) {
            float accL0[4][4];
#pragma unroll
            for (int j = 0; j < 4; j++)
#pragma unroll
                for (int q = 0; q < 4; q++) accL0[j][q] = 0.f;
            mma_pass24(accL0, abase, w0base, a_off, b_off0, b_off1);

            bf16* hnext0 = g_h0buf + (size_t)(ph ^ 1) * Bb * Hh;
#pragma unroll
            for (int p = 0; p < 2; p++) {
                int brow = b0 + wm * 16 + prow + p * 8;
                float hnv[2];
#pragma unroll
                for (int q = 0; q < 2; q++) {
                    float xi = q ? xv[0][p].y : xv[0][p].x;
                    float xf = q ? xv[1][p].y : xv[1][p].x;
                    float xg = q ? xv[2][p].y : xv[2][p].x;
                    float xo = q ? xv[3][p].y : xv[3][p].x;
                    float i_ = sig_ap(accL0[0][p * 2 + q] + xi);
                    float f_ = sig_ap(accL0[1][p * 2 + q] + xf);
                    float g_ = tanh_ap(accL0[2][p * 2 + q] + xg);
                    float o_ = sig_ap(accL0[3][p * 2 + q] + xo);
                    float cn = f_ * cst0[p * 2 + q] + i_ * g_;
                    cst0[p * 2 + q] = cn;
                    hnv[q] = o_ * tanh_ap(cn);
                }
                *(__nv_bfloat162*)(hnext0 + (size_t)brow * Hh + colg) =
                    __floats2bfloat162_rn(hnv[0], hnv[1]);
            }
            // publish h0(t) NOW — neighbors' next-interval wait overlaps our
            // entire phase B below.
            bar_arrive(bx, (unsigned int)(t + 1));
        }

        // ================= phase B : layer-1 step t-1 =================
        if (doL1) {
            float accL1[4][4];
#pragma unroll
            for (int j = 0; j < 4; j++)
#pragma unroll
                for (int q = 0; q < 4; q++) accL1[j][q] = 0.f;
            mma_pass24(accL1, abase, wi1base, a_off, b_off0, b_off1);
            __syncthreads();                 // all warps done reading Asm

            bar_wait(4 + bx, (unsigned int)(t - 1));   // h1(t-2) published
            {
                const bf16* hprev1 = g_h1buf + (size_t)ph * Bb * Hh;
#pragma unroll
                for (int it = 0; it < 12; it++) {
                    int idx = tid + it * 256;
                    int row = idx / 48, c = idx - row * 48;
                    CP_ASYNC16(abase + (uint32_t)((row * 392 + c * 8) * 2),
                               hprev1 + (size_t)(b0 + row) * Hh + c * 8);
                }
                CP_COMMIT(); CP_WAIT0();
                __syncthreads();
            }
            mma_pass24(accL1, abase, w1base, a_off, b_off0, b_off1);

            bf16* hnext1 = g_h1buf + (size_t)(ph ^ 1) * Bb * Hh;
            bf16* houtp  = g_h1b + (size_t)(t - 1) * Bb * Hh;
#pragma unroll
            for (int p = 0; p < 2; p++) {
                int brow = b0 + wm * 16 + prow + p * 8;
                float hnv[2];
#pragma unroll
                for (int q = 0; q < 2; q++) {
                    float i_ = sig_ap(accL1[0][p * 2 + q] + bi1[0][q]);
                    float f_ = sig_ap(accL1[1][p * 2 + q] + bi1[1][q]);
                    float g_ = tanh_ap(accL1[2][p * 2 + q] + bi1[2][q]);
                    float o_ = sig_ap(accL1[3][p * 2 + q] + bi1[3][q]);
                    float cn = f_ * cst1[p * 2 + q] + i_ * g_;
                    cst1[p * 2 + q] = cn;
                    hnv[q] = o_ * tanh_ap(cn);
                }
                __nv_bfloat162 hh = __floats2bfloat162_rn(hnv[0], hnv[1]);
                *(__nv_bfloat162*)(hnext1 + (size_t)brow * Hh + colg) = hh;
                *(__nv_bfloat162*)(houtp + (size_t)brow * Hh + colg) = hh;
            }
            bar_arrive(4 + bx, (unsigned int)t);       // publish h1(t-1)
        }
    }
}

// ------------------------- emissions (N=10 skinny GEMM) --------------------
__global__ __launch_bounds__(256) void em_kernel(
    const bf16* __restrict__ A, const float* __restrict__ W3,
    const float* __restrict__ b3, float* __restrict__ em)
{
    int row  = blockIdx.x * (blockDim.x >> 5) + (threadIdx.x >> 5);
    int lane = threadIdx.x & 31;
    float acc[Kc];
#pragma unroll
    for (int j = 0; j < Kc; j++) acc[j] = 0.f;
    const __nv_bfloat162* ar = (const __nv_bfloat162*)(A + (size_t)row * 1024);
    for (int k2 = lane; k2 < 512; k2 += 32) {
        float2 a = __bfloat1622float2(ar[k2]);
#pragma unroll
        for (int j = 0; j < Kc; j++) {
            acc[j] += a.x * W3[j * 1024 + 2 * k2] + a.y * W3[j * 1024 + 2 * k2 + 1];
        }
    }
#pragma unroll
    for (int j = 0; j < Kc; j++) {
#pragma unroll
        for (int off = 16; off; off >>= 1)
            acc[j] += __shfl_xor_sync(0xffffffffu, acc[j], off);
    }
    if (lane == 0) {
#pragma unroll
        for (int j = 0; j < Kc; j++) em[(size_t)row * Kc + j] = acc[j] + b3[j];
    }
}

// ------------------------------ CRF ----------------------------------------
__global__ __launch_bounds__(32) void crf_kernel(
    const float* __restrict__ em, const int* __restrict__ tags,
    const float* __restrict__ start_t, const float* __restrict__ end_t,
    const float* __restrict__ trans)
{
    const int bp   = blockIdx.x;
    const int lane = threadIdx.x;
    const float NEG = -1e30f;

    float tr[Kc];
    int cl = (lane < Kc) ? lane : 0;
#pragma unroll
    for (int i = 0; i < Kc; i++) tr[i] = trans[i * Kc + cl];

    float a = (lane < Kc) ? (start_t[lane] + em[((size_t)bp * Tt) * Kc + lane]) : NEG;

    for (int tp = 1; tp < Tt; tp++) {
        float e = (lane < Kc) ? em[((size_t)bp * Tt + tp) * Kc + lane] : 0.f;
        float v[Kc];
        float m = NEG;
#pragma unroll
        for (int i = 0; i < Kc; i++) {
            float ai = __shfl_sync(0xffffffffu, a, i);
            v[i] = ai + tr[i];
            m = fmaxf(m, v[i]);
        }
        float s = 0.f;
#pragma unroll
        for (int i = 0; i < Kc; i++) s += __expf(v[i] - m);
        float an = m + __logf(s) + e;
        a = (lane < Kc) ? an : NEG;
    }

    float z = (lane < Kc) ? (a + end_t[lane]) : NEG;
    float zmax = z;
#pragma unroll
    for (int off = 16; off; off >>= 1)
        zmax = fmaxf(zmax, __shfl_xor_sync(0xffffffffu, zmax, off));
    float zs = (lane < Kc) ? __expf(z - zmax) : 0.f;
#pragma unroll
    for (int off = 16; off; off >>= 1)
        zs += __shfl_xor_sync(0xffffffffu, zs, off);
    float logZ = zmax + __logf(zs);

    if (lane == 0) {
        int prev = tags[(size_t)bp * Tt];
        float score = start_t[prev] + em[((size_t)bp * Tt) * Kc + prev];
        for (int tp = 1; tp < Tt; tp++) {
            int tg = tags[(size_t)bp * Tt + tp];
            score += trans[prev * Kc + tg] + em[((size_t)bp * Tt + tp) * Kc + tg];
            prev = tg;
        }
        score += end_t[prev];
        g_partial[bp] = logZ - score;
    }
}

__global__ __launch_bounds__(256) void reduce_kernel(float* __restrict__ out)
{
    __shared__ float sh[256];
    int i = threadIdx.x;
    sh[i] = g_partial[i];
    __syncthreads();
#pragma unroll
    for (int s = 128; s; s >>= 1) {
        if (i < s) sh[i] += sh[i + s];
        __syncthreads();
    }
    if (i == 0) out[0] = sh[0];
}

// ------------------------------ launch -------------------------------------
extern "C" void kernel_launch(void* const* d_in, const int* in_sizes, int n_in,
                              void* d_out, int out_size)
{
    (void)in_sizes; (void)n_in; (void)out_size;
    const float* x    = (const float*)d_in[0];
    const int*   tags = (const int*)d_in[2];
    const float* Wih0 = (const float*)d_in[3];
    const float* Whh0 = (const float*)d_in[4];
    const float* bih0 = (const float*)d_in[5];
    const float* bhh0 = (const float*)d_in[6];
    const float* Wih1 = (const float*)d_in[7];
    const float* Whh1 = (const float*)d_in[8];
    const float* bih1 = (const float*)d_in[9];
    const float* bhh1 = (const float*)d_in[10];
    const float* W1   = (const float*)d_in[11];
    const float* b1   = (const float*)d_in[12];
    const float* W2   = (const float*)d_in[13];
    const float* b2   = (const float*)d_in[14];
    const float* W3   = (const float*)d_in[15];
    const float* b3   = (const float*)d_in[16];
    const float* st   = (const float*)d_in[17];
    const float* et   = (const float*)d_in[18];
    const float* trn  = (const float*)d_in[19];

    float *emb;
    bf16 *xwb, *xb, *h1b, *m1b, *m2b, *wih0b, *w1b, *w2b;
    cudaGetSymbolAddress((void**)&xwb,   g_xwb);
    cudaGetSymbolAddress((void**)&emb,   g_em);
    cudaGetSymbolAddress((void**)&xb,    g_xb);
    cudaGetSymbolAddress((void**)&h1b,   g_h1b);
    cudaGetSymbolAddress((void**)&m1b,   g_m1b);
    cudaGetSymbolAddress((void**)&m2b,   g_m2b);
    cudaGetSymbolAddress((void**)&wih0b, g_wih0b);
    cudaGetSymbolAddress((void**)&w1b,   g_w1b);
    cudaGetSymbolAddress((void**)&w2b,   g_w2b);

    const int M = Tt * Bb;  // 65536
    const size_t LSTM_SMEM = (size_t)(4 * 64 * 392) * sizeof(bf16);  // 200704 B
    cudaFuncSetAttribute(lstm_fused, cudaFuncAttributeMaxDynamicSharedMemorySize,
                         (int)LSTM_SMEM);

    init_state_kernel<<<(2 * Bb * Hh + 255) / 256, 256>>>();                 // 0
    conv_all<<<8192, 256>>>(x, Wih0, W1, W2);                                // 1

    // xw0 = x @ Wih0^T + (bih0+bhh0)  (bf16 output)
    mma_gemm<<<dim3(G4 / 128, M / 128), 256>>>(xb, wih0b, bih0, bhh0,        // 2
                                               nullptr, xwb, M, G4, 128);
    // fused 2-layer recurrence with split barriers
    lstm_fused<<<NCTA_LSTM, 256, LSTM_SMEM>>>(Whh0, Wih1, Whh1, bih1, bhh1); // 3

    // MLP
    mma_gemm<<<dim3(512 / 128, M / 128), 256>>>(h1b, w1b, b1, nullptr,       // 4
                                                nullptr, m1b, M, 512, Hh);
    mma_gemm<<<dim3(1024 / 128, M / 128), 256>>>(m1b, w2b, b2, nullptr,      // 5
                                                 nullptr, m2b, M, 1024, 512);
    em_kernel<<<M / 8, 256>>>(m2b, W3, b3, emb);                             // 6

    crf_kernel<<<Bb, 32>>>(emb, tags, st, et, trn);                          // 7
    reduce_kernel<<<1, 256>>>((float*)d_out);                                // 8
}

// round 10
// speedup vs baseline: 1.1284x; 1.1284x over previous
#include <cuda_runtime.h>
#include <cuda_bf16.h>
#include <cstdint>
#include <cstddef>

// ---------------------------------------------------------------------------
// BiLSTM-NER, Round 9: R7 base (single end-of-interval group barrier) +
//  * pass1/pass2 fused (shared A ldsm, interleaved mma chains)
//  * h1 tile load split + fully hidden under mma (25.6KB side buffer +
//    reuse of A0's upper half after the fused pass releases it)
//  * xw pre-activations in bf16 (halves g_xw traffic)
// ---------------------------------------------------------------------------

#define Tt 256
#define Bb 256
#define Hh 384
#define G4 1536   // 4*H
#define INP 100
#define Kc 10
#define NCTA_LSTM 96

typedef __nv_bfloat16 bf16;

// ============================ PTX helpers ==================================
__device__ __forceinline__ uint32_t smem_to_u32(const void* p) {
    uint32_t a;
    asm("{ .reg .u64 t; cvta.to.shared.u64 t, %1; cvt.u32.u64 %0, t; }"
        : "=r"(a) : "l"(p));
    return a;
}
__device__ __forceinline__ void ldsm4(uint32_t* r, uint32_t saddr) {
    asm volatile("ldmatrix.sync.aligned.m8n8.x4.shared.b16 {%0,%1,%2,%3}, [%4];"
        : "=r"(r[0]), "=r"(r[1]), "=r"(r[2]), "=r"(r[3]) : "r"(saddr));
}
__device__ __forceinline__ void mma_bf16(float* c, const uint32_t* a, const uint32_t* b) {
    asm volatile(
        "mma.sync.aligned.m16n8k16.row.col.f32.bf16.bf16.f32 "
        "{%0,%1,%2,%3}, {%4,%5,%6,%7}, {%8,%9}, {%0,%1,%2,%3};"
        : "+f"(c[0]), "+f"(c[1]), "+f"(c[2]), "+f"(c[3])
        : "r"(a[0]), "r"(a[1]), "r"(a[2]), "r"(a[3]), "r"(b[0]), "r"(b[1]));
}
#define CP_ASYNC16(sa, ga) \
    asm volatile("cp.async.cg.shared.global [%0], [%1], 16;" \
                 :: "r"(sa), "l"(ga) : "memory")
#define CP_COMMIT() asm volatile("cp.async.commit_group;" ::: "memory")
#define CP_WAIT0()  asm volatile("cp.async.wait_group 0;" ::: "memory")
#define CP_WAIT1()  asm volatile("cp.async.wait_group 1;" ::: "memory")

__device__ __forceinline__ float tanh_ap(float x) {
    float y; asm("tanh.approx.f32 %0, %1;" : "=f"(y) : "f"(x)); return y;
}
__device__ __forceinline__ float sig_ap(float x) {
    return fmaf(tanh_ap(0.5f * x), 0.5f, 0.5f);
}

// ------------------------- scratch (device globals) ------------------------
__device__ bf16  g_xwb[(size_t)Tt * Bb * G4];      // layer-0 gate pre-acts (bf16)
__device__ bf16  g_xb[(size_t)Tt * Bb * 128];      // x padded to K=128, bf16
__device__ bf16  g_h1b[(size_t)Tt * Bb * Hh];      // layer1 outputs (bf16)
__device__ bf16  g_m1b[(size_t)Tt * Bb * 512];     // MLP hidden 1 (bf16)
__device__ bf16  g_m2b[(size_t)Tt * Bb * 1024];    // MLP hidden 2 (bf16)
__device__ float g_em[(size_t)Tt * Bb * Kc];       // emissions (fp32)
__device__ bf16  g_wih0b[1536 * 128];              // Wih0 padded K=128
__device__ bf16  g_w1b[512 * 384];
__device__ bf16  g_w2b[1024 * 512];
__device__ bf16  g_h0buf[2 * Bb * Hh];             // recurrent h0 state (bf16)
__device__ bf16  g_h1buf[2 * Bb * Hh];             // recurrent h1 state (bf16)
__device__ float g_partial[Bb];

// 4 independent barrier groups (counters/gens on separate 256B lines)
__device__ unsigned int          g_barcnt4[4 * 64];
__device__ volatile unsigned int g_bargen4[4 * 64];

// ------------------------------ init state --------------------------------
__global__ void init_state_kernel() {
    int i = blockIdx.x * blockDim.x + threadIdx.x;
    if (i < 2 * Bb * Hh) {
        g_h0buf[i] = __float2bfloat16(0.f);
        g_h1buf[i] = __float2bfloat16(0.f);
    }
    if (i < 4 * 64) { g_barcnt4[i] = 0u; g_bargen4[i] = 0u; }
}

// ---------------------- merged bf16 conversions ----------------------------
#define S0 (65536 * 128)
#define S1 (1536 * 128)
#define S3 (512 * 384)
#define S4 (1024 * 512)
__global__ __launch_bounds__(256) void conv_all(
    const float* __restrict__ x, const float* __restrict__ Wih0,
    const float* __restrict__ W1, const float* __restrict__ W2)
{
    const int total = S0 + S1 + S3 + S4;
    for (int i = blockIdx.x * blockDim.x + threadIdx.x; i < total;
         i += gridDim.x * blockDim.x) {
        if (i < S0) {
            int r = i >> 7, c = i & 127;
            g_xb[i] = (c < INP) ? __float2bfloat16(x[(size_t)r * INP + c])
                                : __float2bfloat16(0.f);
        } else if (i < S0 + S1) {
            int j = i - S0;
            int r = j >> 7, c = j & 127;
            g_wih0b[j] = (c < INP) ? __float2bfloat16(Wih0[(size_t)r * INP + c])
                                   : __float2bfloat16(0.f);
        } else if (i < S0 + S1 + S3) {
            int j = i - S0 - S1;
            g_w1b[j] = __float2bfloat16(W1[j]);
        } else {
            int j = i - S0 - S1 - S3;
            g_w2b[j] = __float2bfloat16(W2[j]);
        }
    }
}

// ------------------ per-batch-group grid barrier (24 CTAs) ------------------
__device__ __forceinline__ void group_barrier(int grp) {
    __threadfence();
    __syncthreads();
    if (threadIdx.x == 0) {
        const int s = grp * 64;
        unsigned int gen = g_bargen4[s];
        if (atomicAdd(&g_barcnt4[s], 1u) == 23u) {
            g_barcnt4[s] = 0u;
            __threadfence();
            g_bargen4[s] = gen + 1u;
        } else {
            while (g_bargen4[s] == gen) { }
        }
    }
    __syncthreads();
}

// ======================== HMMA feed-forward GEMM ===========================
__global__ __launch_bounds__(256) void mma_gemm(
    const bf16* __restrict__ A, const bf16* __restrict__ B,
    const float* __restrict__ bias1, const float* __restrict__ bias2,
    float* __restrict__ Cf, bf16* __restrict__ Cb,
    int M, int N, int K)
{
    __shared__ __align__(16) bf16 smA[2][128 * 40];
    __shared__ __align__(16) bf16 smB[2][128 * 40];

    const int tid = threadIdx.x;
    const int lane = tid & 31;
    const int wid = tid >> 5;
    const int wm = wid & 3;
    const int wn = wid >> 2;
    const int m0 = blockIdx.y * 128;
    const int n0 = blockIdx.x * 128;

    const uint32_t saddrA[2] = { smem_to_u32(smA[0]), smem_to_u32(smA[1]) };
    const uint32_t saddrB[2] = { smem_to_u32(smB[0]), smem_to_u32(smB[1]) };

    float acc[2][8][4];
#pragma unroll
    for (int i = 0; i < 2; i++)
#pragma unroll
        for (int j = 0; j < 8; j++)
#pragma unroll
            for (int q = 0; q < 4; q++) acc[i][j][q] = 0.f;

    const uint32_t a_off =
        (uint32_t)(((wm * 32 + (lane & 15)) * 40 + (lane >> 4) * 8) * 2);
    uint32_t b_off[4];
#pragma unroll
    for (int jp = 0; jp < 4; jp++)
        b_off[jp] = (uint32_t)(((wn * 64 + jp * 16 + (lane & 7) + ((lane >> 4) << 3)) * 40
                                + ((lane >> 3) & 1) * 8) * 2);

    const int lrow = tid >> 2;
    const int lc   = tid & 3;

    const int nkt = K >> 5;
#pragma unroll
    for (int it = 0; it < 2; it++) {
        int row = lrow + it * 64;
        uint32_t d = (uint32_t)((row * 40 + lc * 8) * 2);
        CP_ASYNC16(saddrA[0] + d, A + (size_t)(m0 + row) * K + lc * 8);
        CP_ASYNC16(saddrB[0] + d, B + (size_t)(n0 + row) * K + lc * 8);
    }
    CP_COMMIT();

    for (int kt = 0; kt < nkt; kt++) {
        CP_WAIT0();
        __syncthreads();
        if (kt + 1 < nkt) {
            int s = (kt + 1) & 1;
            int k0 = (kt + 1) * 32;
#pragma unroll
            for (int it = 0; it < 2; it++) {
                int row = lrow + it * 64;
                uint32_t d = (uint32_t)((row * 40 + lc * 8) * 2);
                CP_ASYNC16(saddrA[s] + d, A + (size_t)(m0 + row) * K + k0 + lc * 8);
                CP_ASYNC16(saddrB[s] + d, B + (size_t)(n0 + row) * K + k0 + lc * 8);
            }
        }
        CP_COMMIT();

        const uint32_t sa = saddrA[kt & 1];
        const uint32_t sb = saddrB[kt & 1];
#pragma unroll
        for (int kk = 0; kk < 2; kk++) {
            uint32_t a[2][4], b[4][4];
            ldsm4(a[0], sa + a_off + kk * 32);
            ldsm4(a[1], sa + a_off + 1280 + kk * 32);
#pragma unroll
            for (int jp = 0; jp < 4; jp++)
                ldsm4(b[jp], sb + b_off[jp] + kk * 32);
#pragma unroll
            for (int mt = 0; mt < 2; mt++)
#pragma unroll
                for (int j = 0; j < 8; j++)
                    mma_bf16(acc[mt][j], a[mt], &b[j >> 1][(j & 1) * 2]);
        }
        __syncthreads();
    }

#pragma unroll
    for (int mt = 0; mt < 2; mt++)
#pragma unroll
        for (int j = 0; j < 8; j++)
#pragma unroll
            for (int p = 0; p < 2; p++) {
                int row = m0 + wm * 32 + mt * 16 + (lane >> 2) + p * 8;
                int col = n0 + wn * 64 + j * 8 + (lane & 3) * 2;
                float bb0 = bias1[col], bb1 = bias1[col + 1];
                if (bias2) { bb0 += bias2[col]; bb1 += bias2[col + 1]; }
                float v0 = acc[mt][j][p * 2] + bb0;
                float v1 = acc[mt][j][p * 2 + 1] + bb1;
                if (Cf) {
                    *(float2*)(Cf + (size_t)row * N + col) = make_float2(v0, v1);
                } else {
                    *(__nv_bfloat162*)(Cb + (size_t)row * N + col) =
                        __floats2bfloat162_rn(v0, v1);
                }
            }
}

// ================== fused 2-layer persistent LSTM ==========================
// 96 CTAs (4 batch x 24 colgroups), 256 threads = 8 warps (4m x 2n-half).
// Interval t: fused pass = Whh0@h0(t-1) AND Wih1@h0(t-1) (shared A ldsm),
// then L0 pointwise, then Whh1@h1(t-2) (pass3, A hidden: first half in a
// side buffer loaded at interval start, second half in A0's upper columns
// loaded after the fused pass), then L1 pointwise. Single barrier per
// interval (R7-proven).
__global__ __launch_bounds__(256) void lstm_fused(
    const float* __restrict__ Whh0, const float* __restrict__ Wih1,
    const float* __restrict__ Whh1, const float* __restrict__ bih1,
    const float* __restrict__ bhh1)
{
    extern __shared__ bf16 dsm[];
    bf16* W0sm  = dsm;                    // Whh0 slice  (64n x 392)
    bf16* Wi1sm = dsm + 64 * 392;         // Wih1 slice
    bf16* W1sm  = dsm + 2 * 64 * 392;     // Whh1 slice
    bf16* Asm   = dsm + 3 * 64 * 392;     // A0 tile (64 x 392)
    bf16* A1sm  = dsm + 4 * 64 * 392;     // h1 k-tiles 0..11 (64 x 200)
    const uint32_t w0base  = smem_to_u32(W0sm);
    const uint32_t wi1base = smem_to_u32(Wi1sm);
    const uint32_t w1base  = smem_to_u32(W1sm);
    const uint32_t abase   = smem_to_u32(Asm);
    const uint32_t a1base  = smem_to_u32(A1sm);

    const int tid = threadIdx.x;
    const int lane = tid & 31;
    const int wid = tid >> 5;
    const int wm = wid & 3;              // 16-row m tile
    const int wn = wid >> 2;             // h-col half (0/1)
    const int bx = blockIdx.x & 3;
    const int by = blockIdx.x >> 2;
    const int b0 = bx * 64;
    const int c0 = by * 16;

    // ---- load 3 resident W slices: [n][k], n = g*16+hc
    for (int idx = tid; idx < 64 * 384; idx += 256) {
        int n = idx / 384, k = idx - n * 384;
        int g = n >> 4, hc = n & 15;
        size_t grow = (size_t)(g * Hh + c0 + hc) * Hh + k;
        int d = n * 392 + k;
        W0sm[d]  = __float2bfloat16(Whh0[grow]);
        Wi1sm[d] = __float2bfloat16(Wih1[grow]);
        W1sm[d]  = __float2bfloat16(Whh1[grow]);
    }

    const uint32_t a_off =
        (uint32_t)(((wm * 16 + (lane & 15)) * 392 + (lane >> 4) * 8) * 2);
    const uint32_t a1_off =
        (uint32_t)(((wm * 16 + (lane & 15)) * 200 + (lane >> 4) * 8) * 2);
    const uint32_t b_k = ((lane >> 3) & 1) * 8;
    const uint32_t b_off0 =
        (uint32_t)((((0 + (lane >> 4)) * 16 + wn * 8 + (lane & 7)) * 392 + b_k) * 2);
    const uint32_t b_off1 =
        (uint32_t)((((2 + (lane >> 4)) * 16 + wn * 8 + (lane & 7)) * 392 + b_k) * 2);

    const int prow = lane >> 2;          // 0..7
    const int pcol = (lane & 3) * 2;     // 0,2,4,6
    const int colg = c0 + wn * 8 + pcol;

    float bi1[4][2];
#pragma unroll
    for (int g = 0; g < 4; g++)
#pragma unroll
        for (int q = 0; q < 2; q++)
            bi1[g][q] = bih1[g * Hh + colg + q] + bhh1[g * Hh + colg + q];

    float cst0[4], cst1[4];
#pragma unroll
    for (int i = 0; i < 4; i++) { cst0[i] = 0.f; cst1[i] = 0.f; }

    for (int t = 0; t <= Tt; t++) {
        const int ph = t & 1;
        const bool doL0 = (t < Tt);
        const bool doL1 = (t >= 1);

        // ---- xw(t) fragments (bf16), issued before any waiting
        float2 xv[4][2];
        if (doL0) {
            const bf16* xw = g_xwb + (size_t)t * Bb * G4;
#pragma unroll
            for (int g = 0; g < 4; g++)
#pragma unroll
                for (int p = 0; p < 2; p++) {
                    int brow = b0 + wm * 16 + prow + p * 8;
                    xv[g][p] = __bfloat1622float2(
                        *(const __nv_bfloat162*)(xw + (size_t)brow * G4 + g * Hh + colg));
                }
        }

        // ---- A0 <- h0(t-1) (group 1); A1 <- h1(t-2) k-tiles 0..11 (group 2)
        {
            const bf16* hprev0 = g_h0buf + (size_t)ph * Bb * Hh;
#pragma unroll
            for (int it = 0; it < 12; it++) {
                int idx = tid + it * 256;
                int row = idx / 48, c = idx - row * 48;
                CP_ASYNC16(abase + (uint32_t)((row * 392 + c * 8) * 2),
                           hprev0 + (size_t)(b0 + row) * Hh + c * 8);
            }
            CP_COMMIT();
        }
        if (doL1) {
            const bf16* hprev1 = g_h1buf + (size_t)ph * Bb * Hh;
#pragma unroll
            for (int it = 0; it < 6; it++) {
                int idx = tid + it * 256;
                int row = idx / 24, c = idx - row * 24;
                CP_ASYNC16(a1base + (uint32_t)(row * 400 + c * 16),
                           hprev1 + (size_t)(b0 + row) * Hh + c * 8);
            }
            CP_COMMIT();
            CP_WAIT1();     // A0 complete; A1 may still be in flight
        } else {
            CP_WAIT0();
        }
        __syncthreads();

        // ---- fused pass: Whh0@h0 and Wih1@h0, shared A fragments
        float accL0[4][4], accL1[4][4];
#pragma unroll
        for (int j = 0; j < 4; j++)
#pragma unroll
            for (int q = 0; q < 4; q++) { accL0[j][q] = 0.f; accL1[j][q] = 0.f; }

#pragma unroll 4
        for (int kt = 0; kt < 24; kt++) {
            uint32_t koff = (uint32_t)(kt * 32);
            uint32_t a[4], p0[4], p1[4], q0[4], q1[4];
            ldsm4(a, abase + a_off + koff);
            ldsm4(p0, w0base + b_off0 + koff);
            ldsm4(p1, w0base + b_off1 + koff);
            ldsm4(q0, wi1base + b_off0 + koff);
            ldsm4(q1, wi1base + b_off1 + koff);
            mma_bf16(accL0[0], a, &p0[0]);
            mma_bf16(accL1[0], a, &q0[0]);
            mma_bf16(accL0[1], a, &p0[2]);
            mma_bf16(accL1[1], a, &q0[2]);
            mma_bf16(accL0[2], a, &p1[0]);
            mma_bf16(accL1[2], a, &q1[0]);
            mma_bf16(accL0[3], a, &p1[2]);
            mma_bf16(accL1[3], a, &q1[2]);
        }
        __syncthreads();    // all warps done reading A0

        // ---- issue h1 k-tiles 12..23 into A0 cols 192..383 (group)
        if (doL1) {
            const bf16* hprev1 = g_h1buf + (size_t)ph * Bb * Hh;
#pragma unroll
            for (int it = 0; it < 6; it++) {
                int idx = tid + it * 256;
                int row = idx / 24, c = idx - row * 24;
                CP_ASYNC16(abase + (uint32_t)(row * 784 + 384 + c * 16),
                           hprev1 + (size_t)(b0 + row) * Hh + 192 + c * 8);
            }
            CP_COMMIT();
        }

        // ---- L0 pointwise: h0(t) -> h0buf[ph^1] (overlaps the load above)
        if (doL0) {
            bf16* hnext0 = g_h0buf + (size_t)(ph ^ 1) * Bb * Hh;
#pragma unroll
            for (int p = 0; p < 2; p++) {
                int brow = b0 + wm * 16 + prow + p * 8;
                float hnv[2];
#pragma unroll
                for (int q = 0; q < 2; q++) {
                    float xi = q ? xv[0][p].y : xv[0][p].x;
                    float xf = q ? xv[1][p].y : xv[1][p].x;
                    float xg = q ? xv[2][p].y : xv[2][p].x;
                    float xo = q ? xv[3][p].y : xv[3][p].x;
                    float i_ = sig_ap(accL0[0][p * 2 + q] + xi);
                    float f_ = sig_ap(accL0[1][p * 2 + q] + xf);
                    float g_ = tanh_ap(accL0[2][p * 2 + q] + xg);
                    float o_ = sig_ap(accL0[3][p * 2 + q] + xo);
                    float cn = f_ * cst0[p * 2 + q] + i_ * g_;
                    cst0[p * 2 + q] = cn;
                    hnv[q] = o_ * tanh_ap(cn);
                }
                *(__nv_bfloat162*)(hnext0 + (size_t)brow * Hh + colg) =
                    __floats2bfloat162_rn(hnv[0], hnv[1]);
            }
        }

        // ---- pass3: Whh1@h1(t-2); halves from A1 then A0-upper
        if (doL1) {
            CP_WAIT1();      // A1 (k-tiles 0..11) complete
            __syncthreads();
#pragma unroll 4
            for (int kt = 0; kt < 12; kt++) {
                uint32_t koff = (uint32_t)(kt * 32);
                uint32_t a[4], b0v[4], b1v[4];
                ldsm4(a, a1base + a1_off + koff);
                ldsm4(b0v, w1base + b_off0 + koff);
                ldsm4(b1v, w1base + b_off1 + koff);
                mma_bf16(accL1[0], a, &b0v[0]);
                mma_bf16(accL1[1], a, &b0v[2]);
                mma_bf16(accL1[2], a, &b1v[0]);
                mma_bf16(accL1[3], a, &b1v[2]);
            }
            CP_WAIT0();      // A0-upper (k-tiles 12..23) complete
            __syncthreads();
#pragma unroll 4
            for (int kt = 12; kt < 24; kt++) {
                uint32_t koff = (uint32_t)(kt * 32);
                uint32_t a[4], b0v[4], b1v[4];
                ldsm4(a, abase + a_off + koff);
                ldsm4(b0v, w1base + b_off0 + koff);
                ldsm4(b1v, w1base + b_off1 + koff);
                mma_bf16(accL1[0], a, &b0v[0]);
                mma_bf16(accL1[1], a, &b0v[2]);
                mma_bf16(accL1[2], a, &b1v[0]);
                mma_bf16(accL1[3], a, &b1v[2]);
            }

            bf16* hnext1 = g_h1buf + (size_t)(ph ^ 1) * Bb * Hh;
            bf16* houtp  = g_h1b + (size_t)(t - 1) * Bb * Hh;
#pragma unroll
            for (int p = 0; p < 2; p++) {
                int brow = b0 + wm * 16 + prow + p * 8;
                float hnv[2];
#pragma unroll
                for (int q = 0; q < 2; q++) {
                    float i_ = sig_ap(accL1[0][p * 2 + q] + bi1[0][q]);
                    float f_ = sig_ap(accL1[1][p * 2 + q] + bi1[1][q]);
                    float g_ = tanh_ap(accL1[2][p * 2 + q] + bi1[2][q]);
                    float o_ = sig_ap(accL1[3][p * 2 + q] + bi1[3][q]);
                    float cn = f_ * cst1[p * 2 + q] + i_ * g_;
                    cst1[p * 2 + q] = cn;
                    hnv[q] = o_ * tanh_ap(cn);
                }
                __nv_bfloat162 hh = __floats2bfloat162_rn(hnv[0], hnv[1]);
                *(__nv_bfloat162*)(hnext1 + (size_t)brow * Hh + colg) = hh;
                *(__nv_bfloat162*)(houtp + (size_t)brow * Hh + colg) = hh;
            }
        }

        group_barrier(bx);
    }
}

// ------------------------- emissions (N=10 skinny GEMM) --------------------
__global__ __launch_bounds__(256) void em_kernel(
    const bf16* __restrict__ A, const float* __restrict__ W3,
    const float* __restrict__ b3, float* __restrict__ em)
{
    int row  = blockIdx.x * (blockDim.x >> 5) + (threadIdx.x >> 5);
    int lane = threadIdx.x & 31;
    float acc[Kc];
#pragma unroll
    for (int j = 0; j < Kc; j++) acc[j] = 0.f;
    const __nv_bfloat162* ar = (const __nv_bfloat162*)(A + (size_t)row * 1024);
    for (int k2 = lane; k2 < 512; k2 += 32) {
        float2 a = __bfloat1622float2(ar[k2]);
#pragma unroll
        for (int j = 0; j < Kc; j++) {
            acc[j] += a.x * W3[j * 1024 + 2 * k2] + a.y * W3[j * 1024 + 2 * k2 + 1];
        }
    }
#pragma unroll
    for (int j = 0; j < Kc; j++) {
#pragma unroll
        for (int off = 16; off; off >>= 1)
            acc[j] += __shfl_xor_sync(0xffffffffu, acc[j], off);
    }
    if (lane == 0) {
#pragma unroll
        for (int j = 0; j < Kc; j++) em[(size_t)row * Kc + j] = acc[j] + b3[j];
    }
}

// ------------------------------ CRF ----------------------------------------
__global__ __launch_bounds__(32) void crf_kernel(
    const float* __restrict__ em, const int* __restrict__ tags,
    const float* __restrict__ start_t, const float* __restrict__ end_t,
    const float* __restrict__ trans)
{
    const int bp   = blockIdx.x;
    const int lane = threadIdx.x;
    const float NEG = -1e30f;

    float tr[Kc];
    int cl = (lane < Kc) ? lane : 0;
#pragma unroll
    for (int i = 0; i < Kc; i++) tr[i] = trans[i * Kc + cl];

    float a = (lane < Kc) ? (start_t[lane] + em[((size_t)bp * Tt) * Kc + lane]) : NEG;

    for (int tp = 1; tp < Tt; tp++) {
        float e = (lane < Kc) ? em[((size_t)bp * Tt + tp) * Kc + lane] : 0.f;
        float v[Kc];
        float m = NEG;
#pragma unroll
        for (int i = 0; i < Kc; i++) {
            float ai = __shfl_sync(0xffffffffu, a, i);
            v[i] = ai + tr[i];
            m = fmaxf(m, v[i]);
        }
        float s = 0.f;
#pragma unroll
        for (int i = 0; i < Kc; i++) s += __expf(v[i] - m);
        float an = m + __logf(s) + e;
        a = (lane < Kc) ? an : NEG;
    }

    float z = (lane < Kc) ? (a + end_t[lane]) : NEG;
    float zmax = z;
#pragma unroll
    for (int off = 16; off; off >>= 1)
        zmax = fmaxf(zmax, __shfl_xor_sync(0xffffffffu, zmax, off));
    float zs = (lane < Kc) ? __expf(z - zmax) : 0.f;
#pragma unroll
    for (int off = 16; off; off >>= 1)
        zs += __shfl_xor_sync(0xffffffffu, zs, off);
    float logZ = zmax + __logf(zs);

    if (lane == 0) {
        int prev = tags[(size_t)bp * Tt];
        float score = start_t[prev] + em[((size_t)bp * Tt) * Kc + prev];
        for (int tp = 1; tp < Tt; tp++) {
            int tg = tags[(size_t)bp * Tt + tp];
            score += trans[prev * Kc + tg] + em[((size_t)bp * Tt + tp) * Kc + tg];
            prev = tg;
        }
        score += end_t[prev];
        g_partial[bp] = logZ - score;
    }
}

__global__ __launch_bounds__(256) void reduce_kernel(float* __restrict__ out)
{
    __shared__ float sh[256];
    int i = threadIdx.x;
    sh[i] = g_partial[i];
    __syncthreads();
#pragma unroll
    for (int s = 128; s; s >>= 1) {
        if (i < s) sh[i] += sh[i + s];
        __syncthreads();
    }
    if (i == 0) out[0] = sh[0];
}

// ------------------------------ launch -------------------------------------
extern "C" void kernel_launch(void* const* d_in, const int* in_sizes, int n_in,
                              void* d_out, int out_size)
{
    (void)in_sizes; (void)n_in; (void)out_size;
    const float* x    = (const float*)d_in[0];
    const int*   tags = (const int*)d_in[2];
    const float* Wih0 = (const float*)d_in[3];
    const float* Whh0 = (const float*)d_in[4];
    const float* bih0 = (const float*)d_in[5];
    const float* bhh0 = (const float*)d_in[6];
    const float* Wih1 = (const float*)d_in[7];
    const float* Whh1 = (const float*)d_in[8];
    const float* bih1 = (const float*)d_in[9];
    const float* bhh1 = (const float*)d_in[10];
    const float* W1   = (const float*)d_in[11];
    const float* b1   = (const float*)d_in[12];
    const float* W2   = (const float*)d_in[13];
    const float* b2   = (const float*)d_in[14];
    const float* W3   = (const float*)d_in[15];
    const float* b3   = (const float*)d_in[16];
    const float* st   = (const float*)d_in[17];
    const float* et   = (const float*)d_in[18];
    const float* trn  = (const float*)d_in[19];

    float *emb;
    bf16 *xwb, *xb, *h1b, *m1b, *m2b, *wih0b, *w1b, *w2b;
    cudaGetSymbolAddress((void**)&xwb,   g_xwb);
    cudaGetSymbolAddress((void**)&emb,   g_em);
    cudaGetSymbolAddress((void**)&xb,    g_xb);
    cudaGetSymbolAddress((void**)&h1b,   g_h1b);
    cudaGetSymbolAddress((void**)&m1b,   g_m1b);
    cudaGetSymbolAddress((void**)&m2b,   g_m2b);
    cudaGetSymbolAddress((void**)&wih0b, g_wih0b);
    cudaGetSymbolAddress((void**)&w1b,   g_w1b);
    cudaGetSymbolAddress((void**)&w2b,   g_w2b);

    const int M = Tt * Bb;  // 65536
    // SMEM: 3 W slices + A0 (each 64x392 bf16) + A1 (64x200 bf16) = 226304 B
    const size_t LSTM_SMEM = (size_t)(4 * 64 * 392 + 64 * 200) * sizeof(bf16);
    cudaFuncSetAttribute(lstm_fused, cudaFuncAttributeMaxDynamicSharedMemorySize,
                         (int)LSTM_SMEM);

    init_state_kernel<<<(2 * Bb * Hh + 255) / 256, 256>>>();                 // 0
    conv_all<<<8192, 256>>>(x, Wih0, W1, W2);                                // 1

    // xw0 = x @ Wih0^T + (bih0+bhh0)  (bf16 output)
    mma_gemm<<<dim3(G4 / 128, M / 128), 256>>>(xb, wih0b, bih0, bhh0,        // 2
                                               nullptr, xwb, M, G4, 128);
    // fused 2-layer recurrence
    lstm_fused<<<NCTA_LSTM, 256, LSTM_SMEM>>>(Whh0, Wih1, Whh1, bih1, bhh1); // 3

    // MLP
    mma_gemm<<<dim3(512 / 128, M / 128), 256>>>(h1b, w1b, b1, nullptr,       // 4
                                                nullptr, m1b, M, 512, Hh);
    mma_gemm<<<dim3(1024 / 128, M / 128), 256>>>(m1b, w2b, b2, nullptr,      // 5
                                                 nullptr, m2b, M, 1024, 512);
    em_kernel<<<M / 8, 256>>>(m2b, W3, b3, emb);                             // 6

    crf_kernel<<<Bb, 32>>>(emb, tags, st, et, trn);                          // 7
    reduce_kernel<<<1, 256>>>((float*)d_out);                                // 8
}

// round 11
// speedup vs baseline: 1.3120x; 1.1627x over previous
#include <cuda_runtime.h>
#include <cuda_bf16.h>
#include <cstdint>
#include <cstddef>

// ---------------------------------------------------------------------------
// BiLSTM-NER, Round 10:
//  * MLP COLLAPSED: the reference MLP is purely affine, so
//    em = h1 @ (W3*W2*W1)^T + (W3*W2*b1 + W3*b2 + b3). Two HMMA GEMMs and
//    ~330MB of traffic replaced by a 10x384 composed weight + skinny GEMM.
//  * Grid barrier: release/acquire flag array (no atomic chain, no
//    __threadfence) — one flag per CTA on its own 128B line.
//  * LSTM dataflow unchanged from R9 (proven 2837us).
// ---------------------------------------------------------------------------

#define Tt 256
#define Bb 256
#define Hh 384
#define G4 1536   // 4*H
#define INP 100
#define Kc 10
#define NCTA_LSTM 96

typedef __nv_bfloat16 bf16;

// ============================ PTX helpers ==================================
__device__ __forceinline__ uint32_t smem_to_u32(const void* p) {
    uint32_t a;
    asm("{ .reg .u64 t; cvta.to.shared.u64 t, %1; cvt.u32.u64 %0, t; }"
        : "=r"(a) : "l"(p));
    return a;
}
__device__ __forceinline__ void ldsm4(uint32_t* r, uint32_t saddr) {
    asm volatile("ldmatrix.sync.aligned.m8n8.x4.shared.b16 {%0,%1,%2,%3}, [%4];"
        : "=r"(r[0]), "=r"(r[1]), "=r"(r[2]), "=r"(r[3]) : "r"(saddr));
}
__device__ __forceinline__ void mma_bf16(float* c, const uint32_t* a, const uint32_t* b) {
    asm volatile(
        "mma.sync.aligned.m16n8k16.row.col.f32.bf16.bf16.f32 "
        "{%0,%1,%2,%3}, {%4,%5,%6,%7}, {%8,%9}, {%0,%1,%2,%3};"
        : "+f"(c[0]), "+f"(c[1]), "+f"(c[2]), "+f"(c[3])
        : "r"(a[0]), "r"(a[1]), "r"(a[2]), "r"(a[3]), "r"(b[0]), "r"(b[1]));
}
#define CP_ASYNC16(sa, ga) \
    asm volatile("cp.async.cg.shared.global [%0], [%1], 16;" \
                 :: "r"(sa), "l"(ga) : "memory")
#define CP_COMMIT() asm volatile("cp.async.commit_group;" ::: "memory")
#define CP_WAIT0()  asm volatile("cp.async.wait_group 0;" ::: "memory")
#define CP_WAIT1()  asm volatile("cp.async.wait_group 1;" ::: "memory")

__device__ __forceinline__ float tanh_ap(float x) {
    float y; asm("tanh.approx.f32 %0, %1;" : "=f"(y) : "f"(x)); return y;
}
__device__ __forceinline__ float sig_ap(float x) {
    return fmaf(tanh_ap(0.5f * x), 0.5f, 0.5f);
}
__device__ __forceinline__ void st_release_gpu(unsigned int* p, unsigned int v) {
    asm volatile("st.global.release.gpu.b32 [%0], %1;" :: "l"(p), "r"(v) : "memory");
}
__device__ __forceinline__ unsigned int ld_acquire_gpu(const unsigned int* p) {
    unsigned int v;
    asm volatile("ld.global.acquire.gpu.b32 %0, [%1];" : "=r"(v) : "l"(p) : "memory");
    return v;
}

// ------------------------- scratch (device globals) ------------------------
__device__ bf16  g_xwb[(size_t)Tt * Bb * G4];      // layer-0 gate pre-acts (bf16)
__device__ bf16  g_xb[(size_t)Tt * Bb * 128];      // x padded to K=128, bf16
__device__ bf16  g_h1b[(size_t)Tt * Bb * Hh];      // layer1 outputs (bf16)
__device__ float g_em[(size_t)Tt * Bb * Kc];       // emissions (fp32)
__device__ bf16  g_wih0b[1536 * 128];              // Wih0 padded K=128
__device__ float g_wc1[Kc * 512];                  // W3 @ W2  (10 x 512)
__device__ float g_wc[Kc * Hh];                    // W3@W2@W1 (10 x 384)
__device__ float g_t1[1024];                       // W2 @ b1 + b2
__device__ float g_bc[Kc];                         // composed bias
__device__ bf16  g_h0buf[2 * Bb * Hh];             // recurrent h0 state (bf16)
__device__ bf16  g_h1buf[2 * Bb * Hh];             // recurrent h1 state (bf16)
__device__ float g_partial[Bb];

// one flag per CTA, each on its own 128B line; group g = flags [g*24, g*24+24)
__device__ unsigned int g_flags[NCTA_LSTM * 32];

// ------------------------------ init state --------------------------------
__global__ void init_state_kernel() {
    int i = blockIdx.x * blockDim.x + threadIdx.x;
    if (i < 2 * Bb * Hh) {
        g_h0buf[i] = __float2bfloat16(0.f);
        g_h1buf[i] = __float2bfloat16(0.f);
    }
    if (i < NCTA_LSTM * 32) g_flags[i] = 0u;
}

// ---------------------- bf16 conversions (x, Wih0 only) --------------------
#define S0 (65536 * 128)
#define S1 (1536 * 128)
__global__ __launch_bounds__(256) void conv_all(
    const float* __restrict__ x, const float* __restrict__ Wih0)
{
    const int total = S0 + S1;
    for (int i = blockIdx.x * blockDim.x + threadIdx.x; i < total;
         i += gridDim.x * blockDim.x) {
        if (i < S0) {
            int r = i >> 7, c = i & 127;
            g_xb[i] = (c < INP) ? __float2bfloat16(x[(size_t)r * INP + c])
                                : __float2bfloat16(0.f);
        } else {
            int j = i - S0;
            int r = j >> 7, c = j & 127;
            g_wih0b[j] = (c < INP) ? __float2bfloat16(Wih0[(size_t)r * INP + c])
                                   : __float2bfloat16(0.f);
        }
    }
}

// -------------------- MLP weight composition (fp32) ------------------------
// stage 1: Wc1 = W3 @ W2 (10x512);  t1 = W2 @ b1 + b2 (1024)
__global__ __launch_bounds__(256) void compose1(
    const float* __restrict__ W3, const float* __restrict__ W2,
    const float* __restrict__ b1, const float* __restrict__ b2)
{
    int i = blockIdx.x * blockDim.x + threadIdx.x;
    if (i < Kc * 512) {
        int r = i / 512, c = i - r * 512;
        float s = 0.f;
        for (int k = 0; k < 1024; k++)
            s += W3[r * 1024 + k] * W2[k * 512 + c];
        g_wc1[i] = s;
    } else if (i < Kc * 512 + 1024) {
        int j = i - Kc * 512;
        float s = b2[j];
        for (int k = 0; k < 512; k++)
            s += W2[j * 512 + k] * b1[k];
        g_t1[j] = s;
    }
}
// stage 2: Wc = Wc1 @ W1 (10x384);  bc = W3 @ t1 + b3 (10)
__global__ __launch_bounds__(256) void compose2(
    const float* __restrict__ W1, const float* __restrict__ W3,
    const float* __restrict__ b3)
{
    int i = blockIdx.x * blockDim.x + threadIdx.x;
    if (i < Kc * Hh) {
        int r = i / Hh, c = i - r * Hh;
        float s = 0.f;
        for (int k = 0; k < 512; k++)
            s += g_wc1[r * 512 + k] * W1[k * Hh + c];
        g_wc[i] = s;
    } else if (i < Kc * Hh + Kc) {
        int r = i - Kc * Hh;
        float s = b3[r];
        for (int k = 0; k < 1024; k++)
            s += W3[r * 1024 + k] * g_t1[k];
        g_bc[r] = s;
    }
}

// ------------- release/acquire group barrier (24 CTAs/group) ---------------
__device__ __forceinline__ void group_barrier(int grp, int cta_in_grid,
                                              unsigned int target) {
    __syncthreads();                    // all CTA writes happen-before
    if (threadIdx.x < 32) {
        if (threadIdx.x == 0)
            st_release_gpu(&g_flags[cta_in_grid * 32], target);
        if (threadIdx.x < 24) {
            const unsigned int* f = &g_flags[(grp * 24 + threadIdx.x) * 32];
            while (ld_acquire_gpu(f) < target) { }
        }
    }
    __syncthreads();
}

// ======================== HMMA feed-forward GEMM ===========================
__global__ __launch_bounds__(256) void mma_gemm(
    const bf16* __restrict__ A, const bf16* __restrict__ B,
    const float* __restrict__ bias1, const float* __restrict__ bias2,
    float* __restrict__ Cf, bf16* __restrict__ Cb,
    int M, int N, int K)
{
    __shared__ __align__(16) bf16 smA[2][128 * 40];
    __shared__ __align__(16) bf16 smB[2][128 * 40];

    const int tid = threadIdx.x;
    const int lane = tid & 31;
    const int wid = tid >> 5;
    const int wm = wid & 3;
    const int wn = wid >> 2;
    const int m0 = blockIdx.y * 128;
    const int n0 = blockIdx.x * 128;

    const uint32_t saddrA[2] = { smem_to_u32(smA[0]), smem_to_u32(smA[1]) };
    const uint32_t saddrB[2] = { smem_to_u32(smB[0]), smem_to_u32(smB[1]) };

    float acc[2][8][4];
#pragma unroll
    for (int i = 0; i < 2; i++)
#pragma unroll
        for (int j = 0; j < 8; j++)
#pragma unroll
            for (int q = 0; q < 4; q++) acc[i][j][q] = 0.f;

    const uint32_t a_off =
        (uint32_t)(((wm * 32 + (lane & 15)) * 40 + (lane >> 4) * 8) * 2);
    uint32_t b_off[4];
#pragma unroll
    for (int jp = 0; jp < 4; jp++)
        b_off[jp] = (uint32_t)(((wn * 64 + jp * 16 + (lane & 7) + ((lane >> 4) << 3)) * 40
                                + ((lane >> 3) & 1) * 8) * 2);

    const int lrow = tid >> 2;
    const int lc   = tid & 3;

    const int nkt = K >> 5;
#pragma unroll
    for (int it = 0; it < 2; it++) {
        int row = lrow + it * 64;
        uint32_t d = (uint32_t)((row * 40 + lc * 8) * 2);
        CP_ASYNC16(saddrA[0] + d, A + (size_t)(m0 + row) * K + lc * 8);
        CP_ASYNC16(saddrB[0] + d, B + (size_t)(n0 + row) * K + lc * 8);
    }
    CP_COMMIT();

    for (int kt = 0; kt < nkt; kt++) {
        CP_WAIT0();
        __syncthreads();
        if (kt + 1 < nkt) {
            int s = (kt + 1) & 1;
            int k0 = (kt + 1) * 32;
#pragma unroll
            for (int it = 0; it < 2; it++) {
                int row = lrow + it * 64;
                uint32_t d = (uint32_t)((row * 40 + lc * 8) * 2);
                CP_ASYNC16(saddrA[s] + d, A + (size_t)(m0 + row) * K + k0 + lc * 8);
                CP_ASYNC16(saddrB[s] + d, B + (size_t)(n0 + row) * K + k0 + lc * 8);
            }
        }
        CP_COMMIT();

        const uint32_t sa = saddrA[kt & 1];
        const uint32_t sb = saddrB[kt & 1];
#pragma unroll
        for (int kk = 0; kk < 2; kk++) {
            uint32_t a[2][4], b[4][4];
            ldsm4(a[0], sa + a_off + kk * 32);
            ldsm4(a[1], sa + a_off + 1280 + kk * 32);
#pragma unroll
            for (int jp = 0; jp < 4; jp++)
                ldsm4(b[jp], sb + b_off[jp] + kk * 32);
#pragma unroll
            for (int mt = 0; mt < 2; mt++)
#pragma unroll
                for (int j = 0; j < 8; j++)
                    mma_bf16(acc[mt][j], a[mt], &b[j >> 1][(j & 1) * 2]);
        }
        __syncthreads();
    }

#pragma unroll
    for (int mt = 0; mt < 2; mt++)
#pragma unroll
        for (int j = 0; j < 8; j++)
#pragma unroll
            for (int p = 0; p < 2; p++) {
                int row = m0 + wm * 32 + mt * 16 + (lane >> 2) + p * 8;
                int col = n0 + wn * 64 + j * 8 + (lane & 3) * 2;
                float bb0 = bias1[col], bb1 = bias1[col + 1];
                if (bias2) { bb0 += bias2[col]; bb1 += bias2[col + 1]; }
                float v0 = acc[mt][j][p * 2] + bb0;
                float v1 = acc[mt][j][p * 2 + 1] + bb1;
                if (Cf) {
                    *(float2*)(Cf + (size_t)row * N + col) = make_float2(v0, v1);
                } else {
                    *(__nv_bfloat162*)(Cb + (size_t)row * N + col) =
                        __floats2bfloat162_rn(v0, v1);
                }
            }
}

// ================== fused 2-layer persistent LSTM (R9) =====================
__global__ __launch_bounds__(256) void lstm_fused(
    const float* __restrict__ Whh0, const float* __restrict__ Wih1,
    const float* __restrict__ Whh1, const float* __restrict__ bih1,
    const float* __restrict__ bhh1)
{
    extern __shared__ bf16 dsm[];
    bf16* W0sm  = dsm;                    // Whh0 slice  (64n x 392)
    bf16* Wi1sm = dsm + 64 * 392;         // Wih1 slice
    bf16* W1sm  = dsm + 2 * 64 * 392;     // Whh1 slice
    bf16* Asm   = dsm + 3 * 64 * 392;     // A0 tile (64 x 392)
    bf16* A1sm  = dsm + 4 * 64 * 392;     // h1 k-tiles 0..11 (64 x 200)
    const uint32_t w0base  = smem_to_u32(W0sm);
    const uint32_t wi1base = smem_to_u32(Wi1sm);
    const uint32_t w1base  = smem_to_u32(W1sm);
    const uint32_t abase   = smem_to_u32(Asm);
    const uint32_t a1base  = smem_to_u32(A1sm);

    const int tid = threadIdx.x;
    const int lane = tid & 31;
    const int wid = tid >> 5;
    const int wm = wid & 3;              // 16-row m tile
    const int wn = wid >> 2;             // h-col half (0/1)
    const int bx = blockIdx.x & 3;
    const int by = blockIdx.x >> 2;
    const int b0 = bx * 64;
    const int c0 = by * 16;

    for (int idx = tid; idx < 64 * 384; idx += 256) {
        int n = idx / 384, k = idx - n * 384;
        int g = n >> 4, hc = n & 15;
        size_t grow = (size_t)(g * Hh + c0 + hc) * Hh + k;
        int d = n * 392 + k;
        W0sm[d]  = __float2bfloat16(Whh0[grow]);
        Wi1sm[d] = __float2bfloat16(Wih1[grow]);
        W1sm[d]  = __float2bfloat16(Whh1[grow]);
    }

    const uint32_t a_off =
        (uint32_t)(((wm * 16 + (lane & 15)) * 392 + (lane >> 4) * 8) * 2);
    const uint32_t a1_off =
        (uint32_t)(((wm * 16 + (lane & 15)) * 200 + (lane >> 4) * 8) * 2);
    const uint32_t b_k = ((lane >> 3) & 1) * 8;
    const uint32_t b_off0 =
        (uint32_t)((((0 + (lane >> 4)) * 16 + wn * 8 + (lane & 7)) * 392 + b_k) * 2);
    const uint32_t b_off1 =
        (uint32_t)((((2 + (lane >> 4)) * 16 + wn * 8 + (lane & 7)) * 392 + b_k) * 2);

    const int prow = lane >> 2;
    const int pcol = (lane & 3) * 2;
    const int colg = c0 + wn * 8 + pcol;

    float bi1[4][2];
#pragma unroll
    for (int g = 0; g < 4; g++)
#pragma unroll
        for (int q = 0; q < 2; q++)
            bi1[g][q] = bih1[g * Hh + colg + q] + bhh1[g * Hh + colg + q];

    float cst0[4], cst1[4];
#pragma unroll
    for (int i = 0; i < 4; i++) { cst0[i] = 0.f; cst1[i] = 0.f; }

    for (int t = 0; t <= Tt; t++) {
        const int ph = t & 1;
        const bool doL0 = (t < Tt);
        const bool doL1 = (t >= 1);

        float2 xv[4][2];
        if (doL0) {
            const bf16* xw = g_xwb + (size_t)t * Bb * G4;
#pragma unroll
            for (int g = 0; g < 4; g++)
#pragma unroll
                for (int p = 0; p < 2; p++) {
                    int brow = b0 + wm * 16 + prow + p * 8;
                    xv[g][p] = __bfloat1622float2(
                        *(const __nv_bfloat162*)(xw + (size_t)brow * G4 + g * Hh + colg));
                }
        }

        {
            const bf16* hprev0 = g_h0buf + (size_t)ph * Bb * Hh;
#pragma unroll
            for (int it = 0; it < 12; it++) {
                int idx = tid + it * 256;
                int row = idx / 48, c = idx - row * 48;
                CP_ASYNC16(abase + (uint32_t)((row * 392 + c * 8) * 2),
                           hprev0 + (size_t)(b0 + row) * Hh + c * 8);
            }
            CP_COMMIT();
        }
        if (doL1) {
            const bf16* hprev1 = g_h1buf + (size_t)ph * Bb * Hh;
#pragma unroll
            for (int it = 0; it < 6; it++) {
                int idx = tid + it * 256;
                int row = idx / 24, c = idx - row * 24;
                CP_ASYNC16(a1base + (uint32_t)(row * 400 + c * 16),
                           hprev1 + (size_t)(b0 + row) * Hh + c * 8);
            }
            CP_COMMIT();
            CP_WAIT1();
        } else {
            CP_WAIT0();
        }
        __syncthreads();

        float accL0[4][4], accL1[4][4];
#pragma unroll
        for (int j = 0; j < 4; j++)
#pragma unroll
            for (int q = 0; q < 4; q++) { accL0[j][q] = 0.f; accL1[j][q] = 0.f; }

#pragma unroll 4
        for (int kt = 0; kt < 24; kt++) {
            uint32_t koff = (uint32_t)(kt * 32);
            uint32_t a[4], p0[4], p1[4], q0[4], q1[4];
            ldsm4(a, abase + a_off + koff);
            ldsm4(p0, w0base + b_off0 + koff);
            ldsm4(p1, w0base + b_off1 + koff);
            ldsm4(q0, wi1base + b_off0 + koff);
            ldsm4(q1, wi1base + b_off1 + koff);
            mma_bf16(accL0[0], a, &p0[0]);
            mma_bf16(accL1[0], a, &q0[0]);
            mma_bf16(accL0[1], a, &p0[2]);
            mma_bf16(accL1[1], a, &q0[2]);
            mma_bf16(accL0[2], a, &p1[0]);
            mma_bf16(accL1[2], a, &q1[0]);
            mma_bf16(accL0[3], a, &p1[2]);
            mma_bf16(accL1[3], a, &q1[2]);
        }
        __syncthreads();

        if (doL1) {
            const bf16* hprev1 = g_h1buf + (size_t)ph * Bb * Hh;
#pragma unroll
            for (int it = 0; it < 6; it++) {
                int idx = tid + it * 256;
                int row = idx / 24, c = idx - row * 24;
                CP_ASYNC16(abase + (uint32_t)(row * 784 + 384 + c * 16),
                           hprev1 + (size_t)(b0 + row) * Hh + 192 + c * 8);
            }
            CP_COMMIT();
        }

        if (doL0) {
            bf16* hnext0 = g_h0buf + (size_t)(ph ^ 1) * Bb * Hh;
#pragma unroll
            for (int p = 0; p < 2; p++) {
                int brow = b0 + wm * 16 + prow + p * 8;
                float hnv[2];
#pragma unroll
                for (int q = 0; q < 2; q++) {
                    float xi = q ? xv[0][p].y : xv[0][p].x;
                    float xf = q ? xv[1][p].y : xv[1][p].x;
                    float xg = q ? xv[2][p].y : xv[2][p].x;
                    float xo = q ? xv[3][p].y : xv[3][p].x;
                    float i_ = sig_ap(accL0[0][p * 2 + q] + xi);
                    float f_ = sig_ap(accL0[1][p * 2 + q] + xf);
                    float g_ = tanh_ap(accL0[2][p * 2 + q] + xg);
                    float o_ = sig_ap(accL0[3][p * 2 + q] + xo);
                    float cn = f_ * cst0[p * 2 + q] + i_ * g_;
                    cst0[p * 2 + q] = cn;
                    hnv[q] = o_ * tanh_ap(cn);
                }
                *(__nv_bfloat162*)(hnext0 + (size_t)brow * Hh + colg) =
                    __floats2bfloat162_rn(hnv[0], hnv[1]);
            }
        }

        if (doL1) {
            CP_WAIT1();
            __syncthreads();
#pragma unroll 4
            for (int kt = 0; kt < 12; kt++) {
                uint32_t koff = (uint32_t)(kt * 32);
                uint32_t a[4], b0v[4], b1v[4];
                ldsm4(a, a1base + a1_off + koff);
                ldsm4(b0v, w1base + b_off0 + koff);
                ldsm4(b1v, w1base + b_off1 + koff);
                mma_bf16(accL1[0], a, &b0v[0]);
                mma_bf16(accL1[1], a, &b0v[2]);
                mma_bf16(accL1[2], a, &b1v[0]);
                mma_bf16(accL1[3], a, &b1v[2]);
            }
            CP_WAIT0();
            __syncthreads();
#pragma unroll 4
            for (int kt = 12; kt < 24; kt++) {
                uint32_t koff = (uint32_t)(kt * 32);
                uint32_t a[4], b0v[4], b1v[4];
                ldsm4(a, abase + a_off + koff);
                ldsm4(b0v, w1base + b_off0 + koff);
                ldsm4(b1v, w1base + b_off1 + koff);
                mma_bf16(accL1[0], a, &b0v[0]);
                mma_bf16(accL1[1], a, &b0v[2]);
                mma_bf16(accL1[2], a, &b1v[0]);
                mma_bf16(accL1[3], a, &b1v[2]);
            }

            bf16* hnext1 = g_h1buf + (size_t)(ph ^ 1) * Bb * Hh;
            bf16* houtp  = g_h1b + (size_t)(t - 1) * Bb * Hh;
#pragma unroll
            for (int p = 0; p < 2; p++) {
                int brow = b0 + wm * 16 + prow + p * 8;
                float hnv[2];
#pragma unroll
                for (int q = 0; q < 2; q++) {
                    float i_ = sig_ap(accL1[0][p * 2 + q] + bi1[0][q]);
                    float f_ = sig_ap(accL1[1][p * 2 + q] + bi1[1][q]);
                    float g_ = tanh_ap(accL1[2][p * 2 + q] + bi1[2][q]);
                    float o_ = sig_ap(accL1[3][p * 2 + q] + bi1[3][q]);
                    float cn = f_ * cst1[p * 2 + q] + i_ * g_;
                    cst1[p * 2 + q] = cn;
                    hnv[q] = o_ * tanh_ap(cn);
                }
                __nv_bfloat162 hh = __floats2bfloat162_rn(hnv[0], hnv[1]);
                *(__nv_bfloat162*)(hnext1 + (size_t)brow * Hh + colg) = hh;
                *(__nv_bfloat162*)(houtp + (size_t)brow * Hh + colg) = hh;
            }
        }

        group_barrier(bx, blockIdx.x, (unsigned int)(t + 1));
    }
}

// --------------- emissions: h1 @ Wc^T + bc (N=10, K=384) -------------------
__global__ __launch_bounds__(256) void em_kernel(const bf16* __restrict__ A)
{
    int row  = blockIdx.x * (blockDim.x >> 5) + (threadIdx.x >> 5);
    int lane = threadIdx.x & 31;
    float acc[Kc];
#pragma unroll
    for (int j = 0; j < Kc; j++) acc[j] = 0.f;
    const __nv_bfloat162* ar = (const __nv_bfloat162*)(A + (size_t)row * Hh);
#pragma unroll
    for (int it = 0; it < 6; it++) {
        int k2 = lane + it * 32;
        float2 a = __bfloat1622float2(ar[k2]);
#pragma unroll
        for (int j = 0; j < Kc; j++) {
            acc[j] += a.x * g_wc[j * Hh + 2 * k2] + a.y * g_wc[j * Hh + 2 * k2 + 1];
        }
    }
#pragma unroll
    for (int j = 0; j < Kc; j++) {
#pragma unroll
        for (int off = 16; off; off >>= 1)
            acc[j] += __shfl_xor_sync(0xffffffffu, acc[j], off);
    }
    if (lane == 0) {
#pragma unroll
        for (int j = 0; j < Kc; j++)
            g_em[(size_t)row * Kc + j] = acc[j] + g_bc[j];
    }
}

// ------------------------------ CRF ----------------------------------------
__global__ __launch_bounds__(32) void crf_kernel(
    const float* __restrict__ em, const int* __restrict__ tags,
    const float* __restrict__ start_t, const float* __restrict__ end_t,
    const float* __restrict__ trans)
{
    const int bp   = blockIdx.x;
    const int lane = threadIdx.x;
    const float NEG = -1e30f;

    float tr[Kc];
    int cl = (lane < Kc) ? lane : 0;
#pragma unroll
    for (int i = 0; i < Kc; i++) tr[i] = trans[i * Kc + cl];

    float a = (lane < Kc) ? (start_t[lane] + em[((size_t)bp * Tt) * Kc + lane]) : NEG;

    for (int tp = 1; tp < Tt; tp++) {
        float e = (lane < Kc) ? em[((size_t)bp * Tt + tp) * Kc + lane] : 0.f;
        float v[Kc];
        float m = NEG;
#pragma unroll
        for (int i = 0; i < Kc; i++) {
            float ai = __shfl_sync(0xffffffffu, a, i);
            v[i] = ai + tr[i];
            m = fmaxf(m, v[i]);
        }
        float s = 0.f;
#pragma unroll
        for (int i = 0; i < Kc; i++) s += __expf(v[i] - m);
        float an = m + __logf(s) + e;
        a = (lane < Kc) ? an : NEG;
    }

    float z = (lane < Kc) ? (a + end_t[lane]) : NEG;
    float zmax = z;
#pragma unroll
    for (int off = 16; off; off >>= 1)
        zmax = fmaxf(zmax, __shfl_xor_sync(0xffffffffu, zmax, off));
    float zs = (lane < Kc) ? __expf(z - zmax) : 0.f;
#pragma unroll
    for (int off = 16; off; off >>= 1)
        zs += __shfl_xor_sync(0xffffffffu, zs, off);
    float logZ = zmax + __logf(zs);

    if (lane == 0) {
        int prev = tags[(size_t)bp * Tt];
        float score = start_t[prev] + em[((size_t)bp * Tt) * Kc + prev];
        for (int tp = 1; tp < Tt; tp++) {
            int tg = tags[(size_t)bp * Tt + tp];
            score += trans[prev * Kc + tg] + em[((size_t)bp * Tt + tp) * Kc + tg];
            prev = tg;
        }
        score += end_t[prev];
        g_partial[bp] = logZ - score;
    }
}

__global__ __launch_bounds__(256) void reduce_kernel(float* __restrict__ out)
{
    __shared__ float sh[256];
    int i = threadIdx.x;
    sh[i] = g_partial[i];
    __syncthreads();
#pragma unroll
    for (int s = 128; s; s >>= 1) {
        if (i < s) sh[i] += sh[i + s];
        __syncthreads();
    }
    if (i == 0) out[0] = sh[0];
}

// ------------------------------ launch -------------------------------------
extern "C" void kernel_launch(void* const* d_in, const int* in_sizes, int n_in,
                              void* d_out, int out_size)
{
    (void)in_sizes; (void)n_in; (void)out_size;
    const float* x    = (const float*)d_in[0];
    const int*   tags = (const int*)d_in[2];
    const float* Wih0 = (const float*)d_in[3];
    const float* Whh0 = (const float*)d_in[4];
    const float* bih0 = (const float*)d_in[5];
    const float* bhh0 = (const float*)d_in[6];
    const float* Wih1 = (const float*)d_in[7];
    const float* Whh1 = (const float*)d_in[8];
    const float* bih1 = (const float*)d_in[9];
    const float* bhh1 = (const float*)d_in[10];
    const float* W1   = (const float*)d_in[11];
    const float* b1   = (const float*)d_in[12];
    const float* W2   = (const float*)d_in[13];
    const float* b2   = (const float*)d_in[14];
    const float* W3   = (const float*)d_in[15];
    const float* b3   = (const float*)d_in[16];
    const float* st   = (const float*)d_in[17];
    const float* et   = (const float*)d_in[18];
    const float* trn  = (const float*)d_in[19];

    float *emb;
    bf16 *xwb, *xb, *h1b, *wih0b;
    cudaGetSymbolAddress((void**)&xwb,   g_xwb);
    cudaGetSymbolAddress((void**)&emb,   g_em);
    cudaGetSymbolAddress((void**)&xb,    g_xb);
    cudaGetSymbolAddress((void**)&h1b,   g_h1b);
    cudaGetSymbolAddress((void**)&wih0b, g_wih0b);

    const int M = Tt * Bb;  // 65536
    const size_t LSTM_SMEM = (size_t)(4 * 64 * 392 + 64 * 200) * sizeof(bf16);
    cudaFuncSetAttribute(lstm_fused, cudaFuncAttributeMaxDynamicSharedMemorySize,
                         (int)LSTM_SMEM);

    init_state_kernel<<<(2 * Bb * Hh + 255) / 256, 256>>>();                 // 0
    conv_all<<<8192, 256>>>(x, Wih0);                                        // 1
    compose1<<<(Kc * 512 + 1024 + 255) / 256, 256>>>(W3, W2, b1, b2);        // 2
    compose2<<<(Kc * Hh + Kc + 255) / 256, 256>>>(W1, W3, b3);               // 3

    // xw0 = x @ Wih0^T + (bih0+bhh0)  (bf16 output)
    mma_gemm<<<dim3(G4 / 128, M / 128), 256>>>(xb, wih0b, bih0, bhh0,        // 4
                                               nullptr, xwb, M, G4, 128);
    // fused 2-layer recurrence
    lstm_fused<<<NCTA_LSTM, 256, LSTM_SMEM>>>(Whh0, Wih1, Whh1, bih1, bhh1); // 5

    // collapsed MLP: em = h1 @ Wc^T + bc
    em_kernel<<<M / 8, 256>>>(h1b);                                          // 6

    crf_kernel<<<Bb, 32>>>(emb, tags, st, et, trn);                          // 7
    reduce_kernel<<<1, 256>>>((float*)d_out);                                // 8
}

// round 12
// speedup vs baseline: 1.3553x; 1.0330x over previous
#include <cuda_runtime.h>
#include <cuda_bf16.h>
#include <cstdint>
#include <cstddef>

// ---------------------------------------------------------------------------
// BiLSTM-NER, Round 11:
//  * xw0 GEMM folded into the lstm_fused launch as 52 PRODUCER CTAs running
//    on the SMs the 96 persistent LSTM CTAs don't occupy; LSTM gates each
//    interval on a per-timestep ready counter (release/acquire). The entire
//    feed-forward projection now hides under the recurrence.
//  * compose1/compose2 warp-parallelized (75us -> ~6us).
//  * LSTM dataflow / barriers unchanged from R10 (proven 2440us).
// ---------------------------------------------------------------------------

#define Tt 256
#define Bb 256
#define Hh 384
#define G4 1536   // 4*H
#define INP 100
#define Kc 10
#define NCTA_LSTM 96
#define NCTA_GEMM 52
#define NTILES (512 * 12)   // (M/128) * (G4/128)

typedef __nv_bfloat16 bf16;

// ============================ PTX helpers ==================================
__device__ __forceinline__ uint32_t smem_to_u32(const void* p) {
    uint32_t a;
    asm("{ .reg .u64 t; cvta.to.shared.u64 t, %1; cvt.u32.u64 %0, t; }"
        : "=r"(a) : "l"(p));
    return a;
}
__device__ __forceinline__ void ldsm4(uint32_t* r, uint32_t saddr) {
    asm volatile("ldmatrix.sync.aligned.m8n8.x4.shared.b16 {%0,%1,%2,%3}, [%4];"
        : "=r"(r[0]), "=r"(r[1]), "=r"(r[2]), "=r"(r[3]) : "r"(saddr));
}
__device__ __forceinline__ void mma_bf16(float* c, const uint32_t* a, const uint32_t* b) {
    asm volatile(
        "mma.sync.aligned.m16n8k16.row.col.f32.bf16.bf16.f32 "
        "{%0,%1,%2,%3}, {%4,%5,%6,%7}, {%8,%9}, {%0,%1,%2,%3};"
        : "+f"(c[0]), "+f"(c[1]), "+f"(c[2]), "+f"(c[3])
        : "r"(a[0]), "r"(a[1]), "r"(a[2]), "r"(a[3]), "r"(b[0]), "r"(b[1]));
}
#define CP_ASYNC16(sa, ga) \
    asm volatile("cp.async.cg.shared.global [%0], [%1], 16;" \
                 :: "r"(sa), "l"(ga) : "memory")
#define CP_COMMIT() asm volatile("cp.async.commit_group;" ::: "memory")
#define CP_WAIT0()  asm volatile("cp.async.wait_group 0;" ::: "memory")
#define CP_WAIT1()  asm volatile("cp.async.wait_group 1;" ::: "memory")

__device__ __forceinline__ float tanh_ap(float x) {
    float y; asm("tanh.approx.f32 %0, %1;" : "=f"(y) : "f"(x)); return y;
}
__device__ __forceinline__ float sig_ap(float x) {
    return fmaf(tanh_ap(0.5f * x), 0.5f, 0.5f);
}
__device__ __forceinline__ void st_release_gpu(unsigned int* p, unsigned int v) {
    asm volatile("st.global.release.gpu.b32 [%0], %1;" :: "l"(p), "r"(v) : "memory");
}
__device__ __forceinline__ unsigned int ld_acquire_gpu(const unsigned int* p) {
    unsigned int v;
    asm volatile("ld.global.acquire.gpu.b32 %0, [%1];" : "=r"(v) : "l"(p) : "memory");
    return v;
}
__device__ __forceinline__ void red_release_gpu(unsigned int* p, unsigned int v) {
    asm volatile("red.release.gpu.global.add.u32 [%0], %1;" :: "l"(p), "r"(v) : "memory");
}

// ------------------------- scratch (device globals) ------------------------
__device__ bf16  g_xwb[(size_t)Tt * Bb * G4];      // layer-0 gate pre-acts (bf16)
__device__ bf16  g_xb[(size_t)Tt * Bb * 128];      // x padded to K=128, bf16
__device__ bf16  g_h1b[(size_t)Tt * Bb * Hh];      // layer1 outputs (bf16)
__device__ float g_em[(size_t)Tt * Bb * Kc];       // emissions (fp32)
__device__ bf16  g_wih0b[1536 * 128];              // Wih0 padded K=128
__device__ float g_wc1[Kc * 512];                  // W3 @ W2  (10 x 512)
__device__ float g_wc[Kc * Hh];                    // W3@W2@W1 (10 x 384)
__device__ float g_t1[1024];                       // W2 @ b1 + b2
__device__ float g_bc[Kc];                         // composed bias
__device__ bf16  g_h0buf[2 * Bb * Hh];             // recurrent h0 state (bf16)
__device__ bf16  g_h1buf[2 * Bb * Hh];             // recurrent h1 state (bf16)
__device__ float g_partial[Bb];

// one flag per CTA, each on its own 128B line; group g = flags [g*24, g*24+24)
__device__ unsigned int g_flags[NCTA_LSTM * 32];
// per-timestep xw readiness counters (24 tiles per timestep)
__device__ unsigned int g_ready[Tt];

// ------------------------------ init state --------------------------------
__global__ void init_state_kernel() {
    int i = blockIdx.x * blockDim.x + threadIdx.x;
    if (i < 2 * Bb * Hh) {
        g_h0buf[i] = __float2bfloat16(0.f);
        g_h1buf[i] = __float2bfloat16(0.f);
    }
    if (i < NCTA_LSTM * 32) g_flags[i] = 0u;
    if (i < Tt) g_ready[i] = 0u;
}

// ---------------------- bf16 conversions (x, Wih0 only) --------------------
#define S0 (65536 * 128)
#define S1 (1536 * 128)
__global__ __launch_bounds__(256) void conv_all(
    const float* __restrict__ x, const float* __restrict__ Wih0)
{
    const int total = S0 + S1;
    for (int i = blockIdx.x * blockDim.x + threadIdx.x; i < total;
         i += gridDim.x * blockDim.x) {
        if (i < S0) {
            int r = i >> 7, c = i & 127;
            g_xb[i] = (c < INP) ? __float2bfloat16(x[(size_t)r * INP + c])
                                : __float2bfloat16(0.f);
        } else {
            int j = i - S0;
            int r = j >> 7, c = j & 127;
            g_wih0b[j] = (c < INP) ? __float2bfloat16(Wih0[(size_t)r * INP + c])
                                   : __float2bfloat16(0.f);
        }
    }
}

// -------------- MLP weight composition (warp per output) -------------------
__global__ __launch_bounds__(256) void compose1(
    const float* __restrict__ W3, const float* __restrict__ W2,
    const float* __restrict__ b1, const float* __restrict__ b2)
{
    int w = (blockIdx.x * blockDim.x + threadIdx.x) >> 5;
    int lane = threadIdx.x & 31;
    if (w < Kc * 512) {
        int r = w / 512, c = w - r * 512;
        float s = 0.f;
        for (int k = lane; k < 1024; k += 32)
            s += W3[r * 1024 + k] * W2[k * 512 + c];
#pragma unroll
        for (int off = 16; off; off >>= 1)
            s += __shfl_xor_sync(0xffffffffu, s, off);
        if (lane == 0) g_wc1[w] = s;
    } else if (w < Kc * 512 + 1024) {
        int j = w - Kc * 512;
        float s = 0.f;
        for (int k = lane; k < 512; k += 32)
            s += W2[j * 512 + k] * b1[k];
#pragma unroll
        for (int off = 16; off; off >>= 1)
            s += __shfl_xor_sync(0xffffffffu, s, off);
        if (lane == 0) g_t1[j] = s + b2[j];
    }
}
__global__ __launch_bounds__(256) void compose2(
    const float* __restrict__ W1, const float* __restrict__ W3,
    const float* __restrict__ b3)
{
    int w = (blockIdx.x * blockDim.x + threadIdx.x) >> 5;
    int lane = threadIdx.x & 31;
    if (w < Kc * Hh) {
        int r = w / Hh, c = w - r * Hh;
        float s = 0.f;
        for (int k = lane; k < 512; k += 32)
            s += g_wc1[r * 512 + k] * W1[k * Hh + c];
#pragma unroll
        for (int off = 16; off; off >>= 1)
            s += __shfl_xor_sync(0xffffffffu, s, off);
        if (lane == 0) g_wc[w] = s;
    } else if (w < Kc * Hh + Kc) {
        int r = w - Kc * Hh;
        float s = 0.f;
        for (int k = lane; k < 1024; k += 32)
            s += W3[r * 1024 + k] * g_t1[k];
#pragma unroll
        for (int off = 16; off; off >>= 1)
            s += __shfl_xor_sync(0xffffffffu, s, off);
        if (lane == 0) g_bc[r] = s + b3[r];
    }
}

// ------------- release/acquire group barrier (24 CTAs/group) ---------------
__device__ __forceinline__ void group_barrier(int grp, int cta_in_grid,
                                              unsigned int target) {
    __syncthreads();
    if (threadIdx.x < 32) {
        if (threadIdx.x == 0)
            st_release_gpu(&g_flags[cta_in_grid * 32], target);
        if (threadIdx.x < 24) {
            const unsigned int* f = &g_flags[(grp * 24 + threadIdx.x) * 32];
            while (ld_acquire_gpu(f) < target) { }
        }
    }
    __syncthreads();
}

// ---------------- producer role: xw0 GEMM tiles (K=128) --------------------
// 52 CTAs loop over 6144 tiles in t-major order, writing g_xwb (bf16, with
// bias) and bumping g_ready[t] (release) after each tile.
__device__ void xw_gemm_role(bf16* dsm, const float* __restrict__ bih0,
                             const float* __restrict__ bhh0, int worker)
{
    bf16* smA = dsm;                 // [2][128*40]
    bf16* smB = dsm + 2 * 5120;      // [2][128*40]
    const uint32_t saddrA[2] = { smem_to_u32(smA), smem_to_u32(smA + 5120) };
    const uint32_t saddrB[2] = { smem_to_u32(smB), smem_to_u32(smB + 5120) };

    const int tid = threadIdx.x;
    const int lane = tid & 31;
    const int wid = tid >> 5;
    const int wm = wid & 3;
    const int wn = wid >> 2;
    const int K = 128;

    const uint32_t a_off =
        (uint32_t)(((wm * 32 + (lane & 15)) * 40 + (lane >> 4) * 8) * 2);
    uint32_t b_off[4];
#pragma unroll
    for (int jp = 0; jp < 4; jp++)
        b_off[jp] = (uint32_t)(((wn * 64 + jp * 16 + (lane & 7) + ((lane >> 4) << 3)) * 40
                                + ((lane >> 3) & 1) * 8) * 2);
    const int lrow = tid >> 2;
    const int lc   = tid & 3;

    for (int id = worker; id < NTILES; id += NCTA_GEMM) {
        const int t2 = id / 12;             // 128-row m-block (half timestep)
        const int nb = id - t2 * 12;
        const int m0 = t2 * 128;
        const int n0 = nb * 128;

        float acc[2][8][4];
#pragma unroll
        for (int i = 0; i < 2; i++)
#pragma unroll
            for (int j = 0; j < 8; j++)
#pragma unroll
                for (int q = 0; q < 4; q++) acc[i][j][q] = 0.f;

#pragma unroll
        for (int it = 0; it < 2; it++) {
            int row = lrow + it * 64;
            uint32_t d = (uint32_t)((row * 40 + lc * 8) * 2);
            CP_ASYNC16(saddrA[0] + d, g_xb + (size_t)(m0 + row) * K + lc * 8);
            CP_ASYNC16(saddrB[0] + d, g_wih0b + (size_t)(n0 + row) * K + lc * 8);
        }
        CP_COMMIT();

        for (int kt = 0; kt < 4; kt++) {
            CP_WAIT0();
            __syncthreads();
            if (kt + 1 < 4) {
                int s = (kt + 1) & 1;
                int k0 = (kt + 1) * 32;
#pragma unroll
                for (int it = 0; it < 2; it++) {
                    int row = lrow + it * 64;
                    uint32_t d = (uint32_t)((row * 40 + lc * 8) * 2);
                    CP_ASYNC16(saddrA[s] + d, g_xb + (size_t)(m0 + row) * K + k0 + lc * 8);
                    CP_ASYNC16(saddrB[s] + d, g_wih0b + (size_t)(n0 + row) * K + k0 + lc * 8);
                }
            }
            CP_COMMIT();

            const uint32_t sa = saddrA[kt & 1];
            const uint32_t sb = saddrB[kt & 1];
#pragma unroll
            for (int kk = 0; kk < 2; kk++) {
                uint32_t a[2][4], b[4][4];
                ldsm4(a[0], sa + a_off + kk * 32);
                ldsm4(a[1], sa + a_off + 1280 + kk * 32);
#pragma unroll
                for (int jp = 0; jp < 4; jp++)
                    ldsm4(b[jp], sb + b_off[jp] + kk * 32);
#pragma unroll
                for (int mt = 0; mt < 2; mt++)
#pragma unroll
                    for (int j = 0; j < 8; j++)
                        mma_bf16(acc[mt][j], a[mt], &b[j >> 1][(j & 1) * 2]);
            }
            __syncthreads();
        }

#pragma unroll
        for (int mt = 0; mt < 2; mt++)
#pragma unroll
            for (int j = 0; j < 8; j++)
#pragma unroll
                for (int p = 0; p < 2; p++) {
                    int row = m0 + wm * 32 + mt * 16 + (lane >> 2) + p * 8;
                    int col = n0 + wn * 64 + j * 8 + (lane & 3) * 2;
                    float v0 = acc[mt][j][p * 2]     + bih0[col]     + bhh0[col];
                    float v1 = acc[mt][j][p * 2 + 1] + bih0[col + 1] + bhh0[col + 1];
                    *(__nv_bfloat162*)(g_xwb + (size_t)row * G4 + col) =
                        __floats2bfloat162_rn(v0, v1);
                }

        __threadfence();
        __syncthreads();
        if (tid == 0) red_release_gpu(&g_ready[t2 >> 1], 1u);
    }
}

// ================== fused 2-layer persistent LSTM + producer ===============
__global__ __launch_bounds__(256) void lstm_fused(
    const float* __restrict__ Whh0, const float* __restrict__ Wih1,
    const float* __restrict__ Whh1, const float* __restrict__ bih1,
    const float* __restrict__ bhh1, const float* __restrict__ bih0,
    const float* __restrict__ bhh0)
{
    extern __shared__ bf16 dsm[];

    if (blockIdx.x >= NCTA_LSTM) {
        xw_gemm_role(dsm, bih0, bhh0, blockIdx.x - NCTA_LSTM);
        return;
    }

    bf16* W0sm  = dsm;                    // Whh0 slice  (64n x 392)
    bf16* Wi1sm = dsm + 64 * 392;         // Wih1 slice
    bf16* W1sm  = dsm + 2 * 64 * 392;     // Whh1 slice
    bf16* Asm   = dsm + 3 * 64 * 392;     // A0 tile (64 x 392)
    bf16* A1sm  = dsm + 4 * 64 * 392;     // h1 k-tiles 0..11 (64 x 200)
    const uint32_t w0base  = smem_to_u32(W0sm);
    const uint32_t wi1base = smem_to_u32(Wi1sm);
    const uint32_t w1base  = smem_to_u32(W1sm);
    const uint32_t abase   = smem_to_u32(Asm);
    const uint32_t a1base  = smem_to_u32(A1sm);

    const int tid = threadIdx.x;
    const int lane = tid & 31;
    const int wid = tid >> 5;
    const int wm = wid & 3;              // 16-row m tile
    const int wn = wid >> 2;             // h-col half (0/1)
    const int bx = blockIdx.x & 3;
    const int by = blockIdx.x >> 2;
    const int b0 = bx * 64;
    const int c0 = by * 16;

    for (int idx = tid; idx < 64 * 384; idx += 256) {
        int n = idx / 384, k = idx - n * 384;
        int g = n >> 4, hc = n & 15;
        size_t grow = (size_t)(g * Hh + c0 + hc) * Hh + k;
        int d = n * 392 + k;
        W0sm[d]  = __float2bfloat16(Whh0[grow]);
        Wi1sm[d] = __float2bfloat16(Wih1[grow]);
        W1sm[d]  = __float2bfloat16(Whh1[grow]);
    }

    const uint32_t a_off =
        (uint32_t)(((wm * 16 + (lane & 15)) * 392 + (lane >> 4) * 8) * 2);
    const uint32_t a1_off =
        (uint32_t)(((wm * 16 + (lane & 15)) * 200 + (lane >> 4) * 8) * 2);
    const uint32_t b_k = ((lane >> 3) & 1) * 8;
    const uint32_t b_off0 =
        (uint32_t)((((0 + (lane >> 4)) * 16 + wn * 8 + (lane & 7)) * 392 + b_k) * 2);
    const uint32_t b_off1 =
        (uint32_t)((((2 + (lane >> 4)) * 16 + wn * 8 + (lane & 7)) * 392 + b_k) * 2);

    const int prow = lane >> 2;
    const int pcol = (lane & 3) * 2;
    const int colg = c0 + wn * 8 + pcol;

    float bi1[4][2];
#pragma unroll
    for (int g = 0; g < 4; g++)
#pragma unroll
        for (int q = 0; q < 2; q++)
            bi1[g][q] = bih1[g * Hh + colg + q] + bhh1[g * Hh + colg + q];

    float cst0[4], cst1[4];
#pragma unroll
    for (int i = 0; i < 4; i++) { cst0[i] = 0.f; cst1[i] = 0.f; }

    for (int t = 0; t <= Tt; t++) {
        const int ph = t & 1;
        const bool doL0 = (t < Tt);
        const bool doL1 = (t >= 1);

        // ---- issue A0 <- h0(t-1); A1 <- h1(t-2) k-tiles 0..11
        {
            const bf16* hprev0 = g_h0buf + (size_t)ph * Bb * Hh;
#pragma unroll
            for (int it = 0; it < 12; it++) {
                int idx = tid + it * 256;
                int row = idx / 48, c = idx - row * 48;
                CP_ASYNC16(abase + (uint32_t)((row * 392 + c * 8) * 2),
                           hprev0 + (size_t)(b0 + row) * Hh + c * 8);
            }
            CP_COMMIT();
        }
        if (doL1) {
            const bf16* hprev1 = g_h1buf + (size_t)ph * Bb * Hh;
#pragma unroll
            for (int it = 0; it < 6; it++) {
                int idx = tid + it * 256;
                int row = idx / 24, c = idx - row * 24;
                CP_ASYNC16(a1base + (uint32_t)(row * 400 + c * 16),
                           hprev1 + (size_t)(b0 + row) * Hh + c * 8);
            }
            CP_COMMIT();
        }

        // ---- gate: xw(t) tiles published by producer CTAs (spin overlaps
        //      the cp.async in flight above)
        if (doL0) {
            if (tid == 0) {
                while (ld_acquire_gpu(&g_ready[t]) < 24u) { }
            }
        }
        __syncthreads();

        // ---- xw(t) fragments (bf16)
        float2 xv[4][2];
        if (doL0) {
            const bf16* xw = g_xwb + (size_t)t * Bb * G4;
#pragma unroll
            for (int g = 0; g < 4; g++)
#pragma unroll
                for (int p = 0; p < 2; p++) {
                    int brow = b0 + wm * 16 + prow + p * 8;
                    xv[g][p] = __bfloat1622float2(
                        *(const __nv_bfloat162*)(xw + (size_t)brow * G4 + g * Hh + colg));
                }
        }

        if (doL1) CP_WAIT1(); else CP_WAIT0();
        __syncthreads();

        float accL0[4][4], accL1[4][4];
#pragma unroll
        for (int j = 0; j < 4; j++)
#pragma unroll
            for (int q = 0; q < 4; q++) { accL0[j][q] = 0.f; accL1[j][q] = 0.f; }

#pragma unroll 4
        for (int kt = 0; kt < 24; kt++) {
            uint32_t koff = (uint32_t)(kt * 32);
            uint32_t a[4], p0[4], p1[4], q0[4], q1[4];
            ldsm4(a, abase + a_off + koff);
            ldsm4(p0, w0base + b_off0 + koff);
            ldsm4(p1, w0base + b_off1 + koff);
            ldsm4(q0, wi1base + b_off0 + koff);
            ldsm4(q1, wi1base + b_off1 + koff);
            mma_bf16(accL0[0], a, &p0[0]);
            mma_bf16(accL1[0], a, &q0[0]);
            mma_bf16(accL0[1], a, &p0[2]);
            mma_bf16(accL1[1], a, &q0[2]);
            mma_bf16(accL0[2], a, &p1[0]);
            mma_bf16(accL1[2], a, &q1[0]);
            mma_bf16(accL0[3], a, &p1[2]);
            mma_bf16(accL1[3], a, &q1[2]);
        }
        __syncthreads();

        if (doL1) {
            const bf16* hprev1 = g_h1buf + (size_t)ph * Bb * Hh;
#pragma unroll
            for (int it = 0; it < 6; it++) {
                int idx = tid + it * 256;
                int row = idx / 24, c = idx - row * 24;
                CP_ASYNC16(abase + (uint32_t)(row * 784 + 384 + c * 16),
                           hprev1 + (size_t)(b0 + row) * Hh + 192 + c * 8);
            }
            CP_COMMIT();
        }

        if (doL0) {
            bf16* hnext0 = g_h0buf + (size_t)(ph ^ 1) * Bb * Hh;
#pragma unroll
            for (int p = 0; p < 2; p++) {
                int brow = b0 + wm * 16 + prow + p * 8;
                float hnv[2];
#pragma unroll
                for (int q = 0; q < 2; q++) {
                    float xi = q ? xv[0][p].y : xv[0][p].x;
                    float xf = q ? xv[1][p].y : xv[1][p].x;
                    float xg = q ? xv[2][p].y : xv[2][p].x;
                    float xo = q ? xv[3][p].y : xv[3][p].x;
                    float i_ = sig_ap(accL0[0][p * 2 + q] + xi);
                    float f_ = sig_ap(accL0[1][p * 2 + q] + xf);
                    float g_ = tanh_ap(accL0[2][p * 2 + q] + xg);
                    float o_ = sig_ap(accL0[3][p * 2 + q] + xo);
                    float cn = f_ * cst0[p * 2 + q] + i_ * g_;
                    cst0[p * 2 + q] = cn;
                    hnv[q] = o_ * tanh_ap(cn);
                }
                *(__nv_bfloat162*)(hnext0 + (size_t)brow * Hh + colg) =
                    __floats2bfloat162_rn(hnv[0], hnv[1]);
            }
        }

        if (doL1) {
            CP_WAIT1();
            __syncthreads();
#pragma unroll 4
            for (int kt = 0; kt < 12; kt++) {
                uint32_t koff = (uint32_t)(kt * 32);
                uint32_t a[4], b0v[4], b1v[4];
                ldsm4(a, a1base + a1_off + koff);
                ldsm4(b0v, w1base + b_off0 + koff);
                ldsm4(b1v, w1base + b_off1 + koff);
                mma_bf16(accL1[0], a, &b0v[0]);
                mma_bf16(accL1[1], a, &b0v[2]);
                mma_bf16(accL1[2], a, &b1v[0]);
                mma_bf16(accL1[3], a, &b1v[2]);
            }
            CP_WAIT0();
            __syncthreads();
#pragma unroll 4
            for (int kt = 12; kt < 24; kt++) {
                uint32_t koff = (uint32_t)(kt * 32);
                uint32_t a[4], b0v[4], b1v[4];
                ldsm4(a, abase + a_off + koff);
                ldsm4(b0v, w1base + b_off0 + koff);
                ldsm4(b1v, w1base + b_off1 + koff);
                mma_bf16(accL1[0], a, &b0v[0]);
                mma_bf16(accL1[1], a, &b0v[2]);
                mma_bf16(accL1[2], a, &b1v[0]);
                mma_bf16(accL1[3], a, &b1v[2]);
            }

            bf16* hnext1 = g_h1buf + (size_t)(ph ^ 1) * Bb * Hh;
            bf16* houtp  = g_h1b + (size_t)(t - 1) * Bb * Hh;
#pragma unroll
            for (int p = 0; p < 2; p++) {
                int brow = b0 + wm * 16 + prow + p * 8;
                float hnv[2];
#pragma unroll
                for (int q = 0; q < 2; q++) {
                    float i_ = sig_ap(accL1[0][p * 2 + q] + bi1[0][q]);
                    float f_ = sig_ap(accL1[1][p * 2 + q] + bi1[1][q]);
                    float g_ = tanh_ap(accL1[2][p * 2 + q] + bi1[2][q]);
                    float o_ = sig_ap(accL1[3][p * 2 + q] + bi1[3][q]);
                    float cn = f_ * cst1[p * 2 + q] + i_ * g_;
                    cst1[p * 2 + q] = cn;
                    hnv[q] = o_ * tanh_ap(cn);
                }
                __nv_bfloat162 hh = __floats2bfloat162_rn(hnv[0], hnv[1]);
                *(__nv_bfloat162*)(hnext1 + (size_t)brow * Hh + colg) = hh;
                *(__nv_bfloat162*)(houtp + (size_t)brow * Hh + colg) = hh;
            }
        }

        group_barrier(bx, blockIdx.x, (unsigned int)(t + 1));
    }
}

// --------------- emissions: h1 @ Wc^T + bc (N=10, K=384) -------------------
__global__ __launch_bounds__(256) void em_kernel(const bf16* __restrict__ A)
{
    int row  = blockIdx.x * (blockDim.x >> 5) + (threadIdx.x >> 5);
    int lane = threadIdx.x & 31;
    float acc[Kc];
#pragma unroll
    for (int j = 0; j < Kc; j++) acc[j] = 0.f;
    const __nv_bfloat162* ar = (const __nv_bfloat162*)(A + (size_t)row * Hh);
#pragma unroll
    for (int it = 0; it < 6; it++) {
        int k2 = lane + it * 32;
        float2 a = __bfloat1622float2(ar[k2]);
#pragma unroll
        for (int j = 0; j < Kc; j++) {
            acc[j] += a.x * g_wc[j * Hh + 2 * k2] + a.y * g_wc[j * Hh + 2 * k2 + 1];
        }
    }
#pragma unroll
    for (int j = 0; j < Kc; j++) {
#pragma unroll
        for (int off = 16; off; off >>= 1)
            acc[j] += __shfl_xor_sync(0xffffffffu, acc[j], off);
    }
    if (lane == 0) {
#pragma unroll
        for (int j = 0; j < Kc; j++)
            g_em[(size_t)row * Kc + j] = acc[j] + g_bc[j];
    }
}

// ------------------------------ CRF ----------------------------------------
__global__ __launch_bounds__(32) void crf_kernel(
    const float* __restrict__ em, const int* __restrict__ tags,
    const float* __restrict__ start_t, const float* __restrict__ end_t,
    const float* __restrict__ trans)
{
    const int bp   = blockIdx.x;
    const int lane = threadIdx.x;
    const float NEG = -1e30f;

    float tr[Kc];
    int cl = (lane < Kc) ? lane : 0;
#pragma unroll
    for (int i = 0; i < Kc; i++) tr[i] = trans[i * Kc + cl];

    float a = (lane < Kc) ? (start_t[lane] + em[((size_t)bp * Tt) * Kc + lane]) : NEG;

    for (int tp = 1; tp < Tt; tp++) {
        float e = (lane < Kc) ? em[((size_t)bp * Tt + tp) * Kc + lane] : 0.f;
        float v[Kc];
        float m = NEG;
#pragma unroll
        for (int i = 0; i < Kc; i++) {
            float ai = __shfl_sync(0xffffffffu, a, i);
            v[i] = ai + tr[i];
            m = fmaxf(m, v[i]);
        }
        float s = 0.f;
#pragma unroll
        for (int i = 0; i < Kc; i++) s += __expf(v[i] - m);
        float an = m + __logf(s) + e;
        a = (lane < Kc) ? an : NEG;
    }

    float z = (lane < Kc) ? (a + end_t[lane]) : NEG;
    float zmax = z;
#pragma unroll
    for (int off = 16; off; off >>= 1)
        zmax = fmaxf(zmax, __shfl_xor_sync(0xffffffffu, zmax, off));
    float zs = (lane < Kc) ? __expf(z - zmax) : 0.f;
#pragma unroll
    for (int off = 16; off; off >>= 1)
        zs += __shfl_xor_sync(0xffffffffu, zs, off);
    float logZ = zmax + __logf(zs);

    if (lane == 0) {
        int prev = tags[(size_t)bp * Tt];
        float score = start_t[prev] + em[((size_t)bp * Tt) * Kc + prev];
        for (int tp = 1; tp < Tt; tp++) {
            int tg = tags[(size_t)bp * Tt + tp];
            score += trans[prev * Kc + tg] + em[((size_t)bp * Tt + tp) * Kc + tg];
            prev = tg;
        }
        score += end_t[prev];
        g_partial[bp] = logZ - score;
    }
}

__global__ __launch_bounds__(256) void reduce_kernel(float* __restrict__ out)
{
    __shared__ float sh[256];
    int i = threadIdx.x;
    sh[i] = g_partial[i];
    __syncthreads();
#pragma unroll
    for (int s = 128; s; s >>= 1) {
        if (i < s) sh[i] += sh[i + s];
        __syncthreads();
    }
    if (i == 0) out[0] = sh[0];
}

// ------------------------------ launch -------------------------------------
extern "C" void kernel_launch(void* const* d_in, const int* in_sizes, int n_in,
                              void* d_out, int out_size)
{
    (void)in_sizes; (void)n_in; (void)out_size;
    const float* x    = (const float*)d_in[0];
    const int*   tags = (const int*)d_in[2];
    const float* Wih0 = (const float*)d_in[3];
    const float* Whh0 = (const float*)d_in[4];
    const float* bih0 = (const float*)d_in[5];
    const float* bhh0 = (const float*)d_in[6];
    const float* Wih1 = (const float*)d_in[7];
    const float* Whh1 = (const float*)d_in[8];
    const float* bih1 = (const float*)d_in[9];
    const float* bhh1 = (const float*)d_in[10];
    const float* W1   = (const float*)d_in[11];
    const float* b1   = (const float*)d_in[12];
    const float* W2   = (const float*)d_in[13];
    const float* b2   = (const float*)d_in[14];
    const float* W3   = (const float*)d_in[15];
    const float* b3   = (const float*)d_in[16];
    const float* st   = (const float*)d_in[17];
    const float* et   = (const float*)d_in[18];
    const float* trn  = (const float*)d_in[19];

    float *emb;
    bf16 *h1b;
    cudaGetSymbolAddress((void**)&emb, g_em);
    cudaGetSymbolAddress((void**)&h1b, g_h1b);

    const int M = Tt * Bb;  // 65536
    const size_t LSTM_SMEM = (size_t)(4 * 64 * 392 + 64 * 200) * sizeof(bf16);
    cudaFuncSetAttribute(lstm_fused, cudaFuncAttributeMaxDynamicSharedMemorySize,
                         (int)LSTM_SMEM);

    init_state_kernel<<<(2 * Bb * Hh + 255) / 256, 256>>>();                  // 0
    conv_all<<<8192, 256>>>(x, Wih0);                                         // 1
    compose1<<<((Kc * 512 + 1024) * 32 + 255) / 256, 256>>>(W3, W2, b1, b2);  // 2
    compose2<<<((Kc * Hh + Kc) * 32 + 255) / 256, 256>>>(W1, W3, b3);         // 3

    // fused: 96 LSTM CTAs + 52 xw0-GEMM producer CTAs (GEMM hides under LSTM)
    lstm_fused<<<NCTA_LSTM + NCTA_GEMM, 256, LSTM_SMEM>>>(                    // 4
        Whh0, Wih1, Whh1, bih1, bhh1, bih0, bhh0);

    // collapsed MLP: em = h1 @ Wc^T + bc
    em_kernel<<<M / 8, 256>>>(h1b);                                           // 5

    crf_kernel<<<Bb, 32>>>(emb, tags, st, et, trn);                           // 6
    reduce_kernel<<<1, 256>>>((float*)d_out);                                 // 7
}

// round 13
// speedup vs baseline: 1.3747x; 1.0143x over previous
#include <cuda_runtime.h>
#include <cuda_bf16.h>
#include <cstdint>
#include <cstddef>

// ---------------------------------------------------------------------------
// BiLSTM-NER, Round 12:
//  * group barrier FIXED to poll the actual group members {bx, bx+4, ...}
//    (previous poll set mixed batch groups — raced by luck).
//  * conv_all removed: producer CTAs convert x/Wih0 inline in the GEMM loads.
//  * em_kernel folded into producer CTAs (gated on h1 publication flags).
//  * LSTM dataflow unchanged from R11 (proven 2362us).
// ---------------------------------------------------------------------------

#define Tt 256
#define Bb 256
#define Hh 384
#define G4 1536   // 4*H
#define INP 100
#define Kc 10
#define NCTA_LSTM 96
#define NCTA_GEMM 52
#define NTILES (512 * 12)   // (M/128) * (G4/128)

typedef __nv_bfloat16 bf16;

// ============================ PTX helpers ==================================
__device__ __forceinline__ uint32_t smem_to_u32(const void* p) {
    uint32_t a;
    asm("{ .reg .u64 t; cvta.to.shared.u64 t, %1; cvt.u32.u64 %0, t; }"
        : "=r"(a) : "l"(p));
    return a;
}
__device__ __forceinline__ void ldsm4(uint32_t* r, uint32_t saddr) {
    asm volatile("ldmatrix.sync.aligned.m8n8.x4.shared.b16 {%0,%1,%2,%3}, [%4];"
        : "=r"(r[0]), "=r"(r[1]), "=r"(r[2]), "=r"(r[3]) : "r"(saddr));
}
__device__ __forceinline__ void mma_bf16(float* c, const uint32_t* a, const uint32_t* b) {
    asm volatile(
        "mma.sync.aligned.m16n8k16.row.col.f32.bf16.bf16.f32 "
        "{%0,%1,%2,%3}, {%4,%5,%6,%7}, {%8,%9}, {%0,%1,%2,%3};"
        : "+f"(c[0]), "+f"(c[1]), "+f"(c[2]), "+f"(c[3])
        : "r"(a[0]), "r"(a[1]), "r"(a[2]), "r"(a[3]), "r"(b[0]), "r"(b[1]));
}
#define CP_ASYNC16(sa, ga) \
    asm volatile("cp.async.cg.shared.global [%0], [%1], 16;" \
                 :: "r"(sa), "l"(ga) : "memory")
#define CP_COMMIT() asm volatile("cp.async.commit_group;" ::: "memory")
#define CP_WAIT0()  asm volatile("cp.async.wait_group 0;" ::: "memory")
#define CP_WAIT1()  asm volatile("cp.async.wait_group 1;" ::: "memory")

__device__ __forceinline__ float tanh_ap(float x) {
    float y; asm("tanh.approx.f32 %0, %1;" : "=f"(y) : "f"(x)); return y;
}
__device__ __forceinline__ float sig_ap(float x) {
    return fmaf(tanh_ap(0.5f * x), 0.5f, 0.5f);
}
__device__ __forceinline__ void st_release_gpu(unsigned int* p, unsigned int v) {
    asm volatile("st.global.release.gpu.b32 [%0], %1;" :: "l"(p), "r"(v) : "memory");
}
__device__ __forceinline__ unsigned int ld_acquire_gpu(const unsigned int* p) {
    unsigned int v;
    asm volatile("ld.global.acquire.gpu.b32 %0, [%1];" : "=r"(v) : "l"(p) : "memory");
    return v;
}
__device__ __forceinline__ void red_release_gpu(unsigned int* p, unsigned int v) {
    asm volatile("red.release.gpu.global.add.u32 [%0], %1;" :: "l"(p), "r"(v) : "memory");
}

// ------------------------- scratch (device globals) ------------------------
__device__ bf16  g_xwb[(size_t)Tt * Bb * G4];      // layer-0 gate pre-acts (bf16)
__device__ bf16  g_h1b[(size_t)Tt * Bb * Hh];      // layer1 outputs (bf16)
__device__ float g_em[(size_t)Tt * Bb * Kc];       // emissions (fp32)
__device__ float g_wc1[Kc * 512];                  // W3 @ W2  (10 x 512)
__device__ float g_wc[Kc * Hh];                    // W3@W2@W1 (10 x 384)
__device__ float g_t1[1024];                       // W2 @ b1 + b2
__device__ float g_bc[Kc];                         // composed bias
__device__ bf16  g_h0buf[2 * Bb * Hh];             // recurrent h0 state (bf16)
__device__ bf16  g_h1buf[2 * Bb * Hh];             // recurrent h1 state (bf16)
__device__ float g_partial[Bb];

// one flag per CTA, each on its own 128B line
__device__ unsigned int g_flags[NCTA_LSTM * 32];
// per-timestep xw readiness counters (24 tiles per timestep)
__device__ unsigned int g_ready[Tt];

// ------------------------------ init state --------------------------------
__global__ void init_state_kernel() {
    int i = blockIdx.x * blockDim.x + threadIdx.x;
    if (i < 2 * Bb * Hh) {
        g_h0buf[i] = __float2bfloat16(0.f);
        g_h1buf[i] = __float2bfloat16(0.f);
    }
    if (i < NCTA_LSTM * 32) g_flags[i] = 0u;
    if (i < Tt) g_ready[i] = 0u;
}

// -------------- MLP weight composition (warp per output) -------------------
__global__ __launch_bounds__(256) void compose1(
    const float* __restrict__ W3, const float* __restrict__ W2,
    const float* __restrict__ b1, const float* __restrict__ b2)
{
    int w = (blockIdx.x * blockDim.x + threadIdx.x) >> 5;
    int lane = threadIdx.x & 31;
    if (w < Kc * 512) {
        int r = w / 512, c = w - r * 512;
        float s = 0.f;
        for (int k = lane; k < 1024; k += 32)
            s += W3[r * 1024 + k] * W2[k * 512 + c];
#pragma unroll
        for (int off = 16; off; off >>= 1)
            s += __shfl_xor_sync(0xffffffffu, s, off);
        if (lane == 0) g_wc1[w] = s;
    } else if (w < Kc * 512 + 1024) {
        int j = w - Kc * 512;
        float s = 0.f;
        for (int k = lane; k < 512; k += 32)
            s += W2[j * 512 + k] * b1[k];
#pragma unroll
        for (int off = 16; off; off >>= 1)
            s += __shfl_xor_sync(0xffffffffu, s, off);
        if (lane == 0) g_t1[j] = s + b2[j];
    }
}
__global__ __launch_bounds__(256) void compose2(
    const float* __restrict__ W1, const float* __restrict__ W3,
    const float* __restrict__ b3)
{
    int w = (blockIdx.x * blockDim.x + threadIdx.x) >> 5;
    int lane = threadIdx.x & 31;
    if (w < Kc * Hh) {
        int r = w / Hh, c = w - r * Hh;
        float s = 0.f;
        for (int k = lane; k < 512; k += 32)
            s += g_wc1[r * 512 + k] * W1[k * Hh + c];
#pragma unroll
        for (int off = 16; off; off >>= 1)
            s += __shfl_xor_sync(0xffffffffu, s, off);
        if (lane == 0) g_wc[w] = s;
    } else if (w < Kc * Hh + Kc) {
        int r = w - Kc * Hh;
        float s = 0.f;
        for (int k = lane; k < 1024; k += 32)
            s += W3[r * 1024 + k] * g_t1[k];
#pragma unroll
        for (int off = 16; off; off >>= 1)
            s += __shfl_xor_sync(0xffffffffu, s, off);
        if (lane == 0) g_bc[r] = s + b3[r];
    }
}

// ------------- release/acquire group barrier (24 CTAs/group) ---------------
// FIXED: poll exactly the group's members {grp, grp+4, ..., grp+92}.
__device__ __forceinline__ void group_barrier(int grp, int cta_in_grid,
                                              unsigned int target) {
    __syncthreads();
    if (threadIdx.x < 32) {
        if (threadIdx.x == 0)
            st_release_gpu(&g_flags[cta_in_grid * 32], target);
        if (threadIdx.x < 24) {
            const unsigned int* f = &g_flags[(grp + threadIdx.x * 4) * 32];
            while (ld_acquire_gpu(f) < target) { }
        }
    }
    __syncthreads();
}

// ---------------- producer: inline-convert tile loader ---------------------
// Fill one 128-row x 32-k bf16 chunk (row stride 40) from an fp32 source
// with INP->128 zero padding.
__device__ __forceinline__ void fill_chunk_conv(
    bf16* buf, const float* __restrict__ src, int base_row, int kt,
    int lrow, int lc)
{
#pragma unroll
    for (int it = 0; it < 2; it++) {
        int row = lrow + it * 64;
        int r = base_row + row;
        int k = kt * 32 + lc * 8;
        float v[8];
        if (k + 7 < INP) {
            float4 a = *(const float4*)(src + (size_t)r * INP + k);
            float4 b = *(const float4*)(src + (size_t)r * INP + k + 4);
            v[0] = a.x; v[1] = a.y; v[2] = a.z; v[3] = a.w;
            v[4] = b.x; v[5] = b.y; v[6] = b.z; v[7] = b.w;
        } else {
#pragma unroll
            for (int i = 0; i < 8; i++)
                v[i] = (k + i < INP) ? src[(size_t)r * INP + k + i] : 0.f;
        }
        __nv_bfloat162 h0 = __floats2bfloat162_rn(v[0], v[1]);
        __nv_bfloat162 h1 = __floats2bfloat162_rn(v[2], v[3]);
        __nv_bfloat162 h2 = __floats2bfloat162_rn(v[4], v[5]);
        __nv_bfloat162 h3 = __floats2bfloat162_rn(v[6], v[7]);
        uint4 pk;
        pk.x = *(uint32_t*)&h0; pk.y = *(uint32_t*)&h1;
        pk.z = *(uint32_t*)&h2; pk.w = *(uint32_t*)&h3;
        *(uint4*)(buf + row * 40 + lc * 8) = pk;
    }
}

// ---------------- producer role: xw0 GEMM + emissions ----------------------
__device__ void producer_role(bf16* dsm, const float* __restrict__ x,
                              const float* __restrict__ Wih0,
                              const float* __restrict__ bih0,
                              const float* __restrict__ bhh0, int worker)
{
    bf16* smA = dsm;                 // 128 x 40 (one 32-k chunk)
    bf16* smB = dsm + 5120;
    const uint32_t saddrA = smem_to_u32(smA);
    const uint32_t saddrB = smem_to_u32(smB);

    const int tid = threadIdx.x;
    const int lane = tid & 31;
    const int wid = tid >> 5;
    const int wm = wid & 3;
    const int wn = wid >> 2;

    const uint32_t a_off =
        (uint32_t)(((wm * 32 + (lane & 15)) * 40 + (lane >> 4) * 8) * 2);
    uint32_t b_off[4];
#pragma unroll
    for (int jp = 0; jp < 4; jp++)
        b_off[jp] = (uint32_t)(((wn * 64 + jp * 16 + (lane & 7) + ((lane >> 4) << 3)) * 40
                                + ((lane >> 3) & 1) * 8) * 2);
    const int lrow = tid >> 2;
    const int lc   = tid & 3;

    // ---- phase 1: xw0 GEMM tiles (inline fp32->bf16 conversion)
    for (int id = worker; id < NTILES; id += NCTA_GEMM) {
        const int t2 = id / 12;
        const int nb = id - t2 * 12;
        const int m0 = t2 * 128;
        const int n0 = nb * 128;

        float acc[2][8][4];
#pragma unroll
        for (int i = 0; i < 2; i++)
#pragma unroll
            for (int j = 0; j < 8; j++)
#pragma unroll
                for (int q = 0; q < 4; q++) acc[i][j][q] = 0.f;

        for (int kt = 0; kt < 4; kt++) {
            fill_chunk_conv(smA, x,    m0, kt, lrow, lc);
            fill_chunk_conv(smB, Wih0, n0, kt, lrow, lc);
            __syncthreads();
#pragma unroll
            for (int kk = 0; kk < 2; kk++) {
                uint32_t a[2][4], b[4][4];
                ldsm4(a[0], saddrA + a_off + kk * 32);
                ldsm4(a[1], saddrA + a_off + 1280 + kk * 32);
#pragma unroll
                for (int jp = 0; jp < 4; jp++)
                    ldsm4(b[jp], saddrB + b_off[jp] + kk * 32);
#pragma unroll
                for (int mt = 0; mt < 2; mt++)
#pragma unroll
                    for (int j = 0; j < 8; j++)
                        mma_bf16(acc[mt][j], a[mt], &b[j >> 1][(j & 1) * 2]);
            }
            __syncthreads();
        }

#pragma unroll
        for (int mt = 0; mt < 2; mt++)
#pragma unroll
            for (int j = 0; j < 8; j++)
#pragma unroll
                for (int p = 0; p < 2; p++) {
                    int row = m0 + wm * 32 + mt * 16 + (lane >> 2) + p * 8;
                    int col = n0 + wn * 64 + j * 8 + (lane & 3) * 2;
                    float v0 = acc[mt][j][p * 2]     + bih0[col]     + bhh0[col];
                    float v1 = acc[mt][j][p * 2 + 1] + bih0[col + 1] + bhh0[col + 1];
                    *(__nv_bfloat162*)(g_xwb + (size_t)row * G4 + col) =
                        __floats2bfloat162_rn(v0, v1);
                }

        __threadfence();
        __syncthreads();
        if (tid == 0) red_release_gpu(&g_ready[t2 >> 1], 1u);
    }

    // ---- phase 2: emissions em = h1 @ Wc^T + bc, trailing the LSTM frontier
    for (int tau = worker; tau < Tt; tau += NCTA_GEMM) {
        // gate: h1(tau) stored in interval tau+1, published at target tau+2
        if (tid < NCTA_LSTM) {
            while (ld_acquire_gpu(&g_flags[tid * 32]) < (unsigned int)(tau + 2)) { }
        }
        __syncthreads();

        for (int rr = wid; rr < Bb; rr += 8) {
            int row = tau * Bb + rr;
            float acc[Kc];
#pragma unroll
            for (int j = 0; j < Kc; j++) acc[j] = 0.f;
            const __nv_bfloat162* ar =
                (const __nv_bfloat162*)(g_h1b + (size_t)row * Hh);
#pragma unroll
            for (int it = 0; it < 6; it++) {
                int k2 = lane + it * 32;
                float2 a = __bfloat1622float2(ar[k2]);
#pragma unroll
                for (int j = 0; j < Kc; j++)
                    acc[j] += a.x * g_wc[j * Hh + 2 * k2]
                            + a.y * g_wc[j * Hh + 2 * k2 + 1];
            }
#pragma unroll
            for (int j = 0; j < Kc; j++) {
#pragma unroll
                for (int off = 16; off; off >>= 1)
                    acc[j] += __shfl_xor_sync(0xffffffffu, acc[j], off);
            }
            if (lane == 0) {
#pragma unroll
                for (int j = 0; j < Kc; j++)
                    g_em[(size_t)row * Kc + j] = acc[j] + g_bc[j];
            }
        }
        __syncthreads();
    }
}

// ================== fused 2-layer persistent LSTM + producer ===============
__global__ __launch_bounds__(256) void lstm_fused(
    const float* __restrict__ Whh0, const float* __restrict__ Wih1,
    const float* __restrict__ Whh1, const float* __restrict__ bih1,
    const float* __restrict__ bhh1, const float* __restrict__ bih0,
    const float* __restrict__ bhh0, const float* __restrict__ x,
    const float* __restrict__ Wih0)
{
    extern __shared__ bf16 dsm[];

    if (blockIdx.x >= NCTA_LSTM) {
        producer_role(dsm, x, Wih0, bih0, bhh0, blockIdx.x - NCTA_LSTM);
        return;
    }

    bf16* W0sm  = dsm;                    // Whh0 slice  (64n x 392)
    bf16* Wi1sm = dsm + 64 * 392;         // Wih1 slice
    bf16* W1sm  = dsm + 2 * 64 * 392;     // Whh1 slice
    bf16* Asm   = dsm + 3 * 64 * 392;     // A0 tile (64 x 392)
    bf16* A1sm  = dsm + 4 * 64 * 392;     // h1 k-tiles 0..11 (64 x 200)
    const uint32_t w0base  = smem_to_u32(W0sm);
    const uint32_t wi1base = smem_to_u32(Wi1sm);
    const uint32_t w1base  = smem_to_u32(W1sm);
    const uint32_t abase   = smem_to_u32(Asm);
    const uint32_t a1base  = smem_to_u32(A1sm);

    const int tid = threadIdx.x;
    const int lane = tid & 31;
    const int wid = tid >> 5;
    const int wm = wid & 3;              // 16-row m tile
    const int wn = wid >> 2;             // h-col half (0/1)
    const int bx = blockIdx.x & 3;
    const int by = blockIdx.x >> 2;
    const int b0 = bx * 64;
    const int c0 = by * 16;

    for (int idx = tid; idx < 64 * 384; idx += 256) {
        int n = idx / 384, k = idx - n * 384;
        int g = n >> 4, hc = n & 15;
        size_t grow = (size_t)(g * Hh + c0 + hc) * Hh + k;
        int d = n * 392 + k;
        W0sm[d]  = __float2bfloat16(Whh0[grow]);
        Wi1sm[d] = __float2bfloat16(Wih1[grow]);
        W1sm[d]  = __float2bfloat16(Whh1[grow]);
    }

    const uint32_t a_off =
        (uint32_t)(((wm * 16 + (lane & 15)) * 392 + (lane >> 4) * 8) * 2);
    const uint32_t a1_off =
        (uint32_t)(((wm * 16 + (lane & 15)) * 200 + (lane >> 4) * 8) * 2);
    const uint32_t b_k = ((lane >> 3) & 1) * 8;
    const uint32_t b_off0 =
        (uint32_t)((((0 + (lane >> 4)) * 16 + wn * 8 + (lane & 7)) * 392 + b_k) * 2);
    const uint32_t b_off1 =
        (uint32_t)((((2 + (lane >> 4)) * 16 + wn * 8 + (lane & 7)) * 392 + b_k) * 2);

    const int prow = lane >> 2;
    const int pcol = (lane & 3) * 2;
    const int colg = c0 + wn * 8 + pcol;

    float bi1[4][2];
#pragma unroll
    for (int g = 0; g < 4; g++)
#pragma unroll
        for (int q = 0; q < 2; q++)
            bi1[g][q] = bih1[g * Hh + colg + q] + bhh1[g * Hh + colg + q];

    float cst0[4], cst1[4];
#pragma unroll
    for (int i = 0; i < 4; i++) { cst0[i] = 0.f; cst1[i] = 0.f; }

    for (int t = 0; t <= Tt; t++) {
        const int ph = t & 1;
        const bool doL0 = (t < Tt);
        const bool doL1 = (t >= 1);

        // ---- issue A0 <- h0(t-1); A1 <- h1(t-2) k-tiles 0..11
        {
            const bf16* hprev0 = g_h0buf + (size_t)ph * Bb * Hh;
#pragma unroll
            for (int it = 0; it < 12; it++) {
                int idx = tid + it * 256;
                int row = idx / 48, c = idx - row * 48;
                CP_ASYNC16(abase + (uint32_t)((row * 392 + c * 8) * 2),
                           hprev0 + (size_t)(b0 + row) * Hh + c * 8);
            }
            CP_COMMIT();
        }
        if (doL1) {
            const bf16* hprev1 = g_h1buf + (size_t)ph * Bb * Hh;
#pragma unroll
            for (int it = 0; it < 6; it++) {
                int idx = tid + it * 256;
                int row = idx / 24, c = idx - row * 24;
                CP_ASYNC16(a1base + (uint32_t)(row * 400 + c * 16),
                           hprev1 + (size_t)(b0 + row) * Hh + c * 8);
            }
            CP_COMMIT();
        }

        // ---- gate on producer-published xw(t)
        if (doL0) {
            if (tid == 0) {
                while (ld_acquire_gpu(&g_ready[t]) < 24u) { }
            }
        }
        __syncthreads();

        float2 xv[4][2];
        if (doL0) {
            const bf16* xw = g_xwb + (size_t)t * Bb * G4;
#pragma unroll
            for (int g = 0; g < 4; g++)
#pragma unroll
                for (int p = 0; p < 2; p++) {
                    int brow = b0 + wm * 16 + prow + p * 8;
                    xv[g][p] = __bfloat1622float2(
                        *(const __nv_bfloat162*)(xw + (size_t)brow * G4 + g * Hh + colg));
                }
        }

        if (doL1) CP_WAIT1(); else CP_WAIT0();
        __syncthreads();

        float accL0[4][4], accL1[4][4];
#pragma unroll
        for (int j = 0; j < 4; j++)
#pragma unroll
            for (int q = 0; q < 4; q++) { accL0[j][q] = 0.f; accL1[j][q] = 0.f; }

#pragma unroll 4
        for (int kt = 0; kt < 24; kt++) {
            uint32_t koff = (uint32_t)(kt * 32);
            uint32_t a[4], p0[4], p1[4], q0[4], q1[4];
            ldsm4(a, abase + a_off + koff);
            ldsm4(p0, w0base + b_off0 + koff);
            ldsm4(p1, w0base + b_off1 + koff);
            ldsm4(q0, wi1base + b_off0 + koff);
            ldsm4(q1, wi1base + b_off1 + koff);
            mma_bf16(accL0[0], a, &p0[0]);
            mma_bf16(accL1[0], a, &q0[0]);
            mma_bf16(accL0[1], a, &p0[2]);
            mma_bf16(accL1[1], a, &q0[2]);
            mma_bf16(accL0[2], a, &p1[0]);
            mma_bf16(accL1[2], a, &q1[0]);
            mma_bf16(accL0[3], a, &p1[2]);
            mma_bf16(accL1[3], a, &q1[2]);
        }
        __syncthreads();

        if (doL1) {
            const bf16* hprev1 = g_h1buf + (size_t)ph * Bb * Hh;
#pragma unroll
            for (int it = 0; it < 6; it++) {
                int idx = tid + it * 256;
                int row = idx / 24, c = idx - row * 24;
                CP_ASYNC16(abase + (uint32_t)(row * 784 + 384 + c * 16),
                           hprev1 + (size_t)(b0 + row) * Hh + 192 + c * 8);
            }
            CP_COMMIT();
        }

        if (doL0) {
            bf16* hnext0 = g_h0buf + (size_t)(ph ^ 1) * Bb * Hh;
#pragma unroll
            for (int p = 0; p < 2; p++) {
                int brow = b0 + wm * 16 + prow + p * 8;
                float hnv[2];
#pragma unroll
                for (int q = 0; q < 2; q++) {
                    float xi = q ? xv[0][p].y : xv[0][p].x;
                    float xf = q ? xv[1][p].y : xv[1][p].x;
                    float xg = q ? xv[2][p].y : xv[2][p].x;
                    float xo = q ? xv[3][p].y : xv[3][p].x;
                    float i_ = sig_ap(accL0[0][p * 2 + q] + xi);
                    float f_ = sig_ap(accL0[1][p * 2 + q] + xf);
                    float g_ = tanh_ap(accL0[2][p * 2 + q] + xg);
                    float o_ = sig_ap(accL0[3][p * 2 + q] + xo);
                    float cn = f_ * cst0[p * 2 + q] + i_ * g_;
                    cst0[p * 2 + q] = cn;
                    hnv[q] = o_ * tanh_ap(cn);
                }
                *(__nv_bfloat162*)(hnext0 + (size_t)brow * Hh + colg) =
                    __floats2bfloat162_rn(hnv[0], hnv[1]);
            }
        }

        if (doL1) {
            CP_WAIT1();
            __syncthreads();
#pragma unroll 4
            for (int kt = 0; kt < 12; kt++) {
                uint32_t koff = (uint32_t)(kt * 32);
                uint32_t a[4], b0v[4], b1v[4];
                ldsm4(a, a1base + a1_off + koff);
                ldsm4(b0v, w1base + b_off0 + koff);
                ldsm4(b1v, w1base + b_off1 + koff);
                mma_bf16(accL1[0], a, &b0v[0]);
                mma_bf16(accL1[1], a, &b0v[2]);
                mma_bf16(accL1[2], a, &b1v[0]);
                mma_bf16(accL1[3], a, &b1v[2]);
            }
            CP_WAIT0();
            __syncthreads();
#pragma unroll 4
            for (int kt = 12; kt < 24; kt++) {
                uint32_t koff = (uint32_t)(kt * 32);
                uint32_t a[4], b0v[4], b1v[4];
                ldsm4(a, abase + a_off + koff);
                ldsm4(b0v, w1base + b_off0 + koff);
                ldsm4(b1v, w1base + b_off1 + koff);
                mma_bf16(accL1[0], a, &b0v[0]);
                mma_bf16(accL1[1], a, &b0v[2]);
                mma_bf16(accL1[2], a, &b1v[0]);
                mma_bf16(accL1[3], a, &b1v[2]);
            }

            bf16* hnext1 = g_h1buf + (size_t)(ph ^ 1) * Bb * Hh;
            bf16* houtp  = g_h1b + (size_t)(t - 1) * Bb * Hh;
#pragma unroll
            for (int p = 0; p < 2; p++) {
                int brow = b0 + wm * 16 + prow + p * 8;
                float hnv[2];
#pragma unroll
                for (int q = 0; q < 2; q++) {
                    float i_ = sig_ap(accL1[0][p * 2 + q] + bi1[0][q]);
                    float f_ = sig_ap(accL1[1][p * 2 + q] + bi1[1][q]);
                    float g_ = tanh_ap(accL1[2][p * 2 + q] + bi1[2][q]);
                    float o_ = sig_ap(accL1[3][p * 2 + q] + bi1[3][q]);
                    float cn = f_ * cst1[p * 2 + q] + i_ * g_;
                    cst1[p * 2 + q] = cn;
                    hnv[q] = o_ * tanh_ap(cn);
                }
                __nv_bfloat162 hh = __floats2bfloat162_rn(hnv[0], hnv[1]);
                *(__nv_bfloat162*)(hnext1 + (size_t)brow * Hh + colg) = hh;
                *(__nv_bfloat162*)(houtp + (size_t)brow * Hh + colg) = hh;
            }
        }

        group_barrier(bx, blockIdx.x, (unsigned int)(t + 1));
    }
}

// ------------------------------ CRF ----------------------------------------
__global__ __launch_bounds__(32) void crf_kernel(
    const float* __restrict__ em, const int* __restrict__ tags,
    const float* __restrict__ start_t, const float* __restrict__ end_t,
    const float* __restrict__ trans)
{
    const int bp   = blockIdx.x;
    const int lane = threadIdx.x;
    const float NEG = -1e30f;

    float tr[Kc];
    int cl = (lane < Kc) ? lane : 0;
#pragma unroll
    for (int i = 0; i < Kc; i++) tr[i] = trans[i * Kc + cl];

    float a = (lane < Kc) ? (start_t[lane] + em[((size_t)bp * Tt) * Kc + lane]) : NEG;

    for (int tp = 1; tp < Tt; tp++) {
        float e = (lane < Kc) ? em[((size_t)bp * Tt + tp) * Kc + lane] : 0.f;
        float v[Kc];
        float m = NEG;
#pragma unroll
        for (int i = 0; i < Kc; i++) {
            float ai = __shfl_sync(0xffffffffu, a, i);
            v[i] = ai + tr[i];
            m = fmaxf(m, v[i]);
        }
        float s = 0.f;
#pragma unroll
        for (int i = 0; i < Kc; i++) s += __expf(v[i] - m);
        float an = m + __logf(s) + e;
        a = (lane < Kc) ? an : NEG;
    }

    float z = (lane < Kc) ? (a + end_t[lane]) : NEG;
    float zmax = z;
#pragma unroll
    for (int off = 16; off; off >>= 1)
        zmax = fmaxf(zmax, __shfl_xor_sync(0xffffffffu, zmax, off));
    float zs = (lane < Kc) ? __expf(z - zmax) : 0.f;
#pragma unroll
    for (int off = 16; off; off >>= 1)
        zs += __shfl_xor_sync(0xffffffffu, zs, off);
    float logZ = zmax + __logf(zs);

    if (lane == 0) {
        int prev = tags[(size_t)bp * Tt];
        float score = start_t[prev] + em[((size_t)bp * Tt) * Kc + prev];
        for (int tp = 1; tp < Tt; tp++) {
            int tg = tags[(size_t)bp * Tt + tp];
            score += trans[prev * Kc + tg] + em[((size_t)bp * Tt + tp) * Kc + tg];
            prev = tg;
        }
        score += end_t[prev];
        g_partial[bp] = logZ - score;
    }
}

__global__ __launch_bounds__(256) void reduce_kernel(float* __restrict__ out)
{
    __shared__ float sh[256];
    int i = threadIdx.x;
    sh[i] = g_partial[i];
    __syncthreads();
#pragma unroll
    for (int s = 128; s; s >>= 1) {
        if (i < s) sh[i] += sh[i + s];
        __syncthreads();
    }
    if (i == 0) out[0] = sh[0];
}

// ------------------------------ launch -------------------------------------
extern "C" void kernel_launch(void* const* d_in, const int* in_sizes, int n_in,
                              void* d_out, int out_size)
{
    (void)in_sizes; (void)n_in; (void)out_size;
    const float* x    = (const float*)d_in[0];
    const int*   tags = (const int*)d_in[2];
    const float* Wih0 = (const float*)d_in[3];
    const float* Whh0 = (const float*)d_in[4];
    const float* bih0 = (const float*)d_in[5];
    const float* bhh0 = (const float*)d_in[6];
    const float* Wih1 = (const float*)d_in[7];
    const float* Whh1 = (const float*)d_in[8];
    const float* bih1 = (const float*)d_in[9];
    const float* bhh1 = (const float*)d_in[10];
    const float* W1   = (const float*)d_in[11];
    const float* b1   = (const float*)d_in[12];
    const float* W2   = (const float*)d_in[13];
    const float* b2   = (const float*)d_in[14];
    const float* W3   = (const float*)d_in[15];
    const float* b3   = (const float*)d_in[16];
    const float* st   = (const float*)d_in[17];
    const float* et   = (const float*)d_in[18];
    const float* trn  = (const float*)d_in[19];

    float* emb;
    cudaGetSymbolAddress((void**)&emb, g_em);

    const size_t LSTM_SMEM = (size_t)(4 * 64 * 392 + 64 * 200) * sizeof(bf16);
    cudaFuncSetAttribute(lstm_fused, cudaFuncAttributeMaxDynamicSharedMemorySize,
                         (int)LSTM_SMEM);

    init_state_kernel<<<(2 * Bb * Hh + 255) / 256, 256>>>();                  // 0
    compose1<<<((Kc * 512 + 1024) * 32 + 255) / 256, 256>>>(W3, W2, b1, b2);  // 1
    compose2<<<((Kc * Hh + Kc) * 32 + 255) / 256, 256>>>(W1, W3, b3);         // 2

    // fused: 96 LSTM CTAs + 52 producer CTAs (xw0 GEMM w/ inline conversion,
    // then emissions trailing the LSTM frontier)
    lstm_fused<<<NCTA_LSTM + NCTA_GEMM, 256, LSTM_SMEM>>>(                    // 3
        Whh0, Wih1, Whh1, bih1, bhh1, bih0, bhh0, x, Wih0);

    crf_kernel<<<Bb, 32>>>(emb, tags, st, et, trn);                           // 4
    reduce_kernel<<<1, 256>>>((float*)d_out);                                 // 5
}

// round 14
// speedup vs baseline: 1.4681x; 1.0680x over previous
#include <cuda_runtime.h>
#include <cuda_bf16.h>
#include <cstdint>
#include <cstddef>

// ---------------------------------------------------------------------------
// BiLSTM-NER, Round 13 (R12 base, proven 2329us):
//  * xw stored PERMUTED so the consumer reads 1 LDG.128/row instead of 8 LDG.64
//  * h1buf deleted: phase B reads h1(t-2) from the g_h1b history directly
//    (one store instead of two; t==1 skips the zero Whh1 pass)
//  * CRF folded into producer CTAs (sequence tau = timestep tau, fully local)
// ---------------------------------------------------------------------------

#define Tt 256
#define Bb 256
#define Hh 384
#define G4 1536   // 4*H
#define INP 100
#define Kc 10
#define NCTA_LSTM 96
#define NCTA_GEMM 52
#define NTILES (512 * 12)   // (M/128) * (G4/128)

typedef __nv_bfloat16 bf16;

// ============================ PTX helpers ==================================
__device__ __forceinline__ uint32_t smem_to_u32(const void* p) {
    uint32_t a;
    asm("{ .reg .u64 t; cvta.to.shared.u64 t, %1; cvt.u32.u64 %0, t; }"
        : "=r"(a) : "l"(p));
    return a;
}
__device__ __forceinline__ void ldsm4(uint32_t* r, uint32_t saddr) {
    asm volatile("ldmatrix.sync.aligned.m8n8.x4.shared.b16 {%0,%1,%2,%3}, [%4];"
        : "=r"(r[0]), "=r"(r[1]), "=r"(r[2]), "=r"(r[3]) : "r"(saddr));
}
__device__ __forceinline__ void mma_bf16(float* c, const uint32_t* a, const uint32_t* b) {
    asm volatile(
        "mma.sync.aligned.m16n8k16.row.col.f32.bf16.bf16.f32 "
        "{%0,%1,%2,%3}, {%4,%5,%6,%7}, {%8,%9}, {%0,%1,%2,%3};"
        : "+f"(c[0]), "+f"(c[1]), "+f"(c[2]), "+f"(c[3])
        : "r"(a[0]), "r"(a[1]), "r"(a[2]), "r"(a[3]), "r"(b[0]), "r"(b[1]));
}
#define CP_ASYNC16(sa, ga) \
    asm volatile("cp.async.cg.shared.global [%0], [%1], 16;" \
                 :: "r"(sa), "l"(ga) : "memory")
#define CP_COMMIT() asm volatile("cp.async.commit_group;" ::: "memory")
#define CP_WAIT0()  asm volatile("cp.async.wait_group 0;" ::: "memory")
#define CP_WAIT1()  asm volatile("cp.async.wait_group 1;" ::: "memory")

__device__ __forceinline__ float tanh_ap(float x) {
    float y; asm("tanh.approx.f32 %0, %1;" : "=f"(y) : "f"(x)); return y;
}
__device__ __forceinline__ float sig_ap(float x) {
    return fmaf(tanh_ap(0.5f * x), 0.5f, 0.5f);
}
__device__ __forceinline__ void st_release_gpu(unsigned int* p, unsigned int v) {
    asm volatile("st.global.release.gpu.b32 [%0], %1;" :: "l"(p), "r"(v) : "memory");
}
__device__ __forceinline__ unsigned int ld_acquire_gpu(const unsigned int* p) {
    unsigned int v;
    asm volatile("ld.global.acquire.gpu.b32 %0, [%1];" : "=r"(v) : "l"(p) : "memory");
    return v;
}
__device__ __forceinline__ void red_release_gpu(unsigned int* p, unsigned int v) {
    asm volatile("red.release.gpu.global.add.u32 [%0], %1;" :: "l"(p), "r"(v) : "memory");
}

// ------------------------- scratch (device globals) ------------------------
// xw permuted: xwP[((t*256+row)*192 + hc/2)*8 + gate*2 + q]  (bf16)
__device__ bf16  g_xwb[(size_t)Tt * Bb * G4];
__device__ bf16  g_h1b[(size_t)Tt * Bb * Hh];      // layer1 outputs (history)
__device__ float g_em[(size_t)Tt * Bb * Kc];       // emissions (fp32)
__device__ float g_wc1[Kc * 512];                  // W3 @ W2  (10 x 512)
__device__ float g_wc[Kc * Hh];                    // W3@W2@W1 (10 x 384)
__device__ float g_t1[1024];                       // W2 @ b1 + b2
__device__ float g_bc[Kc];                         // composed bias
__device__ bf16  g_h0buf[2 * Bb * Hh];             // recurrent h0 state (bf16)
__device__ float g_partial[Bb];

__device__ unsigned int g_flags[NCTA_LSTM * 32];   // one per CTA, own 128B line
__device__ unsigned int g_ready[Tt];               // xw tiles ready (24/step)

// ------------------------------ init state --------------------------------
__global__ void init_state_kernel() {
    int i = blockIdx.x * blockDim.x + threadIdx.x;
    if (i < 2 * Bb * Hh) g_h0buf[i] = __float2bfloat16(0.f);
    if (i < NCTA_LSTM * 32) g_flags[i] = 0u;
    if (i < Tt) g_ready[i] = 0u;
}

// -------------- MLP weight composition (warp per output) -------------------
__global__ __launch_bounds__(256) void compose1(
    const float* __restrict__ W3, const float* __restrict__ W2,
    const float* __restrict__ b1, const float* __restrict__ b2)
{
    int w = (blockIdx.x * blockDim.x + threadIdx.x) >> 5;
    int lane = threadIdx.x & 31;
    if (w < Kc * 512) {
        int r = w / 512, c = w - r * 512;
        float s = 0.f;
        for (int k = lane; k < 1024; k += 32)
            s += W3[r * 1024 + k] * W2[k * 512 + c];
#pragma unroll
        for (int off = 16; off; off >>= 1)
            s += __shfl_xor_sync(0xffffffffu, s, off);
        if (lane == 0) g_wc1[w] = s;
    } else if (w < Kc * 512 + 1024) {
        int j = w - Kc * 512;
        float s = 0.f;
        for (int k = lane; k < 512; k += 32)
            s += W2[j * 512 + k] * b1[k];
#pragma unroll
        for (int off = 16; off; off >>= 1)
            s += __shfl_xor_sync(0xffffffffu, s, off);
        if (lane == 0) g_t1[j] = s + b2[j];
    }
}
__global__ __launch_bounds__(256) void compose2(
    const float* __restrict__ W1, const float* __restrict__ W3,
    const float* __restrict__ b3)
{
    int w = (blockIdx.x * blockDim.x + threadIdx.x) >> 5;
    int lane = threadIdx.x & 31;
    if (w < Kc * Hh) {
        int r = w / Hh, c = w - r * Hh;
        float s = 0.f;
        for (int k = lane; k < 512; k += 32)
            s += g_wc1[r * 512 + k] * W1[k * Hh + c];
#pragma unroll
        for (int off = 16; off; off >>= 1)
            s += __shfl_xor_sync(0xffffffffu, s, off);
        if (lane == 0) g_wc[w] = s;
    } else if (w < Kc * Hh + Kc) {
        int r = w - Kc * Hh;
        float s = 0.f;
        for (int k = lane; k < 1024; k += 32)
            s += W3[r * 1024 + k] * g_t1[k];
#pragma unroll
        for (int off = 16; off; off >>= 1)
            s += __shfl_xor_sync(0xffffffffu, s, off);
        if (lane == 0) g_bc[r] = s + b3[r];
    }
}

// ------------- release/acquire group barrier (24 CTAs/group) ---------------
__device__ __forceinline__ void group_barrier(int grp, int cta_in_grid,
                                              unsigned int target) {
    __syncthreads();
    if (threadIdx.x < 32) {
        if (threadIdx.x == 0)
            st_release_gpu(&g_flags[cta_in_grid * 32], target);
        if (threadIdx.x < 24) {
            const unsigned int* f = &g_flags[(grp + threadIdx.x * 4) * 32];
            while (ld_acquire_gpu(f) < target) { }
        }
    }
    __syncthreads();
}

// ---------------- producer: inline-convert tile loader ---------------------
__device__ __forceinline__ void fill_chunk_conv(
    bf16* buf, const float* __restrict__ src, int base_row, int kt,
    int lrow, int lc)
{
#pragma unroll
    for (int it = 0; it < 2; it++) {
        int row = lrow + it * 64;
        int r = base_row + row;
        int k = kt * 32 + lc * 8;
        float v[8];
        if (k + 7 < INP) {
            float4 a = *(const float4*)(src + (size_t)r * INP + k);
            float4 b = *(const float4*)(src + (size_t)r * INP + k + 4);
            v[0] = a.x; v[1] = a.y; v[2] = a.z; v[3] = a.w;
            v[4] = b.x; v[5] = b.y; v[6] = b.z; v[7] = b.w;
        } else {
#pragma unroll
            for (int i = 0; i < 8; i++)
                v[i] = (k + i < INP) ? src[(size_t)r * INP + k + i] : 0.f;
        }
        __nv_bfloat162 h0 = __floats2bfloat162_rn(v[0], v[1]);
        __nv_bfloat162 h1 = __floats2bfloat162_rn(v[2], v[3]);
        __nv_bfloat162 h2 = __floats2bfloat162_rn(v[4], v[5]);
        __nv_bfloat162 h3 = __floats2bfloat162_rn(v[6], v[7]);
        uint4 pk;
        pk.x = *(uint32_t*)&h0; pk.y = *(uint32_t*)&h1;
        pk.z = *(uint32_t*)&h2; pk.w = *(uint32_t*)&h3;
        *(uint4*)(buf + row * 40 + lc * 8) = pk;
    }
}

// ---------------- producer role: xw0 GEMM + emissions + CRF ----------------
__device__ void producer_role(bf16* dsm, const float* __restrict__ x,
                              const float* __restrict__ Wih0,
                              const float* __restrict__ bih0,
                              const float* __restrict__ bhh0,
                              const int* __restrict__ tags,
                              const float* __restrict__ start_t,
                              const float* __restrict__ end_t,
                              const float* __restrict__ trans,
                              int worker)
{
    bf16* smA = dsm;                 // 128 x 40 (one 32-k chunk)
    bf16* smB = dsm + 5120;
    const uint32_t saddrA = smem_to_u32(smA);
    const uint32_t saddrB = smem_to_u32(smB);

    const int tid = threadIdx.x;
    const int lane = tid & 31;
    const int wid = tid >> 5;
    const int wm = wid & 3;
    const int wn = wid >> 2;

    const uint32_t a_off =
        (uint32_t)(((wm * 32 + (lane & 15)) * 40 + (lane >> 4) * 8) * 2);
    uint32_t b_off[4];
#pragma unroll
    for (int jp = 0; jp < 4; jp++)
        b_off[jp] = (uint32_t)(((wn * 64 + jp * 16 + (lane & 7) + ((lane >> 4) << 3)) * 40
                                + ((lane >> 3) & 1) * 8) * 2);
    const int lrow = tid >> 2;
    const int lc   = tid & 3;

    // ---- phase 1: xw0 GEMM tiles (inline fp32->bf16; PERMUTED output)
    for (int id = worker; id < NTILES; id += NCTA_GEMM) {
        const int t2 = id / 12;
        const int nb = id - t2 * 12;
        const int m0 = t2 * 128;
        const int n0 = nb * 128;
        const int gate = nb / 3;            // tile lies inside one gate block

        float acc[2][8][4];
#pragma unroll
        for (int i = 0; i < 2; i++)
#pragma unroll
            for (int j = 0; j < 8; j++)
#pragma unroll
                for (int q = 0; q < 4; q++) acc[i][j][q] = 0.f;

        for (int kt = 0; kt < 4; kt++) {
            fill_chunk_conv(smA, x,    m0, kt, lrow, lc);
            fill_chunk_conv(smB, Wih0, n0, kt, lrow, lc);
            __syncthreads();
#pragma unroll
            for (int kk = 0; kk < 2; kk++) {
                uint32_t a[2][4], b[4][4];
                ldsm4(a[0], saddrA + a_off + kk * 32);
                ldsm4(a[1], saddrA + a_off + 1280 + kk * 32);
#pragma unroll
                for (int jp = 0; jp < 4; jp++)
                    ldsm4(b[jp], saddrB + b_off[jp] + kk * 32);
#pragma unroll
                for (int mt = 0; mt < 2; mt++)
#pragma unroll
                    for (int j = 0; j < 8; j++)
                        mma_bf16(acc[mt][j], a[mt], &b[j >> 1][(j & 1) * 2]);
            }
            __syncthreads();
        }

#pragma unroll
        for (int mt = 0; mt < 2; mt++)
#pragma unroll
            for (int j = 0; j < 8; j++)
#pragma unroll
                for (int p = 0; p < 2; p++) {
                    int row = m0 + wm * 32 + mt * 16 + (lane >> 2) + p * 8;
                    int col = n0 + wn * 64 + j * 8 + (lane & 3) * 2;
                    int hc  = col - gate * Hh;
                    float v0 = acc[mt][j][p * 2]     + bih0[col]     + bhh0[col];
                    float v1 = acc[mt][j][p * 2 + 1] + bih0[col + 1] + bhh0[col + 1];
                    // permuted: [row][hc/2][gate*2 + q]
                    size_t dst = ((size_t)row * 192 + (hc >> 1)) * 8 + gate * 2;
                    *(__nv_bfloat162*)(g_xwb + dst) = __floats2bfloat162_rn(v0, v1);
                }

        __threadfence();
        __syncthreads();
        if (tid == 0) red_release_gpu(&g_ready[t2 >> 1], 1u);
    }

    // ---- phase 2+3: emissions + CRF per timestep, trailing the frontier
    for (int tau = worker; tau < Tt; tau += NCTA_GEMM) {
        // gate: h1(tau) stored in interval tau+1, published at target tau+2
        if (tid < NCTA_LSTM) {
            while (ld_acquire_gpu(&g_flags[tid * 32]) < (unsigned int)(tau + 2)) { }
        }
        __syncthreads();

        for (int rr = wid; rr < Bb; rr += 8) {
            int row = tau * Bb + rr;
            float acc[Kc];
#pragma unroll
            for (int j = 0; j < Kc; j++) acc[j] = 0.f;
            const __nv_bfloat162* ar =
                (const __nv_bfloat162*)(g_h1b + (size_t)row * Hh);
#pragma unroll
            for (int it = 0; it < 6; it++) {
                int k2 = lane + it * 32;
                float2 a = __bfloat1622float2(ar[k2]);
#pragma unroll
                for (int j = 0; j < Kc; j++)
                    acc[j] += a.x * g_wc[j * Hh + 2 * k2]
                            + a.y * g_wc[j * Hh + 2 * k2 + 1];
            }
#pragma unroll
            for (int j = 0; j < Kc; j++) {
#pragma unroll
                for (int off = 16; off; off >>= 1)
                    acc[j] += __shfl_xor_sync(0xffffffffu, acc[j], off);
            }
            if (lane == 0) {
#pragma unroll
                for (int j = 0; j < Kc; j++)
                    g_em[(size_t)row * Kc + j] = acc[j] + g_bc[j];
            }
        }
        __syncthreads();   // em rows of tau visible CTA-wide

        // ---- CRF for sequence tau (warp 0)
        if (wid == 0) {
            const float NEG = -1e30f;
            const float* em = g_em;
            float tr[Kc];
            int cl = (lane < Kc) ? lane : 0;
#pragma unroll
            for (int i = 0; i < Kc; i++) tr[i] = trans[i * Kc + cl];

            float a = (lane < Kc)
                ? (start_t[lane] + em[((size_t)tau * Tt) * Kc + lane]) : NEG;
            for (int tp = 1; tp < Tt; tp++) {
                float e = (lane < Kc) ? em[((size_t)tau * Tt + tp) * Kc + lane] : 0.f;
                float v[Kc];
                float m = NEG;
#pragma unroll
                for (int i = 0; i < Kc; i++) {
                    float ai = __shfl_sync(0xffffffffu, a, i);
                    v[i] = ai + tr[i];
                    m = fmaxf(m, v[i]);
                }
                float s = 0.f;
#pragma unroll
                for (int i = 0; i < Kc; i++) s += __expf(v[i] - m);
                float an = m + __logf(s) + e;
                a = (lane < Kc) ? an : NEG;
            }
            float z = (lane < Kc) ? (a + end_t[lane]) : NEG;
            float zmax = z;
#pragma unroll
            for (int off = 16; off; off >>= 1)
                zmax = fmaxf(zmax, __shfl_xor_sync(0xffffffffu, zmax, off));
            float zs = (lane < Kc) ? __expf(z - zmax) : 0.f;
#pragma unroll
            for (int off = 16; off; off >>= 1)
                zs += __shfl_xor_sync(0xffffffffu, zs, off);
            float logZ = zmax + __logf(zs);

            if (lane == 0) {
                int prev = tags[(size_t)tau * Tt];
                float score = start_t[prev] + em[((size_t)tau * Tt) * Kc + prev];
                for (int tp = 1; tp < Tt; tp++) {
                    int tg = tags[(size_t)tau * Tt + tp];
                    score += trans[prev * Kc + tg]
                           + em[((size_t)tau * Tt + tp) * Kc + tg];
                    prev = tg;
                }
                score += end_t[prev];
                g_partial[tau] = logZ - score;
            }
        }
        __syncthreads();
    }
}

// ================== fused 2-layer persistent LSTM + producer ===============
__global__ __launch_bounds__(256) void lstm_fused(
    const float* __restrict__ Whh0, const float* __restrict__ Wih1,
    const float* __restrict__ Whh1, const float* __restrict__ bih1,
    const float* __restrict__ bhh1, const float* __restrict__ bih0,
    const float* __restrict__ bhh0, const float* __restrict__ x,
    const float* __restrict__ Wih0, const int* __restrict__ tags,
    const float* __restrict__ start_t, const float* __restrict__ end_t,
    const float* __restrict__ trans)
{
    extern __shared__ bf16 dsm[];

    if (blockIdx.x >= NCTA_LSTM) {
        producer_role(dsm, x, Wih0, bih0, bhh0, tags, start_t, end_t, trans,
                      blockIdx.x - NCTA_LSTM);
        return;
    }

    bf16* W0sm  = dsm;                    // Whh0 slice  (64n x 392)
    bf16* Wi1sm = dsm + 64 * 392;         // Wih1 slice
    bf16* W1sm  = dsm + 2 * 64 * 392;     // Whh1 slice
    bf16* Asm   = dsm + 3 * 64 * 392;     // A0 tile (64 x 392)
    bf16* A1sm  = dsm + 4 * 64 * 392;     // h1 k-tiles 0..11 (64 x 200)
    const uint32_t w0base  = smem_to_u32(W0sm);
    const uint32_t wi1base = smem_to_u32(Wi1sm);
    const uint32_t w1base  = smem_to_u32(W1sm);
    const uint32_t abase   = smem_to_u32(Asm);
    const uint32_t a1base  = smem_to_u32(A1sm);

    const int tid = threadIdx.x;
    const int lane = tid & 31;
    const int wid = tid >> 5;
    const int wm = wid & 3;              // 16-row m tile
    const int wn = wid >> 2;             // h-col half (0/1)
    const int bx = blockIdx.x & 3;
    const int by = blockIdx.x >> 2;
    const int b0 = bx * 64;
    const int c0 = by * 16;

    for (int idx = tid; idx < 64 * 384; idx += 256) {
        int n = idx / 384, k = idx - n * 384;
        int g = n >> 4, hc = n & 15;
        size_t grow = (size_t)(g * Hh + c0 + hc) * Hh + k;
        int d = n * 392 + k;
        W0sm[d]  = __float2bfloat16(Whh0[grow]);
        Wi1sm[d] = __float2bfloat16(Wih1[grow]);
        W1sm[d]  = __float2bfloat16(Whh1[grow]);
    }

    const uint32_t a_off =
        (uint32_t)(((wm * 16 + (lane & 15)) * 392 + (lane >> 4) * 8) * 2);
    const uint32_t a1_off =
        (uint32_t)(((wm * 16 + (lane & 15)) * 200 + (lane >> 4) * 8) * 2);
    const uint32_t b_k = ((lane >> 3) & 1) * 8;
    const uint32_t b_off0 =
        (uint32_t)((((0 + (lane >> 4)) * 16 + wn * 8 + (lane & 7)) * 392 + b_k) * 2);
    const uint32_t b_off1 =
        (uint32_t)((((2 + (lane >> 4)) * 16 + wn * 8 + (lane & 7)) * 392 + b_k) * 2);

    const int prow = lane >> 2;
    const int pcol = (lane & 3) * 2;
    const int colg = c0 + wn * 8 + pcol;

    float bi1[4][2];
#pragma unroll
    for (int g = 0; g < 4; g++)
#pragma unroll
        for (int q = 0; q < 2; q++)
            bi1[g][q] = bih1[g * Hh + colg + q] + bhh1[g * Hh + colg + q];

    float cst0[4], cst1[4];
#pragma unroll
    for (int i = 0; i < 4; i++) { cst0[i] = 0.f; cst1[i] = 0.f; }

    for (int t = 0; t <= Tt; t++) {
        const int ph = t & 1;
        const bool doL0 = (t < Tt);
        const bool doL1 = (t >= 1);
        const bool doW  = (t >= 2);     // Whh1 pass (h1(t-2) exists)

        // ---- issue A0 <- h0(t-1); A1 <- h1(t-2) k-tiles 0..11 (from g_h1b)
        {
            const bf16* hprev0 = g_h0buf + (size_t)ph * Bb * Hh;
#pragma unroll
            for (int it = 0; it < 12; it++) {
                int idx = tid + it * 256;
                int row = idx / 48, c = idx - row * 48;
                CP_ASYNC16(abase + (uint32_t)((row * 392 + c * 8) * 2),
                           hprev0 + (size_t)(b0 + row) * Hh + c * 8);
            }
            CP_COMMIT();
        }
        if (doW) {
            const bf16* hprev1 = g_h1b + (size_t)(t - 2) * Bb * Hh;
#pragma unroll
            for (int it = 0; it < 6; it++) {
                int idx = tid + it * 256;
                int row = idx / 24, c = idx - row * 24;
                CP_ASYNC16(a1base + (uint32_t)(row * 400 + c * 16),
                           hprev1 + (size_t)(b0 + row) * Hh + c * 8);
            }
            CP_COMMIT();
        }

        // ---- gate on producer-published xw(t)
        if (doL0) {
            if (tid == 0) {
                while (ld_acquire_gpu(&g_ready[t]) < 24u) { }
            }
        }
        __syncthreads();

        // ---- xw(t) fragments: ONE uint4 per row (permuted layout)
        float2 xv[4][2];
        if (doL0) {
#pragma unroll
            for (int p = 0; p < 2; p++) {
                int brow = b0 + wm * 16 + prow + p * 8;
                uint4 pk = *(const uint4*)(g_xwb +
                    (((size_t)t * Bb + brow) * 192 + (colg >> 1)) * 8);
                xv[0][p] = __bfloat1622float2(*(__nv_bfloat162*)&pk.x);
                xv[1][p] = __bfloat1622float2(*(__nv_bfloat162*)&pk.y);
                xv[2][p] = __bfloat1622float2(*(__nv_bfloat162*)&pk.z);
                xv[3][p] = __bfloat1622float2(*(__nv_bfloat162*)&pk.w);
            }
        }

        if (doW) CP_WAIT1(); else CP_WAIT0();
        __syncthreads();

        float accL0[4][4], accL1[4][4];
#pragma unroll
        for (int j = 0; j < 4; j++)
#pragma unroll
            for (int q = 0; q < 4; q++) { accL0[j][q] = 0.f; accL1[j][q] = 0.f; }

#pragma unroll 4
        for (int kt = 0; kt < 24; kt++) {
            uint32_t koff = (uint32_t)(kt * 32);
            uint32_t a[4], p0[4], p1[4], q0[4], q1[4];
            ldsm4(a, abase + a_off + koff);
            ldsm4(p0, w0base + b_off0 + koff);
            ldsm4(p1, w0base + b_off1 + koff);
            ldsm4(q0, wi1base + b_off0 + koff);
            ldsm4(q1, wi1base + b_off1 + koff);
            mma_bf16(accL0[0], a, &p0[0]);
            mma_bf16(accL1[0], a, &q0[0]);
            mma_bf16(accL0[1], a, &p0[2]);
            mma_bf16(accL1[1], a, &q0[2]);
            mma_bf16(accL0[2], a, &p1[0]);
            mma_bf16(accL1[2], a, &q1[0]);
            mma_bf16(accL0[3], a, &p1[2]);
            mma_bf16(accL1[3], a, &q1[2]);
        }
        __syncthreads();

        if (doW) {
            const bf16* hprev1 = g_h1b + (size_t)(t - 2) * Bb * Hh;
#pragma unroll
            for (int it = 0; it < 6; it++) {
                int idx = tid + it * 256;
                int row = idx / 24, c = idx - row * 24;
                CP_ASYNC16(abase + (uint32_t)(row * 784 + 384 + c * 16),
                           hprev1 + (size_t)(b0 + row) * Hh + 192 + c * 8);
            }
            CP_COMMIT();
        }

        if (doL0) {
            bf16* hnext0 = g_h0buf + (size_t)(ph ^ 1) * Bb * Hh;
#pragma unroll
            for (int p = 0; p < 2; p++) {
                int brow = b0 + wm * 16 + prow + p * 8;
                float hnv[2];
#pragma unroll
                for (int q = 0; q < 2; q++) {
                    float xi = q ? xv[0][p].y : xv[0][p].x;
                    float xf = q ? xv[1][p].y : xv[1][p].x;
                    float xg = q ? xv[2][p].y : xv[2][p].x;
                    float xo = q ? xv[3][p].y : xv[3][p].x;
                    float i_ = sig_ap(accL0[0][p * 2 + q] + xi);
                    float f_ = sig_ap(accL0[1][p * 2 + q] + xf);
                    float g_ = tanh_ap(accL0[2][p * 2 + q] + xg);
                    float o_ = sig_ap(accL0[3][p * 2 + q] + xo);
                    float cn = f_ * cst0[p * 2 + q] + i_ * g_;
                    cst0[p * 2 + q] = cn;
                    hnv[q] = o_ * tanh_ap(cn);
                }
                *(__nv_bfloat162*)(hnext0 + (size_t)brow * Hh + colg) =
                    __floats2bfloat162_rn(hnv[0], hnv[1]);
            }
        }

        if (doL1) {
            if (doW) {
                CP_WAIT1();
                __syncthreads();
#pragma unroll 4
                for (int kt = 0; kt < 12; kt++) {
                    uint32_t koff = (uint32_t)(kt * 32);
                    uint32_t a[4], b0v[4], b1v[4];
                    ldsm4(a, a1base + a1_off + koff);
                    ldsm4(b0v, w1base + b_off0 + koff);
                    ldsm4(b1v, w1base + b_off1 + koff);
                    mma_bf16(accL1[0], a, &b0v[0]);
                    mma_bf16(accL1[1], a, &b0v[2]);
                    mma_bf16(accL1[2], a, &b1v[0]);
                    mma_bf16(accL1[3], a, &b1v[2]);
                }
                CP_WAIT0();
                __syncthreads();
#pragma unroll 4
                for (int kt = 12; kt < 24; kt++) {
                    uint32_t koff = (uint32_t)(kt * 32);
                    uint32_t a[4], b0v[4], b1v[4];
                    ldsm4(a, abase + a_off + koff);
                    ldsm4(b0v, w1base + b_off0 + koff);
                    ldsm4(b1v, w1base + b_off1 + koff);
                    mma_bf16(accL1[0], a, &b0v[0]);
                    mma_bf16(accL1[1], a, &b0v[2]);
                    mma_bf16(accL1[2], a, &b1v[0]);
                    mma_bf16(accL1[3], a, &b1v[2]);
                }
            }

            bf16* houtp = g_h1b + (size_t)(t - 1) * Bb * Hh;
#pragma unroll
            for (int p = 0; p < 2; p++) {
                int brow = b0 + wm * 16 + prow + p * 8;
                float hnv[2];
#pragma unroll
                for (int q = 0; q < 2; q++) {
                    float i_ = sig_ap(accL1[0][p * 2 + q] + bi1[0][q]);
                    float f_ = sig_ap(accL1[1][p * 2 + q] + bi1[1][q]);
                    float g_ = tanh_ap(accL1[2][p * 2 + q] + bi1[2][q]);
                    float o_ = sig_ap(accL1[3][p * 2 + q] + bi1[3][q]);
                    float cn = f_ * cst1[p * 2 + q] + i_ * g_;
                    cst1[p * 2 + q] = cn;
                    hnv[q] = o_ * tanh_ap(cn);
                }
                *(__nv_bfloat162*)(houtp + (size_t)brow * Hh + colg) =
                    __floats2bfloat162_rn(hnv[0], hnv[1]);
            }
        }

        group_barrier(bx, blockIdx.x, (unsigned int)(t + 1));
    }
}

// ------------------------------ reduce -------------------------------------
__global__ __launch_bounds__(256) void reduce_kernel(float* __restrict__ out)
{
    __shared__ float sh[256];
    int i = threadIdx.x;
    sh[i] = g_partial[i];
    __syncthreads();
#pragma unroll
    for (int s = 128; s; s >>= 1) {
        if (i < s) sh[i] += sh[i + s];
        __syncthreads();
    }
    if (i == 0) out[0] = sh[0];
}

// ------------------------------ launch -------------------------------------
extern "C" void kernel_launch(void* const* d_in, const int* in_sizes, int n_in,
                              void* d_out, int out_size)
{
    (void)in_sizes; (void)n_in; (void)out_size;
    const float* x    = (const float*)d_in[0];
    const int*   tags = (const int*)d_in[2];
    const float* Wih0 = (const float*)d_in[3];
    const float* Whh0 = (const float*)d_in[4];
    const float* bih0 = (const float*)d_in[5];
    const float* bhh0 = (const float*)d_in[6];
    const float* Wih1 = (const float*)d_in[7];
    const float* Whh1 = (const float*)d_in[8];
    const float* bih1 = (const float*)d_in[9];
    const float* bhh1 = (const float*)d_in[10];
    const float* W1   = (const float*)d_in[11];
    const float* b1   = (const float*)d_in[12];
    const float* W2   = (const float*)d_in[13];
    const float* b2   = (const float*)d_in[14];
    const float* W3   = (const float*)d_in[15];
    const float* b3   = (const float*)d_in[16];
    const float* st   = (const float*)d_in[17];
    const float* et   = (const float*)d_in[18];
    const float* trn  = (const float*)d_in[19];

    const size_t LSTM_SMEM = (size_t)(4 * 64 * 392 + 64 * 200) * sizeof(bf16);
    cudaFuncSetAttribute(lstm_fused, cudaFuncAttributeMaxDynamicSharedMemorySize,
                         (int)LSTM_SMEM);

    init_state_kernel<<<(2 * Bb * Hh + 255) / 256, 256>>>();                  // 0
    compose1<<<((Kc * 512 + 1024) * 32 + 255) / 256, 256>>>(W3, W2, b1, b2);  // 1
    compose2<<<((Kc * Hh + Kc) * 32 + 255) / 256, 256>>>(W1, W3, b3);         // 2

    // fused: 96 LSTM CTAs + 52 producer CTAs (xw0 GEMM -> emissions -> CRF)
    lstm_fused<<<NCTA_LSTM + NCTA_GEMM, 256, LSTM_SMEM>>>(                    // 3
        Whh0, Wih1, Whh1, bih1, bhh1, bih0, bhh0, x, Wih0, tags, st, et, trn);

    reduce_kernel<<<1, 256>>>((float*)d_out);                                 // 4
}

// round 15
// speedup vs baseline: 1.4690x; 1.0006x over previous
#include <cuda_runtime.h>
#include <cuda_bf16.h>
#include <cstdint>
#include <cstddef>

// ---------------------------------------------------------------------------
// BiLSTM-NER, Round 14 (R13 base, proven 2181us):
//  * phase B reordered: [issue h1-upper] -> [12kt on A1] -> [L0 pointwise]
//    -> [wait + 12kt on upper] -> [L1 pointwise]; the upper load now hides
//    under the first Whh1 chunk + pointwise instead of being exposed.
//  * producer flag polling uses __nanosleep backoff so 52x96 spinning
//    threads stop hammering the barrier flag lines during the em/CRF phase.
// ---------------------------------------------------------------------------

#define Tt 256
#define Bb 256
#define Hh 384
#define G4 1536   // 4*H
#define INP 100
#define Kc 10
#define NCTA_LSTM 96
#define NCTA_GEMM 52
#define NTILES (512 * 12)   // (M/128) * (G4/128)

typedef __nv_bfloat16 bf16;

// ============================ PTX helpers ==================================
__device__ __forceinline__ uint32_t smem_to_u32(const void* p) {
    uint32_t a;
    asm("{ .reg .u64 t; cvta.to.shared.u64 t, %1; cvt.u32.u64 %0, t; }"
        : "=r"(a) : "l"(p));
    return a;
}
__device__ __forceinline__ void ldsm4(uint32_t* r, uint32_t saddr) {
    asm volatile("ldmatrix.sync.aligned.m8n8.x4.shared.b16 {%0,%1,%2,%3}, [%4];"
        : "=r"(r[0]), "=r"(r[1]), "=r"(r[2]), "=r"(r[3]) : "r"(saddr));
}
__device__ __forceinline__ void mma_bf16(float* c, const uint32_t* a, const uint32_t* b) {
    asm volatile(
        "mma.sync.aligned.m16n8k16.row.col.f32.bf16.bf16.f32 "
        "{%0,%1,%2,%3}, {%4,%5,%6,%7}, {%8,%9}, {%0,%1,%2,%3};"
        : "+f"(c[0]), "+f"(c[1]), "+f"(c[2]), "+f"(c[3])
        : "r"(a[0]), "r"(a[1]), "r"(a[2]), "r"(a[3]), "r"(b[0]), "r"(b[1]));
}
#define CP_ASYNC16(sa, ga) \
    asm volatile("cp.async.cg.shared.global [%0], [%1], 16;" \
                 :: "r"(sa), "l"(ga) : "memory")
#define CP_COMMIT() asm volatile("cp.async.commit_group;" ::: "memory")
#define CP_WAIT0()  asm volatile("cp.async.wait_group 0;" ::: "memory")
#define CP_WAIT1()  asm volatile("cp.async.wait_group 1;" ::: "memory")

__device__ __forceinline__ float tanh_ap(float x) {
    float y; asm("tanh.approx.f32 %0, %1;" : "=f"(y) : "f"(x)); return y;
}
__device__ __forceinline__ float sig_ap(float x) {
    return fmaf(tanh_ap(0.5f * x), 0.5f, 0.5f);
}
__device__ __forceinline__ void st_release_gpu(unsigned int* p, unsigned int v) {
    asm volatile("st.global.release.gpu.b32 [%0], %1;" :: "l"(p), "r"(v) : "memory");
}
__device__ __forceinline__ unsigned int ld_acquire_gpu(const unsigned int* p) {
    unsigned int v;
    asm volatile("ld.global.acquire.gpu.b32 %0, [%1];" : "=r"(v) : "l"(p) : "memory");
    return v;
}
__device__ __forceinline__ void red_release_gpu(unsigned int* p, unsigned int v) {
    asm volatile("red.release.gpu.global.add.u32 [%0], %1;" :: "l"(p), "r"(v) : "memory");
}
__device__ __forceinline__ void nsleep(unsigned int ns) {
    asm volatile("nanosleep.u32 %0;" :: "r"(ns));
}

// ------------------------- scratch (device globals) ------------------------
// xw permuted: xwP[((t*256+row)*192 + hc/2)*8 + gate*2 + q]  (bf16)
__device__ bf16  g_xwb[(size_t)Tt * Bb * G4];
__device__ bf16  g_h1b[(size_t)Tt * Bb * Hh];      // layer1 outputs (history)
__device__ float g_em[(size_t)Tt * Bb * Kc];       // emissions (fp32)
__device__ float g_wc1[Kc * 512];                  // W3 @ W2  (10 x 512)
__device__ float g_wc[Kc * Hh];                    // W3@W2@W1 (10 x 384)
__device__ float g_t1[1024];                       // W2 @ b1 + b2
__device__ float g_bc[Kc];                         // composed bias
__device__ bf16  g_h0buf[2 * Bb * Hh];             // recurrent h0 state (bf16)
__device__ float g_partial[Bb];

__device__ unsigned int g_flags[NCTA_LSTM * 32];   // one per CTA, own 128B line
__device__ unsigned int g_ready[Tt];               // xw tiles ready (24/step)

// ------------------------------ init state --------------------------------
__global__ void init_state_kernel() {
    int i = blockIdx.x * blockDim.x + threadIdx.x;
    if (i < 2 * Bb * Hh) g_h0buf[i] = __float2bfloat16(0.f);
    if (i < NCTA_LSTM * 32) g_flags[i] = 0u;
    if (i < Tt) g_ready[i] = 0u;
}

// -------------- MLP weight composition (warp per output) -------------------
__global__ __launch_bounds__(256) void compose1(
    const float* __restrict__ W3, const float* __restrict__ W2,
    const float* __restrict__ b1, const float* __restrict__ b2)
{
    int w = (blockIdx.x * blockDim.x + threadIdx.x) >> 5;
    int lane = threadIdx.x & 31;
    if (w < Kc * 512) {
        int r = w / 512, c = w - r * 512;
        float s = 0.f;
        for (int k = lane; k < 1024; k += 32)
            s += W3[r * 1024 + k] * W2[k * 512 + c];
#pragma unroll
        for (int off = 16; off; off >>= 1)
            s += __shfl_xor_sync(0xffffffffu, s, off);
        if (lane == 0) g_wc1[w] = s;
    } else if (w < Kc * 512 + 1024) {
        int j = w - Kc * 512;
        float s = 0.f;
        for (int k = lane; k < 512; k += 32)
            s += W2[j * 512 + k] * b1[k];
#pragma unroll
        for (int off = 16; off; off >>= 1)
            s += __shfl_xor_sync(0xffffffffu, s, off);
        if (lane == 0) g_t1[j] = s + b2[j];
    }
}
__global__ __launch_bounds__(256) void compose2(
    const float* __restrict__ W1, const float* __restrict__ W3,
    const float* __restrict__ b3)
{
    int w = (blockIdx.x * blockDim.x + threadIdx.x) >> 5;
    int lane = threadIdx.x & 31;
    if (w < Kc * Hh) {
        int r = w / Hh, c = w - r * Hh;
        float s = 0.f;
        for (int k = lane; k < 512; k += 32)
            s += g_wc1[r * 512 + k] * W1[k * Hh + c];
#pragma unroll
        for (int off = 16; off; off >>= 1)
            s += __shfl_xor_sync(0xffffffffu, s, off);
        if (lane == 0) g_wc[w] = s;
    } else if (w < Kc * Hh + Kc) {
        int r = w - Kc * Hh;
        float s = 0.f;
        for (int k = lane; k < 1024; k += 32)
            s += W3[r * 1024 + k] * g_t1[k];
#pragma unroll
        for (int off = 16; off; off >>= 1)
            s += __shfl_xor_sync(0xffffffffu, s, off);
        if (lane == 0) g_bc[r] = s + b3[r];
    }
}

// ------------- release/acquire group barrier (24 CTAs/group) ---------------
__device__ __forceinline__ void group_barrier(int grp, int cta_in_grid,
                                              unsigned int target) {
    __syncthreads();
    if (threadIdx.x < 32) {
        if (threadIdx.x == 0)
            st_release_gpu(&g_flags[cta_in_grid * 32], target);
        if (threadIdx.x < 24) {
            const unsigned int* f = &g_flags[(grp + threadIdx.x * 4) * 32];
            while (ld_acquire_gpu(f) < target) { }
        }
    }
    __syncthreads();
}

// ---------------- producer: inline-convert tile loader ---------------------
__device__ __forceinline__ void fill_chunk_conv(
    bf16* buf, const float* __restrict__ src, int base_row, int kt,
    int lrow, int lc)
{
#pragma unroll
    for (int it = 0; it < 2; it++) {
        int row = lrow + it * 64;
        int r = base_row + row;
        int k = kt * 32 + lc * 8;
        float v[8];
        if (k + 7 < INP) {
            float4 a = *(const float4*)(src + (size_t)r * INP + k);
            float4 b = *(const float4*)(src + (size_t)r * INP + k + 4);
            v[0] = a.x; v[1] = a.y; v[2] = a.z; v[3] = a.w;
            v[4] = b.x; v[5] = b.y; v[6] = b.z; v[7] = b.w;
        } else {
#pragma unroll
            for (int i = 0; i < 8; i++)
                v[i] = (k + i < INP) ? src[(size_t)r * INP + k + i] : 0.f;
        }
        __nv_bfloat162 h0 = __floats2bfloat162_rn(v[0], v[1]);
        __nv_bfloat162 h1 = __floats2bfloat162_rn(v[2], v[3]);
        __nv_bfloat162 h2 = __floats2bfloat162_rn(v[4], v[5]);
        __nv_bfloat162 h3 = __floats2bfloat162_rn(v[6], v[7]);
        uint4 pk;
        pk.x = *(uint32_t*)&h0; pk.y = *(uint32_t*)&h1;
        pk.z = *(uint32_t*)&h2; pk.w = *(uint32_t*)&h3;
        *(uint4*)(buf + row * 40 + lc * 8) = pk;
    }
}

// ---------------- producer role: xw0 GEMM + emissions + CRF ----------------
__device__ void producer_role(bf16* dsm, const float* __restrict__ x,
                              const float* __restrict__ Wih0,
                              const float* __restrict__ bih0,
                              const float* __restrict__ bhh0,
                              const int* __restrict__ tags,
                              const float* __restrict__ start_t,
                              const float* __restrict__ end_t,
                              const float* __restrict__ trans,
                              int worker)
{
    bf16* smA = dsm;                 // 128 x 40 (one 32-k chunk)
    bf16* smB = dsm + 5120;
    const uint32_t saddrA = smem_to_u32(smA);
    const uint32_t saddrB = smem_to_u32(smB);

    const int tid = threadIdx.x;
    const int lane = tid & 31;
    const int wid = tid >> 5;
    const int wm = wid & 3;
    const int wn = wid >> 2;

    const uint32_t a_off =
        (uint32_t)(((wm * 32 + (lane & 15)) * 40 + (lane >> 4) * 8) * 2);
    uint32_t b_off[4];
#pragma unroll
    for (int jp = 0; jp < 4; jp++)
        b_off[jp] = (uint32_t)(((wn * 64 + jp * 16 + (lane & 7) + ((lane >> 4) << 3)) * 40
                                + ((lane >> 3) & 1) * 8) * 2);
    const int lrow = tid >> 2;
    const int lc   = tid & 3;

    // ---- phase 1: xw0 GEMM tiles (inline fp32->bf16; PERMUTED output)
    for (int id = worker; id < NTILES; id += NCTA_GEMM) {
        const int t2 = id / 12;
        const int nb = id - t2 * 12;
        const int m0 = t2 * 128;
        const int n0 = nb * 128;
        const int gate = nb / 3;            // tile lies inside one gate block

        float acc[2][8][4];
#pragma unroll
        for (int i = 0; i < 2; i++)
#pragma unroll
            for (int j = 0; j < 8; j++)
#pragma unroll
                for (int q = 0; q < 4; q++) acc[i][j][q] = 0.f;

        for (int kt = 0; kt < 4; kt++) {
            fill_chunk_conv(smA, x,    m0, kt, lrow, lc);
            fill_chunk_conv(smB, Wih0, n0, kt, lrow, lc);
            __syncthreads();
#pragma unroll
            for (int kk = 0; kk < 2; kk++) {
                uint32_t a[2][4], b[4][4];
                ldsm4(a[0], saddrA + a_off + kk * 32);
                ldsm4(a[1], saddrA + a_off + 1280 + kk * 32);
#pragma unroll
                for (int jp = 0; jp < 4; jp++)
                    ldsm4(b[jp], saddrB + b_off[jp] + kk * 32);
#pragma unroll
                for (int mt = 0; mt < 2; mt++)
#pragma unroll
                    for (int j = 0; j < 8; j++)
                        mma_bf16(acc[mt][j], a[mt], &b[j >> 1][(j & 1) * 2]);
            }
            __syncthreads();
        }

#pragma unroll
        for (int mt = 0; mt < 2; mt++)
#pragma unroll
            for (int j = 0; j < 8; j++)
#pragma unroll
                for (int p = 0; p < 2; p++) {
                    int row = m0 + wm * 32 + mt * 16 + (lane >> 2) + p * 8;
                    int col = n0 + wn * 64 + j * 8 + (lane & 3) * 2;
                    int hc  = col - gate * Hh;
                    float v0 = acc[mt][j][p * 2]     + bih0[col]     + bhh0[col];
                    float v1 = acc[mt][j][p * 2 + 1] + bih0[col + 1] + bhh0[col + 1];
                    size_t dst = ((size_t)row * 192 + (hc >> 1)) * 8 + gate * 2;
                    *(__nv_bfloat162*)(g_xwb + dst) = __floats2bfloat162_rn(v0, v1);
                }

        __threadfence();
        __syncthreads();
        if (tid == 0) red_release_gpu(&g_ready[t2 >> 1], 1u);
    }

    // ---- phase 2+3: emissions + CRF per timestep, trailing the frontier
    for (int tau = worker; tau < Tt; tau += NCTA_GEMM) {
        // gate: h1(tau) stored in interval tau+1, published at target tau+2.
        // nanosleep backoff: keep these 52x96 pollers off the barrier lines.
        if (tid < NCTA_LSTM) {
            while (ld_acquire_gpu(&g_flags[tid * 32]) < (unsigned int)(tau + 2))
                nsleep(256);
        }
        __syncthreads();

        for (int rr = wid; rr < Bb; rr += 8) {
            int row = tau * Bb + rr;
            float acc[Kc];
#pragma unroll
            for (int j = 0; j < Kc; j++) acc[j] = 0.f;
            const __nv_bfloat162* ar =
                (const __nv_bfloat162*)(g_h1b + (size_t)row * Hh);
#pragma unroll
            for (int it = 0; it < 6; it++) {
                int k2 = lane + it * 32;
                float2 a = __bfloat1622float2(ar[k2]);
#pragma unroll
                for (int j = 0; j < Kc; j++)
                    acc[j] += a.x * g_wc[j * Hh + 2 * k2]
                            + a.y * g_wc[j * Hh + 2 * k2 + 1];
            }
#pragma unroll
            for (int j = 0; j < Kc; j++) {
#pragma unroll
                for (int off = 16; off; off >>= 1)
                    acc[j] += __shfl_xor_sync(0xffffffffu, acc[j], off);
            }
            if (lane == 0) {
#pragma unroll
                for (int j = 0; j < Kc; j++)
                    g_em[(size_t)row * Kc + j] = acc[j] + g_bc[j];
            }
        }
        __syncthreads();   // em rows of tau visible CTA-wide

        // ---- CRF for sequence tau (warp 0)
        if (wid == 0) {
            const float NEG = -1e30f;
            const float* em = g_em;
            float tr[Kc];
            int cl = (lane < Kc) ? lane : 0;
#pragma unroll
            for (int i = 0; i < Kc; i++) tr[i] = trans[i * Kc + cl];

            float a = (lane < Kc)
                ? (start_t[lane] + em[((size_t)tau * Tt) * Kc + lane]) : NEG;
            for (int tp = 1; tp < Tt; tp++) {
                float e = (lane < Kc) ? em[((size_t)tau * Tt + tp) * Kc + lane] : 0.f;
                float v[Kc];
                float m = NEG;
#pragma unroll
                for (int i = 0; i < Kc; i++) {
                    float ai = __shfl_sync(0xffffffffu, a, i);
                    v[i] = ai + tr[i];
                    m = fmaxf(m, v[i]);
                }
                float s = 0.f;
#pragma unroll
                for (int i = 0; i < Kc; i++) s += __expf(v[i] - m);
                float an = m + __logf(s) + e;
                a = (lane < Kc) ? an : NEG;
            }
            float z = (lane < Kc) ? (a + end_t[lane]) : NEG;
            float zmax = z;
#pragma unroll
            for (int off = 16; off; off >>= 1)
                zmax = fmaxf(zmax, __shfl_xor_sync(0xffffffffu, zmax, off));
            float zs = (lane < Kc) ? __expf(z - zmax) : 0.f;
#pragma unroll
            for (int off = 16; off; off >>= 1)
                zs += __shfl_xor_sync(0xffffffffu, zs, off);
            float logZ = zmax + __logf(zs);

            if (lane == 0) {
                int prev = tags[(size_t)tau * Tt];
                float score = start_t[prev] + em[((size_t)tau * Tt) * Kc + prev];
                for (int tp = 1; tp < Tt; tp++) {
                    int tg = tags[(size_t)tau * Tt + tp];
                    score += trans[prev * Kc + tg]
                           + em[((size_t)tau * Tt + tp) * Kc + tg];
                    prev = tg;
                }
                score += end_t[prev];
                g_partial[tau] = logZ - score;
            }
        }
        __syncthreads();
    }
}

// ================== fused 2-layer persistent LSTM + producer ===============
__global__ __launch_bounds__(256) void lstm_fused(
    const float* __restrict__ Whh0, const float* __restrict__ Wih1,
    const float* __restrict__ Whh1, const float* __restrict__ bih1,
    const float* __restrict__ bhh1, const float* __restrict__ bih0,
    const float* __restrict__ bhh0, const float* __restrict__ x,
    const float* __restrict__ Wih0, const int* __restrict__ tags,
    const float* __restrict__ start_t, const float* __restrict__ end_t,
    const float* __restrict__ trans)
{
    extern __shared__ bf16 dsm[];

    if (blockIdx.x >= NCTA_LSTM) {
        producer_role(dsm, x, Wih0, bih0, bhh0, tags, start_t, end_t, trans,
                      blockIdx.x - NCTA_LSTM);
        return;
    }

    bf16* W0sm  = dsm;                    // Whh0 slice  (64n x 392)
    bf16* Wi1sm = dsm + 64 * 392;         // Wih1 slice
    bf16* W1sm  = dsm + 2 * 64 * 392;     // Whh1 slice
    bf16* Asm   = dsm + 3 * 64 * 392;     // A0 tile (64 x 392)
    bf16* A1sm  = dsm + 4 * 64 * 392;     // h1 k-tiles 0..11 (64 x 200)
    const uint32_t w0base  = smem_to_u32(W0sm);
    const uint32_t wi1base = smem_to_u32(Wi1sm);
    const uint32_t w1base  = smem_to_u32(W1sm);
    const uint32_t abase   = smem_to_u32(Asm);
    const uint32_t a1base  = smem_to_u32(A1sm);

    const int tid = threadIdx.x;
    const int lane = tid & 31;
    const int wid = tid >> 5;
    const int wm = wid & 3;              // 16-row m tile
    const int wn = wid >> 2;             // h-col half (0/1)
    const int bx = blockIdx.x & 3;
    const int by = blockIdx.x >> 2;
    const int b0 = bx * 64;
    const int c0 = by * 16;

    for (int idx = tid; idx < 64 * 384; idx += 256) {
        int n = idx / 384, k = idx - n * 384;
        int g = n >> 4, hc = n & 15;
        size_t grow = (size_t)(g * Hh + c0 + hc) * Hh + k;
        int d = n * 392 + k;
        W0sm[d]  = __float2bfloat16(Whh0[grow]);
        Wi1sm[d] = __float2bfloat16(Wih1[grow]);
        W1sm[d]  = __float2bfloat16(Whh1[grow]);
    }

    const uint32_t a_off =
        (uint32_t)(((wm * 16 + (lane & 15)) * 392 + (lane >> 4) * 8) * 2);
    const uint32_t a1_off =
        (uint32_t)(((wm * 16 + (lane & 15)) * 200 + (lane >> 4) * 8) * 2);
    const uint32_t b_k = ((lane >> 3) & 1) * 8;
    const uint32_t b_off0 =
        (uint32_t)((((0 + (lane >> 4)) * 16 + wn * 8 + (lane & 7)) * 392 + b_k) * 2);
    const uint32_t b_off1 =
        (uint32_t)((((2 + (lane >> 4)) * 16 + wn * 8 + (lane & 7)) * 392 + b_k) * 2);

    const int prow = lane >> 2;
    const int pcol = (lane & 3) * 2;
    const int colg = c0 + wn * 8 + pcol;

    float bi1[4][2];
#pragma unroll
    for (int g = 0; g < 4; g++)
#pragma unroll
        for (int q = 0; q < 2; q++)
            bi1[g][q] = bih1[g * Hh + colg + q] + bhh1[g * Hh + colg + q];

    float cst0[4], cst1[4];
#pragma unroll
    for (int i = 0; i < 4; i++) { cst0[i] = 0.f; cst1[i] = 0.f; }

    for (int t = 0; t <= Tt; t++) {
        const int ph = t & 1;
        const bool doL0 = (t < Tt);
        const bool doL1 = (t >= 1);
        const bool doW  = (t >= 2);     // Whh1 pass (h1(t-2) exists)

        // ---- issue A0 <- h0(t-1); A1 <- h1(t-2) k-tiles 0..11 (from g_h1b)
        {
            const bf16* hprev0 = g_h0buf + (size_t)ph * Bb * Hh;
#pragma unroll
            for (int it = 0; it < 12; it++) {
                int idx = tid + it * 256;
                int row = idx / 48, c = idx - row * 48;
                CP_ASYNC16(abase + (uint32_t)((row * 392 + c * 8) * 2),
                           hprev0 + (size_t)(b0 + row) * Hh + c * 8);
            }
            CP_COMMIT();
        }
        if (doW) {
            const bf16* hprev1 = g_h1b + (size_t)(t - 2) * Bb * Hh;
#pragma unroll
            for (int it = 0; it < 6; it++) {
                int idx = tid + it * 256;
                int row = idx / 24, c = idx - row * 24;
                CP_ASYNC16(a1base + (uint32_t)(row * 400 + c * 16),
                           hprev1 + (size_t)(b0 + row) * Hh + c * 8);
            }
            CP_COMMIT();
        }

        // ---- gate on producer-published xw(t)
        if (doL0) {
            if (tid == 0) {
                while (ld_acquire_gpu(&g_ready[t]) < 24u) { }
            }
        }
        __syncthreads();

        // ---- xw(t) fragments: ONE uint4 per row (permuted layout)
        float2 xv[4][2];
        if (doL0) {
#pragma unroll
            for (int p = 0; p < 2; p++) {
                int brow = b0 + wm * 16 + prow + p * 8;
                uint4 pk = *(const uint4*)(g_xwb +
                    (((size_t)t * Bb + brow) * 192 + (colg >> 1)) * 8);
                xv[0][p] = __bfloat1622float2(*(__nv_bfloat162*)&pk.x);
                xv[1][p] = __bfloat1622float2(*(__nv_bfloat162*)&pk.y);
                xv[2][p] = __bfloat1622float2(*(__nv_bfloat162*)&pk.z);
                xv[3][p] = __bfloat1622float2(*(__nv_bfloat162*)&pk.w);
            }
        }

        if (doW) CP_WAIT1(); else CP_WAIT0();
        __syncthreads();

        float accL0[4][4], accL1[4][4];
#pragma unroll
        for (int j = 0; j < 4; j++)
#pragma unroll
            for (int q = 0; q < 4; q++) { accL0[j][q] = 0.f; accL1[j][q] = 0.f; }

#pragma unroll 4
        for (int kt = 0; kt < 24; kt++) {
            uint32_t koff = (uint32_t)(kt * 32);
            uint32_t a[4], p0[4], p1[4], q0[4], q1[4];
            ldsm4(a, abase + a_off + koff);
            ldsm4(p0, w0base + b_off0 + koff);
            ldsm4(p1, w0base + b_off1 + koff);
            ldsm4(q0, wi1base + b_off0 + koff);
            ldsm4(q1, wi1base + b_off1 + koff);
            mma_bf16(accL0[0], a, &p0[0]);
            mma_bf16(accL1[0], a, &q0[0]);
            mma_bf16(accL0[1], a, &p0[2]);
            mma_bf16(accL1[1], a, &q0[2]);
            mma_bf16(accL0[2], a, &p1[0]);
            mma_bf16(accL1[2], a, &q1[0]);
            mma_bf16(accL0[3], a, &p1[2]);
            mma_bf16(accL1[3], a, &q1[2]);
        }
        __syncthreads();

        // ---- issue h1-upper (k-tiles 12..23) into A0 cols 192..383
        if (doW) {
            const bf16* hprev1 = g_h1b + (size_t)(t - 2) * Bb * Hh;
#pragma unroll
            for (int it = 0; it < 6; it++) {
                int idx = tid + it * 256;
                int row = idx / 24, c = idx - row * 24;
                CP_ASYNC16(abase + (uint32_t)(row * 784 + 384 + c * 16),
                           hprev1 + (size_t)(b0 + row) * Hh + 192 + c * 8);
            }
            CP_COMMIT();
        }

        // ---- Whh1 first chunk on A1 (issued at interval start; ready) —
        //      runs BEFORE L0 pointwise so the upper load hides under both.
        if (doW) {
            CP_WAIT1();
            __syncthreads();
#pragma unroll 4
            for (int kt = 0; kt < 12; kt++) {
                uint32_t koff = (uint32_t)(kt * 32);
                uint32_t a[4], b0v[4], b1v[4];
                ldsm4(a, a1base + a1_off + koff);
                ldsm4(b0v, w1base + b_off0 + koff);
                ldsm4(b1v, w1base + b_off1 + koff);
                mma_bf16(accL1[0], a, &b0v[0]);
                mma_bf16(accL1[1], a, &b0v[2]);
                mma_bf16(accL1[2], a, &b1v[0]);
                mma_bf16(accL1[3], a, &b1v[2]);
            }
        }

        // ---- L0 pointwise: h0(t) -> h0buf[ph^1]
        if (doL0) {
            bf16* hnext0 = g_h0buf + (size_t)(ph ^ 1) * Bb * Hh;
#pragma unroll
            for (int p = 0; p < 2; p++) {
                int brow = b0 + wm * 16 + prow + p * 8;
                float hnv[2];
#pragma unroll
                for (int q = 0; q < 2; q++) {
                    float xi = q ? xv[0][p].y : xv[0][p].x;
                    float xf = q ? xv[1][p].y : xv[1][p].x;
                    float xg = q ? xv[2][p].y : xv[2][p].x;
                    float xo = q ? xv[3][p].y : xv[3][p].x;
                    float i_ = sig_ap(accL0[0][p * 2 + q] + xi);
                    float f_ = sig_ap(accL0[1][p * 2 + q] + xf);
                    float g_ = tanh_ap(accL0[2][p * 2 + q] + xg);
                    float o_ = sig_ap(accL0[3][p * 2 + q] + xo);
                    float cn = f_ * cst0[p * 2 + q] + i_ * g_;
                    cst0[p * 2 + q] = cn;
                    hnv[q] = o_ * tanh_ap(cn);
                }
                *(__nv_bfloat162*)(hnext0 + (size_t)brow * Hh + colg) =
                    __floats2bfloat162_rn(hnv[0], hnv[1]);
            }
        }

        if (doL1) {
            if (doW) {
                CP_WAIT0();
                __syncthreads();
#pragma unroll 4
                for (int kt = 12; kt < 24; kt++) {
                    uint32_t koff = (uint32_t)(kt * 32);
                    uint32_t a[4], b0v[4], b1v[4];
                    ldsm4(a, abase + a_off + koff);
                    ldsm4(b0v, w1base + b_off0 + koff);
                    ldsm4(b1v, w1base + b_off1 + koff);
                    mma_bf16(accL1[0], a, &b0v[0]);
                    mma_bf16(accL1[1], a, &b0v[2]);
                    mma_bf16(accL1[2], a, &b1v[0]);
                    mma_bf16(accL1[3], a, &b1v[2]);
                }
            }

            bf16* houtp = g_h1b + (size_t)(t - 1) * Bb * Hh;
#pragma unroll
            for (int p = 0; p < 2; p++) {
                int brow = b0 + wm * 16 + prow + p * 8;
                float hnv[2];
#pragma unroll
                for (int q = 0; q < 2; q++) {
                    float i_ = sig_ap(accL1[0][p * 2 + q] + bi1[0][q]);
                    float f_ = sig_ap(accL1[1][p * 2 + q] + bi1[1][q]);
                    float g_ = tanh_ap(accL1[2][p * 2 + q] + bi1[2][q]);
                    float o_ = sig_ap(accL1[3][p * 2 + q] + bi1[3][q]);
                    float cn = f_ * cst1[p * 2 + q] + i_ * g_;
                    cst1[p * 2 + q] = cn;
                    hnv[q] = o_ * tanh_ap(cn);
                }
                *(__nv_bfloat162*)(houtp + (size_t)brow * Hh + colg) =
                    __floats2bfloat162_rn(hnv[0], hnv[1]);
            }
        }

        group_barrier(bx, blockIdx.x, (unsigned int)(t + 1));
    }
}

// ------------------------------ reduce -------------------------------------
__global__ __launch_bounds__(256) void reduce_kernel(float* __restrict__ out)
{
    __shared__ float sh[256];
    int i = threadIdx.x;
    sh[i] = g_partial[i];
    __syncthreads();
#pragma unroll
    for (int s = 128; s; s >>= 1) {
        if (i < s) sh[i] += sh[i + s];
        __syncthreads();
    }
    if (i == 0) out[0] = sh[0];
}

// ------------------------------ launch -------------------------------------
extern "C" void kernel_launch(void* const* d_in, const int* in_sizes, int n_in,
                              void* d_out, int out_size)
{
    (void)in_sizes; (void)n_in; (void)out_size;
    const float* x    = (const float*)d_in[0];
    const int*   tags = (const int*)d_in[2];
    const float* Wih0 = (const float*)d_in[3];
    const float* Whh0 = (const float*)d_in[4];
    const float* bih0 = (const float*)d_in[5];
    const float* bhh0 = (const float*)d_in[6];
    const float* Wih1 = (const float*)d_in[7];
    const float* Whh1 = (const float*)d_in[8];
    const float* bih1 = (const float*)d_in[9];
    const float* bhh1 = (const float*)d_in[10];
    const float* W1   = (const float*)d_in[11];
    const float* b1   = (const float*)d_in[12];
    const float* W2   = (const float*)d_in[13];
    const float* b2   = (const float*)d_in[14];
    const float* W3   = (const float*)d_in[15];
    const float* b3   = (const float*)d_in[16];
    const float* st   = (const float*)d_in[17];
    const float* et   = (const float*)d_in[18];
    const float* trn  = (const float*)d_in[19];

    const size_t LSTM_SMEM = (size_t)(4 * 64 * 392 + 64 * 200) * sizeof(bf16);
    cudaFuncSetAttribute(lstm_fused, cudaFuncAttributeMaxDynamicSharedMemorySize,
                         (int)LSTM_SMEM);

    init_state_kernel<<<(2 * Bb * Hh + 255) / 256, 256>>>();                  // 0
    compose1<<<((Kc * 512 + 1024) * 32 + 255) / 256, 256>>>(W3, W2, b1, b2);  // 1
    compose2<<<((Kc * Hh + Kc) * 32 + 255) / 256, 256>>>(W1, W3, b3);         // 2

    // fused: 96 LSTM CTAs + 52 producer CTAs (xw0 GEMM -> emissions -> CRF)
    lstm_fused<<<NCTA_LSTM + NCTA_GEMM, 256, LSTM_SMEM>>>(                    // 3
        Whh0, Wih1, Whh1, bih1, bhh1, bih0, bhh0, x, Wih0, tags, st, et, trn);

    reduce_kernel<<<1, 256>>>((float*)d_out);                                 // 4
}